// round 12
// baseline (speedup 1.0000x reference)
#include <cuda_runtime.h>
#include <cuda_fp16.h>
#include <math.h>
#include <stdint.h>

// ---------------- problem constants ----------------
#define B_     4
#define SEQ    2048
#define D_     512
#define H_     8
#define DH_    64
#define ID_    512
#define MM     266
#define MMP    272
#define INNER_ 1024
#define KW     31
#define LNUM   6
#define ROWS   (B_*SEQ)
#define RH     (ROWS*H_)
#define NBH    (B_*H_)

// ---------------- device scratch ----------------
__device__ __half g_h    [ROWS*D_];                // LN out (GEMM A)
__device__ __half g_qkhi [2*(size_t)ROWS*ID_];     // q|k hi plane [2RH][64]
__device__ __half g_qklo [2*(size_t)ROWS*ID_];     // q|k lo plane
__device__ __half g_vh   [ROWS*ID_];               // v fp16 (ctx B)
__device__ float  g_fp   [2*(size_t)RH*MMP];       // proj out fp32
__device__ __half g_fph  [2*(size_t)RH*MMP];       // qp | kp fp16
__device__ float  g_cpart[(size_t)NBH*8*MMP*72];   // ctx partials [bh][kc][272][72]
__device__ __half g_ctxT [(size_t)NBH*80*288];     // [bh][e][m] fp16
__device__ __half g_att  [ROWS*ID_];               // attn out fp16 (wo A)
__device__ float  g_ya   [ROWS*INNER_];            // pw1 'a' half fp32
__device__ __half g_glu  [ROWS*INNER_];            // gated fp16
__device__ __half g_dw   [ROWS*INNER_];            // dwconv out fp16
__device__ float  g_qkvbias[LNUM*1536];

#define FR_QKV  (64*32*128)
#define FR_PW1  (256*32*128)
#define FR_PW2  (64*64*128)
#define FR_PROJ (48*4*128)
#define FR_LSTR (4*FR_QKV + FR_PW1 + FR_PW2 + FR_PROJ)
__device__ uint32_t g_wfrag[(size_t)LNUM * FR_LSTR];

// ---------------- helpers ----------------
__device__ __forceinline__ uint32_t pk2h(__half a, __half b) {
    __half2 t = __halves2half2(a, b);
    return *reinterpret_cast<uint32_t*>(&t);
}
__device__ __forceinline__ void ldm4(uint32_t* r, uint32_t addr) {
    asm volatile("ldmatrix.sync.aligned.m8n8.x4.shared.b16 {%0,%1,%2,%3}, [%4];\n"
                 : "=r"(r[0]), "=r"(r[1]), "=r"(r[2]), "=r"(r[3]) : "r"(addr));
}
__device__ __forceinline__ void ldm4t(uint32_t* r, uint32_t addr) {
    asm volatile("ldmatrix.sync.aligned.m8n8.x4.trans.shared.b16 {%0,%1,%2,%3}, [%4];\n"
                 : "=r"(r[0]), "=r"(r[1]), "=r"(r[2]), "=r"(r[3]) : "r"(addr));
}
__device__ __forceinline__ void mma_f16(float* c, const uint32_t* a, const uint32_t* b) {
    asm volatile(
        "mma.sync.aligned.m16n8k16.row.col.f32.f16.f16.f32 "
        "{%0,%1,%2,%3}, {%4,%5,%6,%7}, {%8,%9}, {%0,%1,%2,%3};\n"
        : "+f"(c[0]), "+f"(c[1]), "+f"(c[2]), "+f"(c[3])
        : "r"(a[0]), "r"(a[1]), "r"(a[2]), "r"(a[3]), "r"(b[0]), "r"(b[1]));
}

// ---------------- weight -> fragment converter (fp16 hi/lo) -----------------
__global__ void wfrag(const float* __restrict__ W, uint32_t* __restrict__ out,
                      int Ndim, int Kdim, int NT8)
{
    const int KT16 = Kdim >> 4;
    size_t idx = (size_t)blockIdx.x * 256 + threadIdx.x;
    size_t total = (size_t)NT8 * KT16 * 128;
    if (idx >= total) return;
    int r     = (int)(idx & 1);
    int l     = (int)((idx >> 1) & 31);
    int plane = (int)((idx >> 6) & 1);
    size_t ft = idx >> 7;
    int k16 = (int)(ft % KT16);
    int n8  = (int)(ft / KT16);
    int n = n8 * 8 + (l >> 2);
    int k = k16 * 16 + (l & 3) * 2 + r * 8;
    float v0 = 0.f, v1 = 0.f;
    if (n < Ndim) {
        float2 vv = *(const float2*)&W[(size_t)n * Kdim + k];
        v0 = vv.x; v1 = vv.y;
    }
    __half h0 = __float2half_rn(v0), h1 = __float2half_rn(v1);
    uint32_t val = (plane == 0)
        ? pk2h(h0, h1)
        : pk2h(__float2half_rn(v0 - __half2float(h0)),
               __float2half_rn(v1 - __half2float(h1)));
    out[idx] = val;
}

__global__ void biascat(const float* __restrict__ bq, const float* __restrict__ bk,
                        const float* __restrict__ bv, float* __restrict__ out)
{
    int i = blockIdx.x * 256 + threadIdx.x;
    if (i < LNUM * 512) {
        int l = i >> 9, c = i & 511;
        out[l*1536 + c]        = bq[i];
        out[l*1536 + 512 + c]  = bk[i];
        out[l*1536 + 1024 + c] = bv[i];
    }
}

#define ASTR 40

// ======================================================================
// gemm_h: A fp16, B fp16 hi plane. 1 MMA/k-step.
// modes: 0 C fp32 (+extra resid), 2 gate -> Ch fp16,
//        3 qkv split: q,k -> hi/lo planes (Chi/Clo), v -> Ch fp16
// ======================================================================
__global__ __launch_bounds__(256, 2)
void gemm_h(const __half* __restrict__ A, const uint32_t* __restrict__ Bf,
            float* __restrict__ C, __half* __restrict__ Ch,
            __half* __restrict__ Chi, __half* __restrict__ Clo,
            const float* __restrict__ bias, const float* __restrict__ extra,
            int Mdim, int Ndim, int Kdim, int mode)
{
    __shared__ __align__(16) __half Asm[128][ASTR];

    const int tid  = threadIdx.x;
    const int lane = tid & 31;
    const int warp = tid >> 5;
    const int wm = (warp & 1) * 64;
    const int wn = (warp >> 1) * 32;
    const int bm = blockIdx.y * 128;
    const int bn = blockIdx.x * 128;
    const int KT16 = Kdim >> 4;
    const int n8_0 = (bn + wn) >> 3;

    float acc[4][4][4];
    #pragma unroll
    for (int i = 0; i < 4; i++)
        #pragma unroll
        for (int j = 0; j < 4; j++)
            #pragma unroll
            for (int t = 0; t < 4; t++) acc[i][j][t] = 0.f;

    const int a_m = lane & 15;
    const int a_k = (lane >> 4) << 3;
    const uint32_t sA = (uint32_t)__cvta_generic_to_shared(&Asm[0][0]);

    const int KT = Kdim >> 5;
    for (int kt = 0; kt < KT; kt++) {
        #pragma unroll
        for (int u = 0; u < 2; u++) {
            int f = tid + u * 256;
            int row = f >> 2;
            int c8 = (f & 3) * 8;
            *(uint4*)&Asm[row][c8] =
                *(const uint4*)&A[(size_t)(bm + row) * Kdim + kt*32 + c8];
        }
        __syncthreads();

        #pragma unroll
        for (int ks = 0; ks < 2; ks++) {
            uint32_t bhf[4][2];
            const uint32_t* fb = Bf + ((size_t)n8_0 * KT16 + (kt*2 + ks)) * 128 + lane * 2;
            #pragma unroll
            for (int nt = 0; nt < 4; nt++) {
                uint2 hv = *(const uint2*)(fb + (size_t)nt * KT16 * 128);
                bhf[nt][0] = hv.x; bhf[nt][1] = hv.y;
            }
            #pragma unroll
            for (int mt = 0; mt < 4; mt++) {
                uint32_t ah[4];
                uint32_t addr = sA + (uint32_t)(((wm + mt*16 + a_m) * ASTR) + ks*16 + a_k) * 2;
                ldm4(ah, addr);
                #pragma unroll
                for (int nt = 0; nt < 4; nt++)
                    mma_f16(acc[mt][nt], ah, bhf[nt]);
            }
        }
        __syncthreads();
    }

    const int gr = lane >> 2;
    const int gc = (lane & 3) * 2;
    #pragma unroll
    for (int mt = 0; mt < 4; mt++) {
        #pragma unroll
        for (int nt = 0; nt < 4; nt++) {
            const float* cp = acc[mt][nt];
            int row = bm + wm + mt*16 + gr;
            int col = bn + wn + nt*8 + gc;
            #pragma unroll
            for (int half = 0; half < 2; half++) {
                int rr = row + half*8;
                float v0 = cp[half*2 + 0];
                float v1 = cp[half*2 + 1];
                if (bias) { v0 += bias[col]; v1 += bias[col + 1]; }
                if (mode == 0) {
                    if (extra) {
                        v0 += extra[(size_t)rr * Ndim + col];
                        v1 += extra[(size_t)rr * Ndim + col + 1];
                    }
                    *(float2*)&C[(size_t)rr * Ndim + col] = make_float2(v0, v1);
                } else if (mode == 2) {
                    float a0 = extra[(size_t)rr * Ndim + col];
                    float a1 = extra[(size_t)rr * Ndim + col + 1];
                    __half2 hh = __floats2half2_rn(a0 / (1.f + expf(-v0)),
                                                   a1 / (1.f + expf(-v1)));
                    *(__half2*)&Ch[(size_t)rr * Ndim + col] = hh;
                } else { // mode 3
                    if (col < 1024) {
                        __half h0 = __float2half_rn(v0), h1 = __float2half_rn(v1);
                        __half l0 = __float2half_rn(v0 - __half2float(h0));
                        __half l1 = __float2half_rn(v1 - __half2float(h1));
                        size_t off = (size_t)(col >> 9) * ((size_t)ROWS * ID_)
                                   + (size_t)rr * ID_ + (col & 511);
                        *(__half2*)&Chi[off] = __halves2half2(h0, h1);
                        *(__half2*)&Clo[off] = __halves2half2(l0, l1);
                    } else {
                        *(__half2*)&Ch[(size_t)rr * ID_ + (col & 511)] =
                            __floats2half2_rn(v0, v1);
                    }
                }
            }
        }
    }
}

// ======================================================================
// gemm_p (proj): A = hi/lo fp16 planes [2RH][64] (copy fill), 3 MMA.
// Out fp32 [rh][MMP], scaled by alpha.
// ======================================================================
#define PLANE_ELEMS (128*ASTR)
#define PLANE_BYTES (PLANE_ELEMS*2)
__global__ __launch_bounds__(256, 2)
void gemm_p(const __half* __restrict__ Ahi, const __half* __restrict__ Alo,
            const uint32_t* __restrict__ Bf, float* __restrict__ C, float alpha)
{
    __shared__ __align__(16) __half Asm[2][128][ASTR];

    const int tid  = threadIdx.x;
    const int lane = tid & 31;
    const int warp = tid >> 5;
    const int wm = (warp & 1) * 64;
    const int wn = (warp >> 1) * 32;
    const int bm = blockIdx.y * 128;
    const int bn = blockIdx.x * 128;
    const int KT16 = 4;          // Kdim=64
    const int n8_0 = (bn + wn) >> 3;

    float acc[4][4][4];
    #pragma unroll
    for (int i = 0; i < 4; i++)
        #pragma unroll
        for (int j = 0; j < 4; j++)
            #pragma unroll
            for (int t = 0; t < 4; t++) acc[i][j][t] = 0.f;

    const int a_m = lane & 15;
    const int a_k = (lane >> 4) << 3;
    const uint32_t sA = (uint32_t)__cvta_generic_to_shared(&Asm[0][0][0]);

    #pragma unroll
    for (int kt = 0; kt < 2; kt++) {
        #pragma unroll
        for (int u = 0; u < 2; u++) {
            int f = tid + u * 256;
            int row = f >> 2;
            int c8 = (f & 3) * 8;
            *(uint4*)&Asm[0][row][c8] =
                *(const uint4*)&Ahi[(size_t)(bm + row) * DH_ + kt*32 + c8];
            *(uint4*)&Asm[1][row][c8] =
                *(const uint4*)&Alo[(size_t)(bm + row) * DH_ + kt*32 + c8];
        }
        __syncthreads();

        #pragma unroll
        for (int ks = 0; ks < 2; ks++) {
            uint32_t bhf[4][2], blf[4][2];
            const uint32_t* fb = Bf + ((size_t)n8_0 * KT16 + (kt*2 + ks)) * 128 + lane * 2;
            #pragma unroll
            for (int nt = 0; nt < 4; nt++) {
                const uint32_t* fp2 = fb + (size_t)nt * KT16 * 128;
                uint2 h  = *(const uint2*)fp2;
                uint2 lo = *(const uint2*)(fp2 + 64);
                bhf[nt][0] = h.x;  bhf[nt][1] = h.y;
                blf[nt][0] = lo.x; blf[nt][1] = lo.y;
            }
            #pragma unroll
            for (int mt = 0; mt < 4; mt++) {
                uint32_t ah[4], al[4];
                uint32_t addr = sA + (uint32_t)(((wm + mt*16 + a_m) * ASTR) + ks*16 + a_k) * 2;
                ldm4(ah, addr);
                ldm4(al, addr + PLANE_BYTES);
                #pragma unroll
                for (int nt = 0; nt < 4; nt++) {
                    mma_f16(acc[mt][nt], ah, bhf[nt]);
                    mma_f16(acc[mt][nt], ah, blf[nt]);
                    mma_f16(acc[mt][nt], al, bhf[nt]);
                }
            }
        }
        __syncthreads();
    }

    const int gr = lane >> 2;
    const int gc = (lane & 3) * 2;
    #pragma unroll
    for (int mt = 0; mt < 4; mt++) {
        #pragma unroll
        for (int nt = 0; nt < 4; nt++) {
            const float* cp = acc[mt][nt];
            int row = bm + wm + mt*16 + gr;
            int col = bn + wn + nt*8 + gc;
            #pragma unroll
            for (int half = 0; half < 2; half++) {
                int rr = row + half*8;
                #pragma unroll
                for (int j = 0; j < 2; j++) {
                    int cc = col + j;
                    if (cc < MM)
                        C[(size_t)rr * MMP + cc] = cp[half*2 + j] * alpha;
                }
            }
        }
    }
}

// ======================================================================
// ctx_mma: kp^T @ [v | 1 | 0...] over 256-seq chunk -> fp32 partials [272][72]
// col 64 of output = partial k_cumsum (ones-column trick).
// ======================================================================
#define KPITCH 280
#define VPITCH 88
__global__ __launch_bounds__(256, 1)
void ctx_mma(const __half* __restrict__ kp, const __half* __restrict__ v,
             float* __restrict__ part)
{
    __shared__ __align__(16) __half Kp[32][KPITCH];
    __shared__ __align__(16) __half Vs[32][VPITCH];

    const int tid = threadIdx.x;
    const int lane = tid & 31;
    const int warp = tid >> 5;
    const int kc = blockIdx.x;
    const int bh = blockIdx.y;
    const int b = bh >> 3, h = bh & 7;

    const int nmt = (warp == 0) ? 3 : 2;
    int mts[3];
    mts[0] = 2*warp; mts[1] = 2*warp + 1; mts[2] = 16;

    float acc[3][9][4];
    #pragma unroll
    for (int t = 0; t < 3; t++)
        #pragma unroll
        for (int n = 0; n < 9; n++)
            #pragma unroll
            for (int j = 0; j < 4; j++) acc[t][n][j] = 0.f;

    const __half* kpb = kp + ((size_t)(b * SEQ) * H_ + h) * MMP;
    const __half* vb  = v  + ((size_t)(b * SEQ) * H_ + h) * DH_;

    const uint32_t sK = (uint32_t)__cvta_generic_to_shared(&Kp[0][0]);
    const uint32_t sV = (uint32_t)__cvta_generic_to_shared(&Vs[0][0]);
    const int r7 = lane & 7;

    // ones/zero pad: cols 64..79 (col 64 = 1.0), written once
    if (tid < 64) {
        int nn = tid >> 1;
        int c8 = 64 + (tid & 1) * 8;
        __half vals[8];
        #pragma unroll
        for (int j = 0; j < 8; j++) vals[j] = __float2half(0.f);
        if (c8 == 64) vals[0] = __float2half(1.f);
        *(uint4*)&Vs[nn][c8] = *(uint4*)vals;
    }
    __syncthreads();

    for (int it = 0; it < 8; it++) {
        const int n0 = kc * 256 + it * 32;
        for (int f = tid; f < 32*34; f += 256) {
            int nn = f / 34, c8 = (f % 34) * 8;
            *(uint4*)&Kp[nn][c8] =
                *(const uint4*)&kpb[(size_t)(n0 + nn) * (H_*MMP) + c8];
        }
        {
            int nn = tid >> 3, c8 = (tid & 7) * 8;
            *(uint4*)&Vs[nn][c8] =
                *(const uint4*)&vb[(size_t)(n0 + nn) * (H_*DH_) + c8];
        }
        __syncthreads();

        #pragma unroll
        for (int ks = 0; ks < 2; ks++) {
            uint32_t bhf[10][2];
            #pragma unroll
            for (int g = 0; g < 5; g++) {
                int row = ks*16 + ((lane >> 3) & 1) * 8 + r7;
                int col = g*16 + (lane >> 4) * 8;
                uint32_t r[4];
                ldm4t(r, sV + (uint32_t)(row * VPITCH + col) * 2);
                bhf[2*g][0] = r[0]; bhf[2*g][1] = r[1];
                bhf[2*g+1][0] = r[2]; bhf[2*g+1][1] = r[3];
            }
            #pragma unroll
            for (int t = 0; t < 3; t++) {
                if (t < nmt) {
                    int m0 = mts[t] * 16;
                    int row = ks*16 + ((lane >> 4) & 1) * 8 + r7;
                    int col = m0 + ((lane >> 3) & 1) * 8;
                    uint32_t ah[4];
                    ldm4t(ah, sK + (uint32_t)(row * KPITCH + col) * 2);
                    #pragma unroll
                    for (int nt = 0; nt < 9; nt++)
                        mma_f16(acc[t][nt], ah, bhf[nt]);
                }
            }
        }
        __syncthreads();
    }

    const int gr = lane >> 2;
    const int gc = (lane & 3) * 2;
    float* pb = part + ((size_t)(bh * 8 + kc)) * 272 * 72;
    #pragma unroll
    for (int t = 0; t < 3; t++) {
        if (t < nmt) {
            int m0 = mts[t] * 16;
            #pragma unroll
            for (int nt = 0; nt < 9; nt++) {
                int e = nt*8 + gc;
                pb[(size_t)(m0 + gr) * 72 + e]     = acc[t][nt][0];
                pb[(size_t)(m0 + gr) * 72 + e + 1] = acc[t][nt][1];
                pb[(size_t)(m0 + gr + 8) * 72 + e]     = acc[t][nt][2];
                pb[(size_t)(m0 + gr + 8) * 72 + e + 1] = acc[t][nt][3];
            }
        }
    }
}

// ---------------- reduceT: sum partials -> ctxT fp16 [bh][e][m] -------------
// partial col 64 = ksum -> ctxT row 64; rows 65..79 zero.
__global__ void reduceT(const float* __restrict__ part, __half* __restrict__ ctxT)
{
    const int bh = blockIdx.y;
    const int m0 = blockIdx.x * 64;
    const int mw = (272 - m0 < 64) ? (272 - m0) : 64;
    __shared__ float sm[64][73];
    const int t = threadIdx.x;
    for (int f = t; f < mw * 72; f += 256) {
        int mm = f / 72, e = f % 72;
        float s = 0.f;
        #pragma unroll
        for (int kc = 0; kc < 8; kc++)
            s += part[(((size_t)(bh*8 + kc)) * 272 + m0 + mm) * 72 + e];
        sm[mm][e] = s;
    }
    __syncthreads();
    const int m  = t & 63;
    const int er = t >> 6;
    for (int ee = er; ee < 80; ee += 4) {
        if (m0 + m < 288) {
            float val = 0.f;
            if (m < mw && ee <= 64) val = sm[m][ee];
            ctxT[((size_t)bh * 80 + ee) * 288 + m0 + m] = __float2half(val);
        }
    }
}

// ======================================================================
// attn_mma: qp(fp16) @ ctxT^T(fp16); col 64 = dsum; out fp16 att
// ======================================================================
#define APITCH 24
__global__ __launch_bounds__(256, 2)
void attn_mma(const __half* __restrict__ qp, const __half* __restrict__ ctxT,
              __half* __restrict__ out)
{
    __shared__ __align__(16) __half As[128][APITCH];
    __shared__ __align__(16) __half Bs[80][APITCH];

    const int tid = threadIdx.x;
    const int lane = tid & 31;
    const int warp = tid >> 5;
    const int bm = blockIdx.x * 128;
    const int bh = blockIdx.y;
    const int b = bh >> 3, h = bh & 7;
    const int wm = warp * 16;

    const __half* qpb = qp + ((size_t)(b * SEQ) * H_ + h) * MMP;
    const __half* cb  = ctxT + (size_t)bh * 80 * 288;

    float acc[9][4];
    #pragma unroll
    for (int n = 0; n < 9; n++)
        #pragma unroll
        for (int j = 0; j < 4; j++) acc[n][j] = 0.f;

    const uint32_t sA = (uint32_t)__cvta_generic_to_shared(&As[0][0]);
    const uint32_t sB = (uint32_t)__cvta_generic_to_shared(&Bs[0][0]);
    const int a_m = lane & 15;
    const int a_k = (lane >> 4) << 3;
    const int b_n = (lane & 7) | ((lane & 16) >> 1);
    const int b_k = lane & 8;

    for (int k16 = 0; k16 < 17; k16++) {
        const int k0 = k16 * 16;
        {
            int row = tid >> 1, c8 = (tid & 1) * 8;
            *(uint4*)&As[row][c8] =
                *(const uint4*)&qpb[(size_t)(bm + row) * (H_*MMP) + k0 + c8];
        }
        if (tid < 160) {
            int row = tid >> 1, c8 = (tid & 1) * 8;
            *(uint4*)&Bs[row][c8] =
                *(const uint4*)&cb[(size_t)row * 288 + k0 + c8];
        }
        __syncthreads();

        uint32_t bhf[10][2];
        #pragma unroll
        for (int p = 0; p < 5; p++) {
            uint32_t r[4];
            ldm4(r, sB + (uint32_t)((p*16 + b_n) * APITCH + b_k) * 2);
            bhf[2*p][0] = r[0]; bhf[2*p][1] = r[1];
            bhf[2*p+1][0] = r[2]; bhf[2*p+1][1] = r[3];
        }
        {
            uint32_t ah[4];
            ldm4(ah, sA + (uint32_t)((wm + a_m) * APITCH + a_k) * 2);
            #pragma unroll
            for (int nt = 0; nt < 9; nt++)
                mma_f16(acc[nt], ah, bhf[nt]);
        }
        __syncthreads();
    }

    const int gr = lane >> 2;
    const int gc = (lane & 3) * 2;
    float d0 = __shfl_sync(0xffffffffu, acc[8][0], gr * 4);
    float d1 = __shfl_sync(0xffffffffu, acc[8][2], gr * 4);
    const float dinv0 = 1.f / (d0 + 1e-8f);
    const float dinv1 = 1.f / (d1 + 1e-8f);

    const size_t row0 = ((size_t)(b * SEQ + bm + wm + gr) * H_ + h) * DH_;
    const size_t row1 = row0 + (size_t)8 * H_ * DH_;
    #pragma unroll
    for (int nt = 0; nt < 8; nt++) {
        int e = nt*8 + gc;
        *(__half2*)&out[row0 + e] = __floats2half2_rn(acc[nt][0]*dinv0, acc[nt][1]*dinv0);
        *(__half2*)&out[row1 + e] = __floats2half2_rn(acc[nt][2]*dinv1, acc[nt][3]*dinv1);
    }
}

// ---------------- LayerNorm (fp16 out) -----------------
__global__ void ln_kernel(const float* __restrict__ x, const float* __restrict__ g,
                          const float* __restrict__ b, __half* __restrict__ out)
{
    const int r = blockIdx.x;
    const int t = threadIdx.x;
    const float4 v = ((const float4*)(x + (size_t)r * D_))[t];
    float s  = v.x + v.y + v.z + v.w;
    float ss = v.x*v.x + v.y*v.y + v.z*v.z + v.w*v.w;
    __shared__ float rs[128], rss[128];
    rs[t] = s; rss[t] = ss;
    __syncthreads();
    for (int o = 64; o > 0; o >>= 1) {
        if (t < o) { rs[t] += rs[t+o]; rss[t] += rss[t+o]; }
        __syncthreads();
    }
    const float mu   = rs[0] * (1.f / D_);
    const float var  = rss[0] * (1.f / D_) - mu * mu;
    const float rstd = rsqrtf(var + 1e-5f);
    const float4 gg = ((const float4*)g)[t];
    const float4 bb = ((const float4*)b)[t];
    __half2 p0 = __floats2half2_rn((v.x - mu) * rstd * gg.x + bb.x,
                                   (v.y - mu) * rstd * gg.y + bb.y);
    __half2 p1 = __floats2half2_rn((v.z - mu) * rstd * gg.z + bb.z,
                                   (v.w - mu) * rstd * gg.w + bb.w);
    uint2 st;
    st.x = *reinterpret_cast<uint32_t*>(&p0);
    st.y = *reinterpret_cast<uint32_t*>(&p1);
    *(uint2*)&out[(size_t)r * D_ + t * 4] = st;
}

// ---------------- FAVOR postprocess: fp32 dash in, fp16 out -----------------
__global__ __launch_bounds__(256)
void favor_post3(const float* __restrict__ fp, __half* __restrict__ fph,
                 const __half* __restrict__ qhi, const __half* __restrict__ qlo,
                 float ratio)
{
    const int lane = threadIdx.x & 31;
    const int w    = threadIdx.x >> 5;
    const size_t rh = (size_t)blockIdx.x * 8 + w;
    const int isQ = rh < (size_t)RH;

    const float* prow = fp + rh * MMP;
    __half* orow = fph + rh * MMP;

    __half2 h2 = ((const __half2*)(qhi + rh * DH_))[lane];
    __half2 l2 = ((const __half2*)(qlo + rh * DH_))[lane];
    float dx = __half2float(h2.x) + __half2float(l2.x);
    float dy = __half2float(h2.y) + __half2float(l2.y);
    float s = dx*dx + dy*dy;
    #pragma unroll
    for (int o = 16; o > 0; o >>= 1) s += __shfl_xor_sync(0xffffffffu, s, o);
    const float diag = s * 0.0625f;

    float v[9];
    #pragma unroll
    for (int j = 0; j < 9; j++) {
        int m = j*32 + lane;
        v[j] = (m < MM) ? prow[m] : -1e30f;
    }

    if (isQ) {
        float mx = v[0];
        #pragma unroll
        for (int j = 1; j < 9; j++) mx = fmaxf(mx, v[j]);
        #pragma unroll
        for (int o = 16; o > 0; o >>= 1) mx = fmaxf(mx, __shfl_xor_sync(0xffffffffu, mx, o));
        #pragma unroll
        for (int j = 0; j < 9; j++) {
            int m = j*32 + lane;
            if (m < MM)       orow[m] = __float2half(ratio * (expf(v[j] - diag - mx) + 1e-4f));
            else if (m < MMP) orow[m] = __float2half(0.f);
        }
    } else {
        #pragma unroll
        for (int j = 0; j < 9; j++) {
            int m = j*32 + lane;
            if (m < MM)       orow[m] = __float2half(ratio * expf(v[j] - diag + 1e-4f));
            else if (m < MMP) orow[m] = __float2half(0.f);
        }
    }
}

// ---------------- depthwise conv + SiLU (fp16 in/out) ---------------
#define DC_CH 128
#define DC_TN 32
__global__ __launch_bounds__(256)
void dwconv2(const __half* __restrict__ gin, const float* __restrict__ w,
             const float* __restrict__ bias, __half* __restrict__ out)
{
    __shared__ float sin_[DC_TN + 30][DC_CH];
    __shared__ float sw[DC_CH * KW];

    const int c0 = blockIdx.x * DC_CH;
    const int n0 = blockIdx.y * DC_TN;
    const int b  = blockIdx.z;
    const int t  = threadIdx.x;

    for (int i = t; i < DC_CH * KW; i += 256)
        sw[i] = w[(size_t)c0 * KW + i];
    #pragma unroll
    for (int u = 0; u < (DC_TN + 30) * DC_CH / 256; u++) {
        int f = t + u * 256;
        int rowi = f >> 7;
        int ch = f & 127;
        int n = n0 + rowi - 15;
        sin_[rowi][ch] = ((unsigned)n < SEQ)
            ? __half2float(gin[((size_t)(b * SEQ + n) << 10) + c0 + ch]) : 0.f;
    }
    __syncthreads();

    const int ch = t & 127;
    const int nl0 = (t >> 7) * 16;

    float wr[KW];
    #pragma unroll
    for (int k = 0; k < KW; k++) wr[k] = sw[ch * KW + k];
    const float bb = bias[c0 + ch];

    #pragma unroll
    for (int i = 0; i < 16; i++) {
        float acc = bb;
        #pragma unroll
        for (int k = 0; k < KW; k++)
            acc += sin_[nl0 + i + k][ch] * wr[k];
        float o = acc / (1.f + expf(-acc));
        out[((size_t)(b * SEQ + n0 + nl0 + i) << 10) + c0 + ch] = __float2half(o);
    }
}

// ---------------- host orchestration ----------------------------------------
static inline void run_gemm_h(const __half* A, const uint32_t* Bf, float* C,
                              __half* Ch, __half* Chi, __half* Clo,
                              const float* bias, const float* extra,
                              int Mdim, int Ndim, int Kdim, int mode)
{
    dim3 grid(Ndim / 128, Mdim / 128);
    gemm_h<<<grid, 256>>>(A, Bf, C, Ch, Chi, Clo, bias, extra, Mdim, Ndim, Kdim, mode);
}
static inline void run_wfrag(const float* W, uint32_t* out, int Ndim, int Kdim, int NT8)
{
    size_t total = (size_t)NT8 * (Kdim >> 4) * 128;
    wfrag<<<(unsigned)((total + 255) / 256), 256>>>(W, out, Ndim, Kdim, NT8);
}

extern "C" void kernel_launch(void* const* d_in, const int* in_sizes, int n_in,
                              void* d_out, int out_size)
{
    const float* x    = (const float*)d_in[0];
    const float* ln1g = (const float*)d_in[1];
    const float* ln1b = (const float*)d_in[2];
    const float* wq   = (const float*)d_in[3];
    const float* bq   = (const float*)d_in[4];
    const float* wk   = (const float*)d_in[5];
    const float* bk   = (const float*)d_in[6];
    const float* wv   = (const float*)d_in[7];
    const float* bv   = (const float*)d_in[8];
    const float* wo   = (const float*)d_in[9];
    const float* bo   = (const float*)d_in[10];
    const float* proj = (const float*)d_in[11];
    const float* ln2g = (const float*)d_in[12];
    const float* ln2b = (const float*)d_in[13];
    const float* pw1w = (const float*)d_in[14];
    const float* pw1b = (const float*)d_in[15];
    const float* dww  = (const float*)d_in[16];
    const float* dwb  = (const float*)d_in[17];
    const float* pw2w = (const float*)d_in[18];
    const float* pw2b = (const float*)d_in[19];
    float* xo = (float*)d_out;

    __half *h, *qkhi, *qklo, *vh, *fph, *ctxT, *att, *glu, *dw;
    float *fp, *cpart, *ya, *qkvb;
    uint32_t* wf;
    cudaGetSymbolAddress((void**)&h,     g_h);
    cudaGetSymbolAddress((void**)&qkhi,  g_qkhi);
    cudaGetSymbolAddress((void**)&qklo,  g_qklo);
    cudaGetSymbolAddress((void**)&vh,    g_vh);
    cudaGetSymbolAddress((void**)&fp,    g_fp);
    cudaGetSymbolAddress((void**)&fph,   g_fph);
    cudaGetSymbolAddress((void**)&cpart, g_cpart);
    cudaGetSymbolAddress((void**)&ctxT,  g_ctxT);
    cudaGetSymbolAddress((void**)&att,   g_att);
    cudaGetSymbolAddress((void**)&ya,    g_ya);
    cudaGetSymbolAddress((void**)&glu,   g_glu);
    cudaGetSymbolAddress((void**)&dw,    g_dw);
    cudaGetSymbolAddress((void**)&qkvb,  g_qkvbias);
    cudaGetSymbolAddress((void**)&wf,    g_wfrag);

    __half* qph = fph;
    __half* kph = fph + (size_t)RH * MMP;

    const size_t OFF_WQ = 0;
    const size_t OFF_WO = OFF_WQ + 3*FR_QKV;
    const size_t OFF_P1 = OFF_WO + FR_QKV;
    const size_t OFF_P2 = OFF_P1 + FR_PW1;
    const size_t OFF_PR = OFF_P2 + FR_PW2;

    for (int l = 0; l < LNUM; l++) {
        uint32_t* lw = wf + (size_t)l * FR_LSTR;
        run_wfrag(wq   + (size_t)l*ID_*D_,    lw + OFF_WQ,            512, 512, 64);
        run_wfrag(wk   + (size_t)l*ID_*D_,    lw + OFF_WQ + FR_QKV,   512, 512, 64);
        run_wfrag(wv   + (size_t)l*ID_*D_,    lw + OFF_WQ + 2*FR_QKV, 512, 512, 64);
        run_wfrag(wo   + (size_t)l*ID_*D_,    lw + OFF_WO, 512, 512, 64);
        run_wfrag(pw1w + (size_t)l*2048*D_,   lw + OFF_P1, 2048, 512, 256);
        run_wfrag(pw2w + (size_t)l*D_*INNER_, lw + OFF_P2, 512, 1024, 64);
        run_wfrag(proj + (size_t)l*MM*DH_,    lw + OFF_PR, 266, 64, 48);
    }
    biascat<<<(LNUM*512 + 255)/256, 256>>>(bq, bk, bv, qkvb);

    cudaMemcpyAsync(xo, x, (size_t)ROWS * D_ * sizeof(float),
                    cudaMemcpyDeviceToDevice);

    const float dn    = (float)(1.0 / sqrt(sqrt(64.0)));
    const float ratio = (float)(1.0 / sqrt(266.0));

    for (int l = 0; l < LNUM; l++) {
        uint32_t* lw = wf + (size_t)l * FR_LSTR;

        ln_kernel<<<ROWS, 128>>>(xo, ln1g + (size_t)l*D_, ln1b + (size_t)l*D_, h);
        // fused QKV: q,k -> fp16 hi/lo planes; v -> fp16
        run_gemm_h(h, lw + OFF_WQ, nullptr, vh, qkhi, qklo,
                   qkvb + (size_t)l*1536, nullptr, ROWS, 1536, D_, 3);
        // proj (feeds exp): hi/lo planes, 3-term
        {
            dim3 grid(3, (2*RH) / 128);
            gemm_p<<<grid, 256>>>(qkhi, qklo, lw + OFF_PR, fp, dn);
        }
        favor_post3<<<2*RH/8, 256>>>(fp, fph, qkhi, qklo, ratio);
        {
            dim3 cg(8, NBH);
            ctx_mma<<<cg, 256>>>(kph, vh, cpart);
            dim3 rg(5, NBH);
            reduceT<<<rg, 256>>>(cpart, ctxT);
            dim3 ag(SEQ / 128, NBH);
            attn_mma<<<ag, 256>>>(qph, ctxT, att);
        }
        run_gemm_h(att, lw + OFF_WO, xo, nullptr, nullptr, nullptr,
                   bo + (size_t)l*D_, xo, ROWS, D_, ID_, 0);
        ln_kernel<<<ROWS, 128>>>(xo, ln2g + (size_t)l*D_, ln2b + (size_t)l*D_, h);
        run_gemm_h(h, lw + OFF_P1, ya, nullptr, nullptr, nullptr,
                   pw1b + (size_t)l*2048, nullptr, ROWS, INNER_, D_, 0);
        run_gemm_h(h, lw + OFF_P1 + (size_t)128*32*128, nullptr, glu, nullptr, nullptr,
                   pw1b + (size_t)l*2048 + INNER_, ya, ROWS, INNER_, D_, 2);
        {
            dim3 dg(INNER_/DC_CH, SEQ/DC_TN, B_);
            dwconv2<<<dg, 256>>>(glu, dww + (size_t)l*INNER_*KW, dwb + (size_t)l*INNER_, dw);
        }
        run_gemm_h(dw, lw + OFF_P2, xo, nullptr, nullptr, nullptr,
                   pw2b + (size_t)l*D_, xo, ROWS, D_, INNER_, 0);
    }
}

// round 13
// speedup vs baseline: 1.1012x; 1.1012x over previous
#include <cuda_runtime.h>
#include <cuda_fp16.h>
#include <math.h>
#include <stdint.h>

// ---------------- problem constants ----------------
#define B_     4
#define SEQ    2048
#define D_     512
#define H_     8
#define DH_    64
#define ID_    512
#define MM     266
#define MMP    272
#define INNER_ 1024
#define KW     31
#define LNUM   6
#define ROWS   (B_*SEQ)
#define RH     (ROWS*H_)
#define NBH    (B_*H_)

// ---------------- device scratch ----------------
__device__ __half g_h    [ROWS*D_];                // LN out (GEMM A)
__device__ float  g_qk   [2*(size_t)ROWS*ID_];     // q | k fp32
__device__ __half g_vh   [ROWS*ID_];               // v fp16
__device__ __half g_fph  [2*(size_t)RH*MMP];       // qp | kp fp16
__device__ float  g_ks   [NBH*MMP];
__device__ float  g_part [NBH*8*MMP];
__device__ float  g_cpart[(size_t)NBH*8*MMP*DH_];  // ctx partials fp32
__device__ __half g_ctxT [(size_t)NBH*80*288];     // [bh][e][m] fp16
__device__ __half g_att  [ROWS*ID_];               // attn out fp16
__device__ __half g_glu  [ROWS*INNER_];            // gated fp16
__device__ __half g_dw   [ROWS*INNER_];            // dwconv out fp16
__device__ float  g_qkvbias[LNUM*1536];
__device__ float  g_pw1bi [LNUM*2048];             // interleaved pw1 bias

#define FR_QKV  (64*32*128)
#define FR_PW1  (256*32*128)
#define FR_PW2  (64*64*128)
#define FR_PROJ (48*4*128)
#define FR_LSTR (4*FR_QKV + FR_PW1 + FR_PW2 + FR_PROJ)
__device__ uint32_t g_wfrag[(size_t)LNUM * FR_LSTR];

// ---------------- helpers ----------------
__device__ __forceinline__ uint32_t pk2h(__half a, __half b) {
    __half2 t = __halves2half2(a, b);
    return *reinterpret_cast<uint32_t*>(&t);
}
__device__ __forceinline__ void splitf4h(float4 v, uint2& hi, uint2& lo) {
    __half h0 = __float2half_rn(v.x), h1 = __float2half_rn(v.y),
           h2 = __float2half_rn(v.z), h3 = __float2half_rn(v.w);
    hi.x = pk2h(h0, h1); hi.y = pk2h(h2, h3);
    lo.x = pk2h(__float2half_rn(v.x - __half2float(h0)),
                __float2half_rn(v.y - __half2float(h1)));
    lo.y = pk2h(__float2half_rn(v.z - __half2float(h2)),
                __float2half_rn(v.w - __half2float(h3)));
}
__device__ __forceinline__ void ldm4(uint32_t* r, uint32_t addr) {
    asm volatile("ldmatrix.sync.aligned.m8n8.x4.shared.b16 {%0,%1,%2,%3}, [%4];\n"
                 : "=r"(r[0]), "=r"(r[1]), "=r"(r[2]), "=r"(r[3]) : "r"(addr));
}
__device__ __forceinline__ void ldm4t(uint32_t* r, uint32_t addr) {
    asm volatile("ldmatrix.sync.aligned.m8n8.x4.trans.shared.b16 {%0,%1,%2,%3}, [%4];\n"
                 : "=r"(r[0]), "=r"(r[1]), "=r"(r[2]), "=r"(r[3]) : "r"(addr));
}
__device__ __forceinline__ void mma_f16(float* c, const uint32_t* a, const uint32_t* b) {
    asm volatile(
        "mma.sync.aligned.m16n8k16.row.col.f32.f16.f16.f32 "
        "{%0,%1,%2,%3}, {%4,%5,%6,%7}, {%8,%9}, {%0,%1,%2,%3};\n"
        : "+f"(c[0]), "+f"(c[1]), "+f"(c[2]), "+f"(c[3])
        : "r"(a[0]), "r"(a[1]), "r"(a[2]), "r"(a[3]), "r"(b[0]), "r"(b[1]));
}

// ---------------- weight -> fragment converter (fp16 hi/lo) -----------------
// pair=1: source row remap n -> (n odd ? 1024 + n/2 : n/2) for fused GLU pw1.
__global__ void wfrag(const float* __restrict__ W, uint32_t* __restrict__ out,
                      int Ndim, int Kdim, int NT8, int pair)
{
    const int KT16 = Kdim >> 4;
    size_t idx = (size_t)blockIdx.x * 256 + threadIdx.x;
    size_t total = (size_t)NT8 * KT16 * 128;
    if (idx >= total) return;
    int r     = (int)(idx & 1);
    int l     = (int)((idx >> 1) & 31);
    int plane = (int)((idx >> 6) & 1);
    size_t ft = idx >> 7;
    int k16 = (int)(ft % KT16);
    int n8  = (int)(ft / KT16);
    int n = n8 * 8 + (l >> 2);
    int k = k16 * 16 + (l & 3) * 2 + r * 8;
    float v0 = 0.f, v1 = 0.f;
    if (n < Ndim) {
        int srcn = pair ? ((n & 1) ? 1024 + (n >> 1) : (n >> 1)) : n;
        float2 vv = *(const float2*)&W[(size_t)srcn * Kdim + k];
        v0 = vv.x; v1 = vv.y;
    }
    __half h0 = __float2half_rn(v0), h1 = __float2half_rn(v1);
    uint32_t val = (plane == 0)
        ? pk2h(h0, h1)
        : pk2h(__float2half_rn(v0 - __half2float(h0)),
               __float2half_rn(v1 - __half2float(h1)));
    out[idx] = val;
}

__global__ void biascat(const float* __restrict__ bq, const float* __restrict__ bk,
                        const float* __restrict__ bv, float* __restrict__ out)
{
    int i = blockIdx.x * 256 + threadIdx.x;
    if (i < LNUM * 512) {
        int l = i >> 9, c = i & 511;
        out[l*1536 + c]        = bq[i];
        out[l*1536 + 512 + c]  = bk[i];
        out[l*1536 + 1024 + c] = bv[i];
    }
}
__global__ void bias2(const float* __restrict__ pw1b, float* __restrict__ out)
{
    int i = blockIdx.x * 256 + threadIdx.x;   // LNUM*2048
    if (i < LNUM * 2048) {
        int l = i >> 11, c = i & 2047;
        int src = (c & 1) ? 1024 + (c >> 1) : (c >> 1);
        out[l*2048 + c] = pw1b[(size_t)l*2048 + src];
    }
}

#define ASTR 40

// ======================================================================
// gemm_h: A fp16, B fp16 hi plane. 1 MMA/k-step.
// modes: 0 C fp32 (+extra resid), 2 gate(a from extra), 3 qkv split,
//        4 pair-gate (col even=a, odd=g) -> Ch fp16 width Ndim/2
// ======================================================================
__global__ __launch_bounds__(256, 2)
void gemm_h(const __half* __restrict__ A, const uint32_t* __restrict__ Bf,
            float* __restrict__ C, __half* __restrict__ Ch,
            const float* __restrict__ bias, const float* __restrict__ extra,
            int Mdim, int Ndim, int Kdim, int mode)
{
    __shared__ __align__(16) __half Asm[128][ASTR];

    const int tid  = threadIdx.x;
    const int lane = tid & 31;
    const int warp = tid >> 5;
    const int wm = (warp & 1) * 64;
    const int wn = (warp >> 1) * 32;
    const int bm = blockIdx.y * 128;
    const int bn = blockIdx.x * 128;
    const int KT16 = Kdim >> 4;
    const int n8_0 = (bn + wn) >> 3;

    float acc[4][4][4];
    #pragma unroll
    for (int i = 0; i < 4; i++)
        #pragma unroll
        for (int j = 0; j < 4; j++)
            #pragma unroll
            for (int t = 0; t < 4; t++) acc[i][j][t] = 0.f;

    const int a_m = lane & 15;
    const int a_k = (lane >> 4) << 3;
    const uint32_t sA = (uint32_t)__cvta_generic_to_shared(&Asm[0][0]);

    const int KT = Kdim >> 5;
    for (int kt = 0; kt < KT; kt++) {
        #pragma unroll
        for (int u = 0; u < 2; u++) {
            int f = tid + u * 256;
            int row = f >> 2;
            int c8 = (f & 3) * 8;
            *(uint4*)&Asm[row][c8] =
                *(const uint4*)&A[(size_t)(bm + row) * Kdim + kt*32 + c8];
        }
        __syncthreads();

        #pragma unroll
        for (int ks = 0; ks < 2; ks++) {
            uint32_t bhf[4][2];
            const uint32_t* fb = Bf + ((size_t)n8_0 * KT16 + (kt*2 + ks)) * 128 + lane * 2;
            #pragma unroll
            for (int nt = 0; nt < 4; nt++) {
                uint2 hv = *(const uint2*)(fb + (size_t)nt * KT16 * 128);
                bhf[nt][0] = hv.x; bhf[nt][1] = hv.y;
            }
            #pragma unroll
            for (int mt = 0; mt < 4; mt++) {
                uint32_t ah[4];
                uint32_t addr = sA + (uint32_t)(((wm + mt*16 + a_m) * ASTR) + ks*16 + a_k) * 2;
                ldm4(ah, addr);
                #pragma unroll
                for (int nt = 0; nt < 4; nt++)
                    mma_f16(acc[mt][nt], ah, bhf[nt]);
            }
        }
        __syncthreads();
    }

    const int gr = lane >> 2;
    const int gc = (lane & 3) * 2;
    #pragma unroll
    for (int mt = 0; mt < 4; mt++) {
        #pragma unroll
        for (int nt = 0; nt < 4; nt++) {
            const float* cp = acc[mt][nt];
            int row = bm + wm + mt*16 + gr;
            int col = bn + wn + nt*8 + gc;
            #pragma unroll
            for (int half = 0; half < 2; half++) {
                int rr = row + half*8;
                float v0 = cp[half*2 + 0];
                float v1 = cp[half*2 + 1];
                if (bias) { v0 += bias[col]; v1 += bias[col + 1]; }
                if (mode == 0) {
                    if (extra) {
                        v0 += extra[(size_t)rr * Ndim + col];
                        v1 += extra[(size_t)rr * Ndim + col + 1];
                    }
                    *(float2*)&C[(size_t)rr * Ndim + col] = make_float2(v0, v1);
                } else if (mode == 2) {
                    float a0 = extra[(size_t)rr * Ndim + col];
                    float a1 = extra[(size_t)rr * Ndim + col + 1];
                    __half2 hh = __floats2half2_rn(a0 / (1.f + expf(-v0)),
                                                   a1 / (1.f + expf(-v1)));
                    *(__half2*)&Ch[(size_t)rr * Ndim + col] = hh;
                } else if (mode == 4) {
                    // col even = a, col+1 = g  ->  out channel col/2
                    Ch[(size_t)rr * (Ndim >> 1) + (col >> 1)] =
                        __float2half(v0 / (1.f + expf(-v1)));
                } else { // mode 3: q,k fp32; v fp16
                    if (col < 1024) {
                        *(float2*)&C[(size_t)(col >> 9) * ((size_t)ROWS * ID_)
                                     + (size_t)rr * ID_ + (col & 511)] =
                            make_float2(v0, v1);
                    } else {
                        *(__half2*)&Ch[(size_t)rr * ID_ + (col & 511)] =
                            __floats2half2_rn(v0, v1);
                    }
                }
            }
        }
    }
}

// ======================================================================
// proj_favor: fused  fph = favor( dn * qk @ proj^T )
// CTA: 64 rows x 272 cols. 8 warps = 4 row-groups x 2 col-halves (136 each).
// A fp32 split hi/lo (3 MMAs, exp needs precision). Writes fph fp16 directly.
// ======================================================================
#define PFP 72
__global__ __launch_bounds__(256, 2)
void proj_favor(const float* __restrict__ qk, const uint32_t* __restrict__ Bf,
                __half* __restrict__ fph, float dn, float ratio)
{
    __shared__ __align__(16) __half Ah[64][PFP];
    __shared__ __align__(16) __half Al[64][PFP];
    __shared__ float ds[64];
    __shared__ float hm[8][16];

    const int tid = threadIdx.x;
    const int lane = tid & 31;
    const int warp = tid >> 5;
    const int rg = warp >> 1;
    const int hn = warp & 1;
    const int wm = rg * 16;
    const size_t bm = (size_t)blockIdx.x * 64;
    const int isQ = (bm < (size_t)RH);

    // fill A: 64x64 fp32 -> hi/lo fp16 planes
    #pragma unroll
    for (int u = 0; u < 4; u++) {
        int f = tid + u * 256;
        int row = f >> 4;
        int c4 = (f & 15) * 4;
        float4 v = *(const float4*)&qk[(bm + row) * DH_ + c4];
        uint2 hi, lo;
        splitf4h(v, hi, lo);
        *(uint2*)&Ah[row][c4] = hi;
        *(uint2*)&Al[row][c4] = lo;
    }
    __syncthreads();

    // diag[row] = sum q^2 / 16  (4 threads per row)
    {
        int row = tid >> 2;
        int seg = (tid & 3) * 16;
        float s = 0.f;
        #pragma unroll
        for (int j = 0; j < 16; j++) {
            float q = __half2float(Ah[row][seg + j]) + __half2float(Al[row][seg + j]);
            s += q * q;
        }
        s += __shfl_xor_sync(0xffffffffu, s, 1);
        s += __shfl_xor_sync(0xffffffffu, s, 2);
        if ((tid & 3) == 0) ds[row] = s * 0.0625f;
    }

    float acc[17][4];
    #pragma unroll
    for (int nt = 0; nt < 17; nt++)
        #pragma unroll
        for (int j = 0; j < 4; j++) acc[nt][j] = 0.f;

    const uint32_t sH = (uint32_t)__cvta_generic_to_shared(&Ah[0][0]);
    const uint32_t sL = (uint32_t)__cvta_generic_to_shared(&Al[0][0]);
    const int a_m = lane & 15;
    const int a_k = (lane >> 4) << 3;
    const int n8base = hn * 17;

    #pragma unroll
    for (int k16 = 0; k16 < 4; k16++) {
        uint32_t ah[4], al[4];
        uint32_t off = (uint32_t)((wm + a_m) * PFP + k16*16 + a_k) * 2;
        ldm4(ah, sH + off);
        ldm4(al, sL + off);
        #pragma unroll
        for (int nt = 0; nt < 17; nt++) {
            const uint32_t* fb = Bf + ((size_t)(n8base + nt) * 4 + k16) * 128 + lane * 2;
            uint2 hv = *(const uint2*)fb;
            uint2 lv = *(const uint2*)(fb + 64);
            uint32_t bh[2] = {hv.x, hv.y};
            uint32_t bl[2] = {lv.x, lv.y};
            mma_f16(acc[nt], ah, bh);
            mma_f16(acc[nt], ah, bl);
            mma_f16(acc[nt], al, bh);
        }
    }

    const int gr = lane >> 2;
    const int gc = (lane & 3) * 2;
    const int cbase = hn * 136 + gc;

    // per-row max over this warp's half (queries only)
    if (isQ) {
        float mx0 = -1e30f, mx1 = -1e30f;
        #pragma unroll
        for (int nt = 0; nt < 17; nt++) {
            int c0 = cbase + nt*8;
            if (c0 < MM)     { mx0 = fmaxf(mx0, acc[nt][0]); mx1 = fmaxf(mx1, acc[nt][2]); }
            if (c0 + 1 < MM) { mx0 = fmaxf(mx0, acc[nt][1]); mx1 = fmaxf(mx1, acc[nt][3]); }
        }
        mx0 = fmaxf(mx0, __shfl_xor_sync(0xffffffffu, mx0, 1));
        mx0 = fmaxf(mx0, __shfl_xor_sync(0xffffffffu, mx0, 2));
        mx1 = fmaxf(mx1, __shfl_xor_sync(0xffffffffu, mx1, 1));
        mx1 = fmaxf(mx1, __shfl_xor_sync(0xffffffffu, mx1, 2));
        if ((lane & 3) == 0) { hm[warp][gr] = mx0; hm[warp][gr + 8] = mx1; }
    }
    __syncthreads();

    float fmx0 = 0.f, fmx1 = 0.f;
    if (isQ) {
        fmx0 = fmaxf(hm[warp][gr],     hm[warp ^ 1][gr])     * dn;
        fmx1 = fmaxf(hm[warp][gr + 8], hm[warp ^ 1][gr + 8]) * dn;
    }
    const float d0 = ds[wm + gr];
    const float d1 = ds[wm + gr + 8];
    __half* o0 = fph + (bm + wm + gr) * MMP;
    __half* o1 = o0 + (size_t)8 * MMP;

    #pragma unroll
    for (int nt = 0; nt < 17; nt++) {
        #pragma unroll
        for (int j = 0; j < 2; j++) {
            int col = cbase + nt*8 + j;
            float va = acc[nt][j]     * dn;
            float vb = acc[nt][2 + j] * dn;
            float ra, rb;
            if (col < MM) {
                if (isQ) {
                    ra = ratio * (expf(va - d0 - fmx0) + 1e-4f);
                    rb = ratio * (expf(vb - d1 - fmx1) + 1e-4f);
                } else {
                    ra = ratio * expf(va - d0 + 1e-4f);
                    rb = ratio * expf(vb - d1 + 1e-4f);
                }
            } else { ra = 0.f; rb = 0.f; }
            o0[col] = __float2half(ra);
            o1[col] = __float2half(rb);
        }
    }
}

// ======================================================================
// ctx_mma: single-fp16 kp^T @ v over 256-seq chunk -> fp32 partials
// ======================================================================
#define KPITCH 280
#define VPITCH 72
__global__ __launch_bounds__(256, 1)
void ctx_mma(const __half* __restrict__ kp, const __half* __restrict__ v,
             float* __restrict__ part)
{
    __shared__ __align__(16) __half Kp[32][KPITCH];
    __shared__ __align__(16) __half Vs[32][VPITCH];

    const int tid = threadIdx.x;
    const int lane = tid & 31;
    const int warp = tid >> 5;
    const int kc = blockIdx.x;
    const int bh = blockIdx.y;
    const int b = bh >> 3, h = bh & 7;

    const int nmt = (warp == 0) ? 3 : 2;
    int mts[3];
    mts[0] = 2*warp; mts[1] = 2*warp + 1; mts[2] = 16;

    float acc[3][8][4];
    #pragma unroll
    for (int t = 0; t < 3; t++)
        #pragma unroll
        for (int n = 0; n < 8; n++)
            #pragma unroll
            for (int j = 0; j < 4; j++) acc[t][n][j] = 0.f;

    const __half* kpb = kp + ((size_t)(b * SEQ) * H_ + h) * MMP;
    const __half* vb  = v  + ((size_t)(b * SEQ) * H_ + h) * DH_;

    const uint32_t sK = (uint32_t)__cvta_generic_to_shared(&Kp[0][0]);
    const uint32_t sV = (uint32_t)__cvta_generic_to_shared(&Vs[0][0]);
    const int r7 = lane & 7;

    for (int it = 0; it < 8; it++) {
        const int n0 = kc * 256 + it * 32;
        for (int f = tid; f < 32*34; f += 256) {
            int nn = f / 34, c8 = (f % 34) * 8;
            *(uint4*)&Kp[nn][c8] =
                *(const uint4*)&kpb[(size_t)(n0 + nn) * (H_*MMP) + c8];
        }
        {
            int nn = tid >> 3, c8 = (tid & 7) * 8;
            *(uint4*)&Vs[nn][c8] =
                *(const uint4*)&vb[(size_t)(n0 + nn) * (H_*DH_) + c8];
        }
        __syncthreads();

        #pragma unroll
        for (int ks = 0; ks < 2; ks++) {
            uint32_t bhf[8][2];
            #pragma unroll
            for (int g = 0; g < 4; g++) {
                int row = ks*16 + ((lane >> 3) & 1) * 8 + r7;
                int col = g*16 + (lane >> 4) * 8;
                uint32_t r[4];
                ldm4t(r, sV + (uint32_t)(row * VPITCH + col) * 2);
                bhf[2*g][0] = r[0]; bhf[2*g][1] = r[1];
                bhf[2*g+1][0] = r[2]; bhf[2*g+1][1] = r[3];
            }
            #pragma unroll
            for (int t = 0; t < 3; t++) {
                if (t < nmt) {
                    int m0 = mts[t] * 16;
                    int row = ks*16 + ((lane >> 4) & 1) * 8 + r7;
                    int col = m0 + ((lane >> 3) & 1) * 8;
                    uint32_t ah[4];
                    ldm4t(ah, sK + (uint32_t)(row * KPITCH + col) * 2);
                    #pragma unroll
                    for (int nt = 0; nt < 8; nt++)
                        mma_f16(acc[t][nt], ah, bhf[nt]);
                }
            }
        }
        __syncthreads();
    }

    const int gr = lane >> 2;
    const int gc = (lane & 3) * 2;
    float* pb = part + ((size_t)(bh * 8 + kc)) * 272 * 64;
    #pragma unroll
    for (int t = 0; t < 3; t++) {
        if (t < nmt) {
            int m0 = mts[t] * 16;
            #pragma unroll
            for (int nt = 0; nt < 8; nt++) {
                int e = nt*8 + gc;
                pb[(size_t)(m0 + gr) * 64 + e]     = acc[t][nt][0];
                pb[(size_t)(m0 + gr) * 64 + e + 1] = acc[t][nt][1];
                pb[(size_t)(m0 + gr + 8) * 64 + e]     = acc[t][nt][2];
                pb[(size_t)(m0 + gr + 8) * 64 + e + 1] = acc[t][nt][3];
            }
        }
    }
}

// ---------------- reduceT: sum partials -> ctxT fp16 [bh][e][m] (+ks row) ---
__global__ void reduceT(const float* __restrict__ part, const float* __restrict__ ks,
                        __half* __restrict__ ctxT)
{
    const int bh = blockIdx.y;
    const int m0 = blockIdx.x * 64;
    const int mw = (272 - m0 < 64) ? (272 - m0) : 64;
    __shared__ float sm[64][65];
    const int t = threadIdx.x;
    const int e  = t & 63;
    const int mr = t >> 6;
    for (int mm = mr; mm < mw; mm += 4) {
        float s = 0.f;
        #pragma unroll
        for (int kc = 0; kc < 8; kc++)
            s += part[(((size_t)(bh*8 + kc)) * 272 + m0 + mm) * 64 + e];
        sm[mm][e] = s;
    }
    __syncthreads();
    const int m  = t & 63;
    const int er = t >> 6;
    for (int ee = er; ee < 80; ee += 4) {
        if (m0 + m < 288) {
            float val = 0.f;
            if (m < mw) {
                if (ee < 64)       val = sm[m][ee];
                else if (ee == 64) val = ks[(size_t)bh * MMP + m0 + m];
            }
            ctxT[((size_t)bh * 80 + ee) * 288 + m0 + m] = __float2half(val);
        }
    }
}

// ======================================================================
// attn_mma: qp(fp16) @ ctxT^T(fp16); col 64 = dsum; out fp16 att
// ======================================================================
#define APITCH 24
__global__ __launch_bounds__(256, 2)
void attn_mma(const __half* __restrict__ qp, const __half* __restrict__ ctxT,
              __half* __restrict__ out)
{
    __shared__ __align__(16) __half As[128][APITCH];
    __shared__ __align__(16) __half Bs[80][APITCH];

    const int tid = threadIdx.x;
    const int lane = tid & 31;
    const int warp = tid >> 5;
    const int bm = blockIdx.x * 128;
    const int bh = blockIdx.y;
    const int b = bh >> 3, h = bh & 7;
    const int wm = warp * 16;

    const __half* qpb = qp + ((size_t)(b * SEQ) * H_ + h) * MMP;
    const __half* cb  = ctxT + (size_t)bh * 80 * 288;

    float acc[9][4];
    #pragma unroll
    for (int n = 0; n < 9; n++)
        #pragma unroll
        for (int j = 0; j < 4; j++) acc[n][j] = 0.f;

    const uint32_t sA = (uint32_t)__cvta_generic_to_shared(&As[0][0]);
    const uint32_t sB = (uint32_t)__cvta_generic_to_shared(&Bs[0][0]);
    const int a_m = lane & 15;
    const int a_k = (lane >> 4) << 3;
    const int b_n = (lane & 7) | ((lane & 16) >> 1);
    const int b_k = lane & 8;

    for (int k16 = 0; k16 < 17; k16++) {
        const int k0 = k16 * 16;
        {
            int row = tid >> 1, c8 = (tid & 1) * 8;
            *(uint4*)&As[row][c8] =
                *(const uint4*)&qpb[(size_t)(bm + row) * (H_*MMP) + k0 + c8];
        }
        if (tid < 160) {
            int row = tid >> 1, c8 = (tid & 1) * 8;
            *(uint4*)&Bs[row][c8] =
                *(const uint4*)&cb[(size_t)row * 288 + k0 + c8];
        }
        __syncthreads();

        uint32_t bhf[10][2];
        #pragma unroll
        for (int p = 0; p < 5; p++) {
            uint32_t r[4];
            ldm4(r, sB + (uint32_t)((p*16 + b_n) * APITCH + b_k) * 2);
            bhf[2*p][0] = r[0]; bhf[2*p][1] = r[1];
            bhf[2*p+1][0] = r[2]; bhf[2*p+1][1] = r[3];
        }
        {
            uint32_t ah[4];
            ldm4(ah, sA + (uint32_t)((wm + a_m) * APITCH + a_k) * 2);
            #pragma unroll
            for (int nt = 0; nt < 9; nt++)
                mma_f16(acc[nt], ah, bhf[nt]);
        }
        __syncthreads();
    }

    const int gr = lane >> 2;
    const int gc = (lane & 3) * 2;
    float d0 = __shfl_sync(0xffffffffu, acc[8][0], gr * 4);
    float d1 = __shfl_sync(0xffffffffu, acc[8][2], gr * 4);
    const float dinv0 = 1.f / (d0 + 1e-8f);
    const float dinv1 = 1.f / (d1 + 1e-8f);

    const size_t row0 = ((size_t)(b * SEQ + bm + wm + gr) * H_ + h) * DH_;
    const size_t row1 = row0 + (size_t)8 * H_ * DH_;
    #pragma unroll
    for (int nt = 0; nt < 8; nt++) {
        int e = nt*8 + gc;
        *(__half2*)&out[row0 + e] = __floats2half2_rn(acc[nt][0]*dinv0, acc[nt][1]*dinv0);
        *(__half2*)&out[row1 + e] = __floats2half2_rn(acc[nt][2]*dinv1, acc[nt][3]*dinv1);
    }
}

// ---------------- LayerNorm (fp16 out) -----------------
__global__ void ln_kernel(const float* __restrict__ x, const float* __restrict__ g,
                          const float* __restrict__ b, __half* __restrict__ out)
{
    const int r = blockIdx.x;
    const int t = threadIdx.x;
    const float4 v = ((const float4*)(x + (size_t)r * D_))[t];
    float s  = v.x + v.y + v.z + v.w;
    float ss = v.x*v.x + v.y*v.y + v.z*v.z + v.w*v.w;
    __shared__ float rs[128], rss[128];
    rs[t] = s; rss[t] = ss;
    __syncthreads();
    for (int o = 64; o > 0; o >>= 1) {
        if (t < o) { rs[t] += rs[t+o]; rss[t] += rss[t+o]; }
        __syncthreads();
    }
    const float mu   = rs[0] * (1.f / D_);
    const float var  = rss[0] * (1.f / D_) - mu * mu;
    const float rstd = rsqrtf(var + 1e-5f);
    const float4 gg = ((const float4*)g)[t];
    const float4 bb = ((const float4*)b)[t];
    __half2 p0 = __floats2half2_rn((v.x - mu) * rstd * gg.x + bb.x,
                                   (v.y - mu) * rstd * gg.y + bb.y);
    __half2 p1 = __floats2half2_rn((v.z - mu) * rstd * gg.z + bb.z,
                                   (v.w - mu) * rstd * gg.w + bb.w);
    uint2 st;
    st.x = *reinterpret_cast<uint32_t*>(&p0);
    st.y = *reinterpret_cast<uint32_t*>(&p1);
    *(uint2*)&out[(size_t)r * D_ + t * 4] = st;
}

// ---------------- ksum two-stage (fp16 in) ---------------
__global__ void ksum1(const __half* __restrict__ kp, float* __restrict__ part)
{
    const int bh = blockIdx.y;
    const int chunk = blockIdx.x;
    const int m = threadIdx.x;
    if (m >= MMP) return;
    const int b = bh >> 3, h = bh & 7;
    const __half* base = kp + ((size_t)(b * SEQ + chunk * 256) * H_ + h) * MMP + m;
    const size_t stride = (size_t)H_ * MMP;
    float s0 = 0.f, s1 = 0.f, s2 = 0.f, s3 = 0.f;
    for (int n = 0; n < 256; n += 4) {
        s0 += __half2float(base[(n+0) * stride]);
        s1 += __half2float(base[(n+1) * stride]);
        s2 += __half2float(base[(n+2) * stride]);
        s3 += __half2float(base[(n+3) * stride]);
    }
    part[((size_t)bh * 8 + chunk) * MMP + m] = (s0 + s1) + (s2 + s3);
}
__global__ void ksum2(const float* __restrict__ part, float* __restrict__ ks)
{
    const int bh = blockIdx.x;
    const int m = threadIdx.x;
    if (m >= MMP) return;
    float s = 0.f;
    #pragma unroll
    for (int c = 0; c < 8; c++) s += part[((size_t)bh * 8 + c) * MMP + m];
    ks[(size_t)bh * MMP + m] = s;
}

// ---------------- depthwise conv + SiLU (fp16 in/out) ---------------
#define DC_CH 128
#define DC_TN 32
__global__ __launch_bounds__(256)
void dwconv2(const __half* __restrict__ gin, const float* __restrict__ w,
             const float* __restrict__ bias, __half* __restrict__ out)
{
    __shared__ float sin_[DC_TN + 30][DC_CH];
    __shared__ float sw[DC_CH * KW];

    const int c0 = blockIdx.x * DC_CH;
    const int n0 = blockIdx.y * DC_TN;
    const int b  = blockIdx.z;
    const int t  = threadIdx.x;

    for (int i = t; i < DC_CH * KW; i += 256)
        sw[i] = w[(size_t)c0 * KW + i];
    #pragma unroll
    for (int u = 0; u < (DC_TN + 30) * DC_CH / 256; u++) {
        int f = t + u * 256;
        int rowi = f >> 7;
        int ch = f & 127;
        int n = n0 + rowi - 15;
        sin_[rowi][ch] = ((unsigned)n < SEQ)
            ? __half2float(gin[((size_t)(b * SEQ + n) << 10) + c0 + ch]) : 0.f;
    }
    __syncthreads();

    const int ch = t & 127;
    const int nl0 = (t >> 7) * 16;

    float wr[KW];
    #pragma unroll
    for (int k = 0; k < KW; k++) wr[k] = sw[ch * KW + k];
    const float bb = bias[c0 + ch];

    #pragma unroll
    for (int i = 0; i < 16; i++) {
        float acc = bb;
        #pragma unroll
        for (int k = 0; k < KW; k++)
            acc += sin_[nl0 + i + k][ch] * wr[k];
        float o = acc / (1.f + expf(-acc));
        out[((size_t)(b * SEQ + n0 + nl0 + i) << 10) + c0 + ch] = __float2half(o);
    }
}

// ---------------- host orchestration ----------------------------------------
static inline void run_gemm_h(const __half* A, const uint32_t* Bf, float* C,
                              __half* Ch, const float* bias, const float* extra,
                              int Mdim, int Ndim, int Kdim, int mode)
{
    dim3 grid(Ndim / 128, Mdim / 128);
    gemm_h<<<grid, 256>>>(A, Bf, C, Ch, bias, extra, Mdim, Ndim, Kdim, mode);
}
static inline void run_wfrag(const float* W, uint32_t* out, int Ndim, int Kdim,
                             int NT8, int pair)
{
    size_t total = (size_t)NT8 * (Kdim >> 4) * 128;
    wfrag<<<(unsigned)((total + 255) / 256), 256>>>(W, out, Ndim, Kdim, NT8, pair);
}

extern "C" void kernel_launch(void* const* d_in, const int* in_sizes, int n_in,
                              void* d_out, int out_size)
{
    const float* x    = (const float*)d_in[0];
    const float* ln1g = (const float*)d_in[1];
    const float* ln1b = (const float*)d_in[2];
    const float* wq   = (const float*)d_in[3];
    const float* bq   = (const float*)d_in[4];
    const float* wk   = (const float*)d_in[5];
    const float* bk   = (const float*)d_in[6];
    const float* wv   = (const float*)d_in[7];
    const float* bv   = (const float*)d_in[8];
    const float* wo   = (const float*)d_in[9];
    const float* bo   = (const float*)d_in[10];
    const float* proj = (const float*)d_in[11];
    const float* ln2g = (const float*)d_in[12];
    const float* ln2b = (const float*)d_in[13];
    const float* pw1w = (const float*)d_in[14];
    const float* pw1b = (const float*)d_in[15];
    const float* dww  = (const float*)d_in[16];
    const float* dwb  = (const float*)d_in[17];
    const float* pw2w = (const float*)d_in[18];
    const float* pw2b = (const float*)d_in[19];
    float* xo = (float*)d_out;

    __half *h, *vh, *fph, *ctxT, *att, *glu, *dw;
    float *qk, *ks, *part, *cpart, *qkvb, *pw1bi;
    uint32_t* wf;
    cudaGetSymbolAddress((void**)&h,     g_h);
    cudaGetSymbolAddress((void**)&qk,    g_qk);
    cudaGetSymbolAddress((void**)&vh,    g_vh);
    cudaGetSymbolAddress((void**)&fph,   g_fph);
    cudaGetSymbolAddress((void**)&ks,    g_ks);
    cudaGetSymbolAddress((void**)&part,  g_part);
    cudaGetSymbolAddress((void**)&cpart, g_cpart);
    cudaGetSymbolAddress((void**)&ctxT,  g_ctxT);
    cudaGetSymbolAddress((void**)&att,   g_att);
    cudaGetSymbolAddress((void**)&glu,   g_glu);
    cudaGetSymbolAddress((void**)&dw,    g_dw);
    cudaGetSymbolAddress((void**)&qkvb,  g_qkvbias);
    cudaGetSymbolAddress((void**)&pw1bi, g_pw1bi);
    cudaGetSymbolAddress((void**)&wf,    g_wfrag);

    __half* qph = fph;
    __half* kph = fph + (size_t)RH * MMP;

    const size_t OFF_WQ = 0;
    const size_t OFF_WO = OFF_WQ + 3*FR_QKV;
    const size_t OFF_P1 = OFF_WO + FR_QKV;
    const size_t OFF_P2 = OFF_P1 + FR_PW1;
    const size_t OFF_PR = OFF_P2 + FR_PW2;

    for (int l = 0; l < LNUM; l++) {
        uint32_t* lw = wf + (size_t)l * FR_LSTR;
        run_wfrag(wq   + (size_t)l*ID_*D_,    lw + OFF_WQ,            512, 512, 64, 0);
        run_wfrag(wk   + (size_t)l*ID_*D_,    lw + OFF_WQ + FR_QKV,   512, 512, 64, 0);
        run_wfrag(wv   + (size_t)l*ID_*D_,    lw + OFF_WQ + 2*FR_QKV, 512, 512, 64, 0);
        run_wfrag(wo   + (size_t)l*ID_*D_,    lw + OFF_WO, 512, 512, 64, 0);
        run_wfrag(pw1w + (size_t)l*2048*D_,   lw + OFF_P1, 2048, 512, 256, 1);
        run_wfrag(pw2w + (size_t)l*D_*INNER_, lw + OFF_P2, 512, 1024, 64, 0);
        run_wfrag(proj + (size_t)l*MM*DH_,    lw + OFF_PR, 266, 64, 48, 0);
    }
    biascat<<<(LNUM*512 + 255)/256, 256>>>(bq, bk, bv, qkvb);
    bias2<<<(LNUM*2048 + 255)/256, 256>>>(pw1b, pw1bi);

    cudaMemcpyAsync(xo, x, (size_t)ROWS * D_ * sizeof(float),
                    cudaMemcpyDeviceToDevice);

    const float dn    = (float)(1.0 / sqrt(sqrt(64.0)));
    const float ratio = (float)(1.0 / sqrt(266.0));

    for (int l = 0; l < LNUM; l++) {
        uint32_t* lw = wf + (size_t)l * FR_LSTR;

        ln_kernel<<<ROWS, 128>>>(xo, ln1g + (size_t)l*D_, ln1b + (size_t)l*D_, h);
        run_gemm_h(h, lw + OFF_WQ, qk, vh, qkvb + (size_t)l*1536, nullptr,
                   ROWS, 1536, D_, 3);
        // fused proj + favor postprocess -> fph fp16 directly
        proj_favor<<<(2*RH)/64, 256>>>(qk, lw + OFF_PR, fph, dn, ratio);
        {
            dim3 k1(8, NBH);
            ksum1<<<k1, 288>>>(kph, part);
            ksum2<<<NBH, 288>>>(part, ks);
            dim3 cg(8, NBH);
            ctx_mma<<<cg, 256>>>(kph, vh, cpart);
            dim3 rg(5, NBH);
            reduceT<<<rg, 256>>>(cpart, ks, ctxT);
            dim3 ag(SEQ / 128, NBH);
            attn_mma<<<ag, 256>>>(qph, ctxT, att);
        }
        run_gemm_h(att, lw + OFF_WO, xo, nullptr, bo + (size_t)l*D_, xo,
                   ROWS, D_, ID_, 0);
        ln_kernel<<<ROWS, 128>>>(xo, ln2g + (size_t)l*D_, ln2b + (size_t)l*D_, h);
        // fused pw1 + GLU (interleaved a/g weights) -> glu fp16
        run_gemm_h(h, lw + OFF_P1, nullptr, glu, pw1bi + (size_t)l*2048, nullptr,
                   ROWS, 2048, D_, 4);
        {
            dim3 dg(INNER_/DC_CH, SEQ/DC_TN, B_);
            dwconv2<<<dg, 256>>>(glu, dww + (size_t)l*INNER_*KW, dwb + (size_t)l*INNER_, dw);
        }
        run_gemm_h(dw, lw + OFF_P2, xo, nullptr, pw2b + (size_t)l*D_, xo,
                   ROWS, D_, INNER_, 0);
    }
}

// round 14
// speedup vs baseline: 1.1280x; 1.0243x over previous
#include <cuda_runtime.h>
#include <cuda_fp16.h>
#include <math.h>
#include <stdint.h>

// ---------------- problem constants ----------------
#define B_     4
#define SEQ    2048
#define D_     512
#define H_     8
#define DH_    64
#define ID_    512
#define MM     266
#define MMP    272
#define INNER_ 1024
#define KW     31
#define LNUM   6
#define ROWS   (B_*SEQ)
#define RH     (ROWS*H_)
#define NBH    (B_*H_)
#define NCHK   4               // ctx seq chunks

// ---------------- device scratch ----------------
__device__ __half g_h    [ROWS*D_];
__device__ float  g_qk   [2*(size_t)ROWS*ID_];
__device__ __half g_vh   [ROWS*ID_];
__device__ __half g_fph  [2*(size_t)RH*MMP];
__device__ float  g_ks   [NBH*MMP];
__device__ float  g_part [NBH*8*MMP];
__device__ float  g_cpart[(size_t)NBH*NCHK*MMP*DH_];
__device__ __half g_ctxT [(size_t)NBH*80*288];
__device__ __half g_att  [ROWS*ID_];
__device__ __half g_glu  [ROWS*INNER_];
__device__ __half g_dw   [ROWS*INNER_];
__device__ float  g_qkvbias[LNUM*1536];
__device__ float  g_pw1bi [LNUM*2048];

#define FR_QKV  (64*32*128)
#define FR_PW1  (256*32*128)
#define FR_PW2  (64*64*128)
#define FR_PROJ (48*4*128)
#define FR_LSTR (4*FR_QKV + FR_PW1 + FR_PW2 + FR_PROJ)
__device__ uint32_t g_wfrag[(size_t)LNUM * FR_LSTR];

// ---------------- helpers ----------------
__device__ __forceinline__ uint32_t pk2h(__half a, __half b) {
    __half2 t = __halves2half2(a, b);
    return *reinterpret_cast<uint32_t*>(&t);
}
__device__ __forceinline__ void splitf4h(float4 v, uint2& hi, uint2& lo) {
    __half h0 = __float2half_rn(v.x), h1 = __float2half_rn(v.y),
           h2 = __float2half_rn(v.z), h3 = __float2half_rn(v.w);
    hi.x = pk2h(h0, h1); hi.y = pk2h(h2, h3);
    lo.x = pk2h(__float2half_rn(v.x - __half2float(h0)),
                __float2half_rn(v.y - __half2float(h1)));
    lo.y = pk2h(__float2half_rn(v.z - __half2float(h2)),
                __float2half_rn(v.w - __half2float(h3)));
}
__device__ __forceinline__ void ldm4(uint32_t* r, uint32_t addr) {
    asm volatile("ldmatrix.sync.aligned.m8n8.x4.shared.b16 {%0,%1,%2,%3}, [%4];\n"
                 : "=r"(r[0]), "=r"(r[1]), "=r"(r[2]), "=r"(r[3]) : "r"(addr));
}
__device__ __forceinline__ void ldm4t(uint32_t* r, uint32_t addr) {
    asm volatile("ldmatrix.sync.aligned.m8n8.x4.trans.shared.b16 {%0,%1,%2,%3}, [%4];\n"
                 : "=r"(r[0]), "=r"(r[1]), "=r"(r[2]), "=r"(r[3]) : "r"(addr));
}
__device__ __forceinline__ void mma_f16(float* c, const uint32_t* a, const uint32_t* b) {
    asm volatile(
        "mma.sync.aligned.m16n8k16.row.col.f32.f16.f16.f32 "
        "{%0,%1,%2,%3}, {%4,%5,%6,%7}, {%8,%9}, {%0,%1,%2,%3};\n"
        : "+f"(c[0]), "+f"(c[1]), "+f"(c[2]), "+f"(c[3])
        : "r"(a[0]), "r"(a[1]), "r"(a[2]), "r"(a[3]), "r"(b[0]), "r"(b[1]));
}
__device__ __forceinline__ void cpa16(uint32_t dst, const void* src) {
    asm volatile("cp.async.cg.shared.global [%0], [%1], 16;\n"
                 :: "r"(dst), "l"(src) : "memory");
}

// ---------------- weight -> fragment converter (fp16 hi/lo) -----------------
__global__ void wfrag(const float* __restrict__ W, uint32_t* __restrict__ out,
                      int Ndim, int Kdim, int NT8, int pair)
{
    const int KT16 = Kdim >> 4;
    size_t idx = (size_t)blockIdx.x * 256 + threadIdx.x;
    size_t total = (size_t)NT8 * KT16 * 128;
    if (idx >= total) return;
    int r     = (int)(idx & 1);
    int l     = (int)((idx >> 1) & 31);
    int plane = (int)((idx >> 6) & 1);
    size_t ft = idx >> 7;
    int k16 = (int)(ft % KT16);
    int n8  = (int)(ft / KT16);
    int n = n8 * 8 + (l >> 2);
    int k = k16 * 16 + (l & 3) * 2 + r * 8;
    float v0 = 0.f, v1 = 0.f;
    if (n < Ndim) {
        int srcn = pair ? ((n & 1) ? 1024 + (n >> 1) : (n >> 1)) : n;
        float2 vv = *(const float2*)&W[(size_t)srcn * Kdim + k];
        v0 = vv.x; v1 = vv.y;
    }
    __half h0 = __float2half_rn(v0), h1 = __float2half_rn(v1);
    uint32_t val = (plane == 0)
        ? pk2h(h0, h1)
        : pk2h(__float2half_rn(v0 - __half2float(h0)),
               __float2half_rn(v1 - __half2float(h1)));
    out[idx] = val;
}

__global__ void biascat(const float* __restrict__ bq, const float* __restrict__ bk,
                        const float* __restrict__ bv, float* __restrict__ out)
{
    int i = blockIdx.x * 256 + threadIdx.x;
    if (i < LNUM * 512) {
        int l = i >> 9, c = i & 511;
        out[l*1536 + c]        = bq[i];
        out[l*1536 + 512 + c]  = bk[i];
        out[l*1536 + 1024 + c] = bv[i];
    }
}
__global__ void bias2(const float* __restrict__ pw1b, float* __restrict__ out)
{
    int i = blockIdx.x * 256 + threadIdx.x;
    if (i < LNUM * 2048) {
        int l = i >> 11, c = i & 2047;
        int src = (c & 1) ? 1024 + (c >> 1) : (c >> 1);
        out[l*2048 + c] = pw1b[(size_t)l*2048 + src];
    }
}

#define ASTR 40
#define STAGEB (128*ASTR*2)

// ======================================================================
// gemm_h: A fp16 via cp.async double buffer, B fp16 hi fragments.
// modes: 0 C fp32 (+extra resid), 3 qkv split, 4 pair-gate
// ======================================================================
__global__ __launch_bounds__(256, 2)
void gemm_h(const __half* __restrict__ A, const uint32_t* __restrict__ Bf,
            float* __restrict__ C, __half* __restrict__ Ch,
            const float* __restrict__ bias, const float* __restrict__ extra,
            int Mdim, int Ndim, int Kdim, int mode)
{
    __shared__ __align__(16) __half Asm[2][128][ASTR];

    const int tid  = threadIdx.x;
    const int lane = tid & 31;
    const int warp = tid >> 5;
    const int wm = (warp & 1) * 64;
    const int wn = (warp >> 1) * 32;
    const int bm = blockIdx.y * 128;
    const int bn = blockIdx.x * 128;
    const int KT16 = Kdim >> 4;
    const int n8_0 = (bn + wn) >> 3;

    float acc[4][4][4];
    #pragma unroll
    for (int i = 0; i < 4; i++)
        #pragma unroll
        for (int j = 0; j < 4; j++)
            #pragma unroll
            for (int t = 0; t < 4; t++) acc[i][j][t] = 0.f;

    const int a_m = lane & 15;
    const int a_k = (lane >> 4) << 3;
    const uint32_t sA = (uint32_t)__cvta_generic_to_shared(&Asm[0][0][0]);

    const int r0 = tid >> 2;        // fill rows: 0..63 (+64 on second pass)
    const int c8 = (tid & 3) * 8;

    const int KT = Kdim >> 5;

    auto issue = [&](int kt, int st) {
        #pragma unroll
        for (int u = 0; u < 2; u++) {
            int row = r0 + u * 64;
            cpa16(sA + (uint32_t)st * STAGEB + (uint32_t)(row * ASTR + c8) * 2,
                  &A[(size_t)(bm + row) * Kdim + kt*32 + c8]);
        }
        asm volatile("cp.async.commit_group;\n" ::: "memory");
    };

    issue(0, 0);
    if (KT > 1) issue(1, 1);

    for (int kt = 0; kt < KT; kt++) {
        const int st = kt & 1;
        if (kt + 1 < KT) asm volatile("cp.async.wait_group 1;\n" ::: "memory");
        else             asm volatile("cp.async.wait_group 0;\n" ::: "memory");
        __syncthreads();

        // hoist B fragments for both ks halves
        uint32_t bhf[2][4][2];
        #pragma unroll
        for (int ks = 0; ks < 2; ks++) {
            const uint32_t* fb = Bf + ((size_t)n8_0 * KT16 + (kt*2 + ks)) * 128 + lane * 2;
            #pragma unroll
            for (int nt = 0; nt < 4; nt++) {
                uint2 hv = *(const uint2*)(fb + (size_t)nt * KT16 * 128);
                bhf[ks][nt][0] = hv.x; bhf[ks][nt][1] = hv.y;
            }
        }
        const uint32_t stBase = sA + (uint32_t)st * STAGEB;
        #pragma unroll
        for (int ks = 0; ks < 2; ks++) {
            #pragma unroll
            for (int mt = 0; mt < 4; mt++) {
                uint32_t ah[4];
                uint32_t addr = stBase + (uint32_t)(((wm + mt*16 + a_m) * ASTR) + ks*16 + a_k) * 2;
                ldm4(ah, addr);
                #pragma unroll
                for (int nt = 0; nt < 4; nt++)
                    mma_f16(acc[mt][nt], ah, bhf[ks][nt]);
            }
        }
        __syncthreads();
        if (kt + 2 < KT) issue(kt + 2, st);
    }

    const int gr = lane >> 2;
    const int gc = (lane & 3) * 2;
    #pragma unroll
    for (int mt = 0; mt < 4; mt++) {
        #pragma unroll
        for (int nt = 0; nt < 4; nt++) {
            const float* cp = acc[mt][nt];
            int row = bm + wm + mt*16 + gr;
            int col = bn + wn + nt*8 + gc;
            #pragma unroll
            for (int half = 0; half < 2; half++) {
                int rr = row + half*8;
                float v0 = cp[half*2 + 0];
                float v1 = cp[half*2 + 1];
                if (bias) { v0 += bias[col]; v1 += bias[col + 1]; }
                if (mode == 0) {
                    if (extra) {
                        v0 += extra[(size_t)rr * Ndim + col];
                        v1 += extra[(size_t)rr * Ndim + col + 1];
                    }
                    *(float2*)&C[(size_t)rr * Ndim + col] = make_float2(v0, v1);
                } else if (mode == 4) {
                    Ch[(size_t)rr * (Ndim >> 1) + (col >> 1)] =
                        __float2half(v0 / (1.f + expf(-v1)));
                } else { // mode 3
                    if (col < 1024) {
                        *(float2*)&C[(size_t)(col >> 9) * ((size_t)ROWS * ID_)
                                     + (size_t)rr * ID_ + (col & 511)] =
                            make_float2(v0, v1);
                    } else {
                        *(__half2*)&Ch[(size_t)rr * ID_ + (col & 511)] =
                            __floats2half2_rn(v0, v1);
                    }
                }
            }
        }
    }
}

// ======================================================================
// proj_favor: fused fph = favor( dn * qk @ proj^T ), 3-term split A.
// ======================================================================
#define PFP 72
__global__ __launch_bounds__(256, 2)
void proj_favor(const float* __restrict__ qk, const uint32_t* __restrict__ Bf,
                __half* __restrict__ fph, float dn, float ratio)
{
    __shared__ __align__(16) __half Ah[64][PFP];
    __shared__ __align__(16) __half Al[64][PFP];
    __shared__ float ds[64];
    __shared__ float hm[8][16];

    const int tid = threadIdx.x;
    const int lane = tid & 31;
    const int warp = tid >> 5;
    const int rg = warp >> 1;
    const int hn = warp & 1;
    const int wm = rg * 16;
    const size_t bm = (size_t)blockIdx.x * 64;
    const int isQ = (bm < (size_t)RH);

    #pragma unroll
    for (int u = 0; u < 4; u++) {
        int f = tid + u * 256;
        int row = f >> 4;
        int c4 = (f & 15) * 4;
        float4 v = *(const float4*)&qk[(bm + row) * DH_ + c4];
        uint2 hi, lo;
        splitf4h(v, hi, lo);
        *(uint2*)&Ah[row][c4] = hi;
        *(uint2*)&Al[row][c4] = lo;
    }
    __syncthreads();

    {
        int row = tid >> 2;
        int seg = (tid & 3) * 16;
        float s = 0.f;
        #pragma unroll
        for (int j = 0; j < 16; j++) {
            float q = __half2float(Ah[row][seg + j]) + __half2float(Al[row][seg + j]);
            s += q * q;
        }
        s += __shfl_xor_sync(0xffffffffu, s, 1);
        s += __shfl_xor_sync(0xffffffffu, s, 2);
        if ((tid & 3) == 0) ds[row] = s * 0.0625f;
    }

    float acc[17][4];
    #pragma unroll
    for (int nt = 0; nt < 17; nt++)
        #pragma unroll
        for (int j = 0; j < 4; j++) acc[nt][j] = 0.f;

    const uint32_t sH = (uint32_t)__cvta_generic_to_shared(&Ah[0][0]);
    const uint32_t sL = (uint32_t)__cvta_generic_to_shared(&Al[0][0]);
    const int a_m = lane & 15;
    const int a_k = (lane >> 4) << 3;
    const int n8base = hn * 17;

    #pragma unroll
    for (int k16 = 0; k16 < 4; k16++) {
        uint32_t ah[4], al[4];
        uint32_t off = (uint32_t)((wm + a_m) * PFP + k16*16 + a_k) * 2;
        ldm4(ah, sH + off);
        ldm4(al, sL + off);
        #pragma unroll
        for (int nt = 0; nt < 17; nt++) {
            const uint32_t* fb = Bf + ((size_t)(n8base + nt) * 4 + k16) * 128 + lane * 2;
            uint2 hv = *(const uint2*)fb;
            uint2 lv = *(const uint2*)(fb + 64);
            uint32_t bh[2] = {hv.x, hv.y};
            uint32_t bl[2] = {lv.x, lv.y};
            mma_f16(acc[nt], ah, bh);
            mma_f16(acc[nt], ah, bl);
            mma_f16(acc[nt], al, bh);
        }
    }

    const int gr = lane >> 2;
    const int gc = (lane & 3) * 2;
    const int cbase = hn * 136 + gc;

    if (isQ) {
        float mx0 = -1e30f, mx1 = -1e30f;
        #pragma unroll
        for (int nt = 0; nt < 17; nt++) {
            int c0 = cbase + nt*8;
            if (c0 < MM)     { mx0 = fmaxf(mx0, acc[nt][0]); mx1 = fmaxf(mx1, acc[nt][2]); }
            if (c0 + 1 < MM) { mx0 = fmaxf(mx0, acc[nt][1]); mx1 = fmaxf(mx1, acc[nt][3]); }
        }
        mx0 = fmaxf(mx0, __shfl_xor_sync(0xffffffffu, mx0, 1));
        mx0 = fmaxf(mx0, __shfl_xor_sync(0xffffffffu, mx0, 2));
        mx1 = fmaxf(mx1, __shfl_xor_sync(0xffffffffu, mx1, 1));
        mx1 = fmaxf(mx1, __shfl_xor_sync(0xffffffffu, mx1, 2));
        if ((lane & 3) == 0) { hm[warp][gr] = mx0; hm[warp][gr + 8] = mx1; }
    }
    __syncthreads();

    float fmx0 = 0.f, fmx1 = 0.f;
    if (isQ) {
        fmx0 = fmaxf(hm[warp][gr],     hm[warp ^ 1][gr])     * dn;
        fmx1 = fmaxf(hm[warp][gr + 8], hm[warp ^ 1][gr + 8]) * dn;
    }
    const float d0 = ds[wm + gr];
    const float d1 = ds[wm + gr + 8];
    __half* o0 = fph + (bm + wm + gr) * MMP;
    __half* o1 = o0 + (size_t)8 * MMP;

    #pragma unroll
    for (int nt = 0; nt < 17; nt++) {
        #pragma unroll
        for (int j = 0; j < 2; j++) {
            int col = cbase + nt*8 + j;
            float va = acc[nt][j]     * dn;
            float vb = acc[nt][2 + j] * dn;
            float ra, rb;
            if (col < MM) {
                if (isQ) {
                    ra = ratio * (expf(va - d0 - fmx0) + 1e-4f);
                    rb = ratio * (expf(vb - d1 - fmx1) + 1e-4f);
                } else {
                    ra = ratio * expf(va - d0 + 1e-4f);
                    rb = ratio * expf(vb - d1 + 1e-4f);
                }
            } else { ra = 0.f; rb = 0.f; }
            o0[col] = __float2half(ra);
            o1[col] = __float2half(rb);
        }
    }
}

// ======================================================================
// ctx_mma: kp^T @ v over 512-seq chunk (NCHK=4) -> fp32 partials
// ======================================================================
#define KPITCH 280
#define VPITCH 72
__global__ __launch_bounds__(256, 1)
void ctx_mma(const __half* __restrict__ kp, const __half* __restrict__ v,
             float* __restrict__ part)
{
    __shared__ __align__(16) __half Kp[32][KPITCH];
    __shared__ __align__(16) __half Vs[32][VPITCH];

    const int tid = threadIdx.x;
    const int lane = tid & 31;
    const int warp = tid >> 5;
    const int kc = blockIdx.x;      // 0..NCHK-1
    const int bh = blockIdx.y;
    const int b = bh >> 3, h = bh & 7;

    const int nmt = (warp == 0) ? 3 : 2;
    int mts[3];
    mts[0] = 2*warp; mts[1] = 2*warp + 1; mts[2] = 16;

    float acc[3][8][4];
    #pragma unroll
    for (int t = 0; t < 3; t++)
        #pragma unroll
        for (int n = 0; n < 8; n++)
            #pragma unroll
            for (int j = 0; j < 4; j++) acc[t][n][j] = 0.f;

    const __half* kpb = kp + ((size_t)(b * SEQ) * H_ + h) * MMP;
    const __half* vb  = v  + ((size_t)(b * SEQ) * H_ + h) * DH_;

    const uint32_t sK = (uint32_t)__cvta_generic_to_shared(&Kp[0][0]);
    const uint32_t sV = (uint32_t)__cvta_generic_to_shared(&Vs[0][0]);
    const int r7 = lane & 7;
    const int NIT = SEQ / NCHK / 32;   // 16

    for (int it = 0; it < NIT; it++) {
        const int n0 = kc * (SEQ / NCHK) + it * 32;
        for (int f = tid; f < 32*34; f += 256) {
            int nn = f / 34, c8 = (f % 34) * 8;
            *(uint4*)&Kp[nn][c8] =
                *(const uint4*)&kpb[(size_t)(n0 + nn) * (H_*MMP) + c8];
        }
        {
            int nn = tid >> 3, c8 = (tid & 7) * 8;
            *(uint4*)&Vs[nn][c8] =
                *(const uint4*)&vb[(size_t)(n0 + nn) * (H_*DH_) + c8];
        }
        __syncthreads();

        #pragma unroll
        for (int ks = 0; ks < 2; ks++) {
            uint32_t bhf[8][2];
            #pragma unroll
            for (int g = 0; g < 4; g++) {
                int row = ks*16 + ((lane >> 3) & 1) * 8 + r7;
                int col = g*16 + (lane >> 4) * 8;
                uint32_t r[4];
                ldm4t(r, sV + (uint32_t)(row * VPITCH + col) * 2);
                bhf[2*g][0] = r[0]; bhf[2*g][1] = r[1];
                bhf[2*g+1][0] = r[2]; bhf[2*g+1][1] = r[3];
            }
            #pragma unroll
            for (int t = 0; t < 3; t++) {
                if (t < nmt) {
                    int m0 = mts[t] * 16;
                    int row = ks*16 + ((lane >> 4) & 1) * 8 + r7;
                    int col = m0 + ((lane >> 3) & 1) * 8;
                    uint32_t ah[4];
                    ldm4t(ah, sK + (uint32_t)(row * KPITCH + col) * 2);
                    #pragma unroll
                    for (int nt = 0; nt < 8; nt++)
                        mma_f16(acc[t][nt], ah, bhf[nt]);
                }
            }
        }
        __syncthreads();
    }

    const int gr = lane >> 2;
    const int gc = (lane & 3) * 2;
    float* pb = part + ((size_t)(bh * NCHK + kc)) * 272 * 64;
    #pragma unroll
    for (int t = 0; t < 3; t++) {
        if (t < nmt) {
            int m0 = mts[t] * 16;
            #pragma unroll
            for (int nt = 0; nt < 8; nt++) {
                int e = nt*8 + gc;
                pb[(size_t)(m0 + gr) * 64 + e]     = acc[t][nt][0];
                pb[(size_t)(m0 + gr) * 64 + e + 1] = acc[t][nt][1];
                pb[(size_t)(m0 + gr + 8) * 64 + e]     = acc[t][nt][2];
                pb[(size_t)(m0 + gr + 8) * 64 + e + 1] = acc[t][nt][3];
            }
        }
    }
}

// ---------------- reduceT: sum partials -> ctxT fp16 [bh][e][m] (+ks row) ---
__global__ void reduceT(const float* __restrict__ part, const float* __restrict__ ks,
                        __half* __restrict__ ctxT)
{
    const int bh = blockIdx.y;
    const int m0 = blockIdx.x * 64;
    const int mw = (272 - m0 < 64) ? (272 - m0) : 64;
    __shared__ float sm[64][65];
    const int t = threadIdx.x;
    const int e  = t & 63;
    const int mr = t >> 6;
    for (int mm = mr; mm < mw; mm += 4) {
        float s = 0.f;
        #pragma unroll
        for (int kc = 0; kc < NCHK; kc++)
            s += part[(((size_t)(bh*NCHK + kc)) * 272 + m0 + mm) * 64 + e];
        sm[mm][e] = s;
    }
    __syncthreads();
    const int m  = t & 63;
    const int er = t >> 6;
    for (int ee = er; ee < 80; ee += 4) {
        if (m0 + m < 288) {
            float val = 0.f;
            if (m < mw) {
                if (ee < 64)       val = sm[m][ee];
                else if (ee == 64) val = ks[(size_t)bh * MMP + m0 + m];
            }
            ctxT[((size_t)bh * 80 + ee) * 288 + m0 + m] = __float2half(val);
        }
    }
}

// ======================================================================
// attn_mma: qp(fp16) @ ctxT^T(fp16); col 64 = dsum; out fp16 att
// ======================================================================
#define APITCH 24
__global__ __launch_bounds__(256, 2)
void attn_mma(const __half* __restrict__ qp, const __half* __restrict__ ctxT,
              __half* __restrict__ out)
{
    __shared__ __align__(16) __half As[128][APITCH];
    __shared__ __align__(16) __half Bs[80][APITCH];

    const int tid = threadIdx.x;
    const int lane = tid & 31;
    const int warp = tid >> 5;
    const int bm = blockIdx.x * 128;
    const int bh = blockIdx.y;
    const int b = bh >> 3, h = bh & 7;
    const int wm = warp * 16;

    const __half* qpb = qp + ((size_t)(b * SEQ) * H_ + h) * MMP;
    const __half* cb  = ctxT + (size_t)bh * 80 * 288;

    float acc[9][4];
    #pragma unroll
    for (int n = 0; n < 9; n++)
        #pragma unroll
        for (int j = 0; j < 4; j++) acc[n][j] = 0.f;

    const uint32_t sA = (uint32_t)__cvta_generic_to_shared(&As[0][0]);
    const uint32_t sB = (uint32_t)__cvta_generic_to_shared(&Bs[0][0]);
    const int a_m = lane & 15;
    const int a_k = (lane >> 4) << 3;
    const int b_n = (lane & 7) | ((lane & 16) >> 1);
    const int b_k = lane & 8;

    for (int k16 = 0; k16 < 17; k16++) {
        const int k0 = k16 * 16;
        {
            int row = tid >> 1, c8 = (tid & 1) * 8;
            *(uint4*)&As[row][c8] =
                *(const uint4*)&qpb[(size_t)(bm + row) * (H_*MMP) + k0 + c8];
        }
        if (tid < 160) {
            int row = tid >> 1, c8 = (tid & 1) * 8;
            *(uint4*)&Bs[row][c8] =
                *(const uint4*)&cb[(size_t)row * 288 + k0 + c8];
        }
        __syncthreads();

        uint32_t bhf[10][2];
        #pragma unroll
        for (int p = 0; p < 5; p++) {
            uint32_t r[4];
            ldm4(r, sB + (uint32_t)((p*16 + b_n) * APITCH + b_k) * 2);
            bhf[2*p][0] = r[0]; bhf[2*p][1] = r[1];
            bhf[2*p+1][0] = r[2]; bhf[2*p+1][1] = r[3];
        }
        {
            uint32_t ah[4];
            ldm4(ah, sA + (uint32_t)((wm + a_m) * APITCH + a_k) * 2);
            #pragma unroll
            for (int nt = 0; nt < 9; nt++)
                mma_f16(acc[nt], ah, bhf[nt]);
        }
        __syncthreads();
    }

    const int gr = lane >> 2;
    const int gc = (lane & 3) * 2;
    float d0 = __shfl_sync(0xffffffffu, acc[8][0], gr * 4);
    float d1 = __shfl_sync(0xffffffffu, acc[8][2], gr * 4);
    const float dinv0 = 1.f / (d0 + 1e-8f);
    const float dinv1 = 1.f / (d1 + 1e-8f);

    const size_t row0 = ((size_t)(b * SEQ + bm + wm + gr) * H_ + h) * DH_;
    const size_t row1 = row0 + (size_t)8 * H_ * DH_;
    #pragma unroll
    for (int nt = 0; nt < 8; nt++) {
        int e = nt*8 + gc;
        *(__half2*)&out[row0 + e] = __floats2half2_rn(acc[nt][0]*dinv0, acc[nt][1]*dinv0);
        *(__half2*)&out[row1 + e] = __floats2half2_rn(acc[nt][2]*dinv1, acc[nt][3]*dinv1);
    }
}

// ---------------- LayerNorm (fp16 out) -----------------
__global__ void ln_kernel(const float* __restrict__ x, const float* __restrict__ g,
                          const float* __restrict__ b, __half* __restrict__ out)
{
    const int r = blockIdx.x;
    const int t = threadIdx.x;
    const float4 v = ((const float4*)(x + (size_t)r * D_))[t];
    float s  = v.x + v.y + v.z + v.w;
    float ss = v.x*v.x + v.y*v.y + v.z*v.z + v.w*v.w;
    __shared__ float rs[128], rss[128];
    rs[t] = s; rss[t] = ss;
    __syncthreads();
    for (int o = 64; o > 0; o >>= 1) {
        if (t < o) { rs[t] += rs[t+o]; rss[t] += rss[t+o]; }
        __syncthreads();
    }
    const float mu   = rs[0] * (1.f / D_);
    const float var  = rss[0] * (1.f / D_) - mu * mu;
    const float rstd = rsqrtf(var + 1e-5f);
    const float4 gg = ((const float4*)g)[t];
    const float4 bb = ((const float4*)b)[t];
    __half2 p0 = __floats2half2_rn((v.x - mu) * rstd * gg.x + bb.x,
                                   (v.y - mu) * rstd * gg.y + bb.y);
    __half2 p1 = __floats2half2_rn((v.z - mu) * rstd * gg.z + bb.z,
                                   (v.w - mu) * rstd * gg.w + bb.w);
    uint2 st;
    st.x = *reinterpret_cast<uint32_t*>(&p0);
    st.y = *reinterpret_cast<uint32_t*>(&p1);
    *(uint2*)&out[(size_t)r * D_ + t * 4] = st;
}

// ---------------- ksum two-stage (fp16 in) ---------------
__global__ void ksum1(const __half* __restrict__ kp, float* __restrict__ part)
{
    const int bh = blockIdx.y;
    const int chunk = blockIdx.x;
    const int m = threadIdx.x;
    if (m >= MMP) return;
    const int b = bh >> 3, h = bh & 7;
    const __half* base = kp + ((size_t)(b * SEQ + chunk * 256) * H_ + h) * MMP + m;
    const size_t stride = (size_t)H_ * MMP;
    float s0 = 0.f, s1 = 0.f, s2 = 0.f, s3 = 0.f;
    for (int n = 0; n < 256; n += 4) {
        s0 += __half2float(base[(n+0) * stride]);
        s1 += __half2float(base[(n+1) * stride]);
        s2 += __half2float(base[(n+2) * stride]);
        s3 += __half2float(base[(n+3) * stride]);
    }
    part[((size_t)bh * 8 + chunk) * MMP + m] = (s0 + s1) + (s2 + s3);
}
__global__ void ksum2(const float* __restrict__ part, float* __restrict__ ks)
{
    const int bh = blockIdx.x;
    const int m = threadIdx.x;
    if (m >= MMP) return;
    float s = 0.f;
    #pragma unroll
    for (int c = 0; c < 8; c++) s += part[((size_t)bh * 8 + c) * MMP + m];
    ks[(size_t)bh * MMP + m] = s;
}

// ---------------- depthwise conv + SiLU (fp16 in/out) ---------------
#define DC_CH 128
#define DC_TN 32
__global__ __launch_bounds__(256)
void dwconv2(const __half* __restrict__ gin, const float* __restrict__ w,
             const float* __restrict__ bias, __half* __restrict__ out)
{
    __shared__ float sin_[DC_TN + 30][DC_CH];
    __shared__ float sw[DC_CH * KW];

    const int c0 = blockIdx.x * DC_CH;
    const int n0 = blockIdx.y * DC_TN;
    const int b  = blockIdx.z;
    const int t  = threadIdx.x;

    for (int i = t; i < DC_CH * KW; i += 256)
        sw[i] = w[(size_t)c0 * KW + i];
    #pragma unroll
    for (int u = 0; u < (DC_TN + 30) * DC_CH / 256; u++) {
        int f = t + u * 256;
        int rowi = f >> 7;
        int ch = f & 127;
        int n = n0 + rowi - 15;
        sin_[rowi][ch] = ((unsigned)n < SEQ)
            ? __half2float(gin[((size_t)(b * SEQ + n) << 10) + c0 + ch]) : 0.f;
    }
    __syncthreads();

    const int ch = t & 127;
    const int nl0 = (t >> 7) * 16;

    float wr[KW];
    #pragma unroll
    for (int k = 0; k < KW; k++) wr[k] = sw[ch * KW + k];
    const float bb = bias[c0 + ch];

    #pragma unroll
    for (int i = 0; i < 16; i++) {
        float acc = bb;
        #pragma unroll
        for (int k = 0; k < KW; k++)
            acc += sin_[nl0 + i + k][ch] * wr[k];
        float o = acc / (1.f + expf(-acc));
        out[((size_t)(b * SEQ + n0 + nl0 + i) << 10) + c0 + ch] = __float2half(o);
    }
}

// ---------------- host orchestration ----------------------------------------
static inline void run_gemm_h(const __half* A, const uint32_t* Bf, float* C,
                              __half* Ch, const float* bias, const float* extra,
                              int Mdim, int Ndim, int Kdim, int mode)
{
    dim3 grid(Ndim / 128, Mdim / 128);
    gemm_h<<<grid, 256>>>(A, Bf, C, Ch, bias, extra, Mdim, Ndim, Kdim, mode);
}
static inline void run_wfrag(const float* W, uint32_t* out, int Ndim, int Kdim,
                             int NT8, int pair)
{
    size_t total = (size_t)NT8 * (Kdim >> 4) * 128;
    wfrag<<<(unsigned)((total + 255) / 256), 256>>>(W, out, Ndim, Kdim, NT8, pair);
}

extern "C" void kernel_launch(void* const* d_in, const int* in_sizes, int n_in,
                              void* d_out, int out_size)
{
    const float* x    = (const float*)d_in[0];
    const float* ln1g = (const float*)d_in[1];
    const float* ln1b = (const float*)d_in[2];
    const float* wq   = (const float*)d_in[3];
    const float* bq   = (const float*)d_in[4];
    const float* wk   = (const float*)d_in[5];
    const float* bk   = (const float*)d_in[6];
    const float* wv   = (const float*)d_in[7];
    const float* bv   = (const float*)d_in[8];
    const float* wo   = (const float*)d_in[9];
    const float* bo   = (const float*)d_in[10];
    const float* proj = (const float*)d_in[11];
    const float* ln2g = (const float*)d_in[12];
    const float* ln2b = (const float*)d_in[13];
    const float* pw1w = (const float*)d_in[14];
    const float* pw1b = (const float*)d_in[15];
    const float* dww  = (const float*)d_in[16];
    const float* dwb  = (const float*)d_in[17];
    const float* pw2w = (const float*)d_in[18];
    const float* pw2b = (const float*)d_in[19];
    float* xo = (float*)d_out;

    __half *h, *vh, *fph, *ctxT, *att, *glu, *dw;
    float *qk, *ks, *part, *cpart, *qkvb, *pw1bi;
    uint32_t* wf;
    cudaGetSymbolAddress((void**)&h,     g_h);
    cudaGetSymbolAddress((void**)&qk,    g_qk);
    cudaGetSymbolAddress((void**)&vh,    g_vh);
    cudaGetSymbolAddress((void**)&fph,   g_fph);
    cudaGetSymbolAddress((void**)&ks,    g_ks);
    cudaGetSymbolAddress((void**)&part,  g_part);
    cudaGetSymbolAddress((void**)&cpart, g_cpart);
    cudaGetSymbolAddress((void**)&ctxT,  g_ctxT);
    cudaGetSymbolAddress((void**)&att,   g_att);
    cudaGetSymbolAddress((void**)&glu,   g_glu);
    cudaGetSymbolAddress((void**)&dw,    g_dw);
    cudaGetSymbolAddress((void**)&qkvb,  g_qkvbias);
    cudaGetSymbolAddress((void**)&pw1bi, g_pw1bi);
    cudaGetSymbolAddress((void**)&wf,    g_wfrag);

    __half* qph = fph;
    __half* kph = fph + (size_t)RH * MMP;

    const size_t OFF_WQ = 0;
    const size_t OFF_WO = OFF_WQ + 3*FR_QKV;
    const size_t OFF_P1 = OFF_WO + FR_QKV;
    const size_t OFF_P2 = OFF_P1 + FR_PW1;
    const size_t OFF_PR = OFF_P2 + FR_PW2;

    for (int l = 0; l < LNUM; l++) {
        uint32_t* lw = wf + (size_t)l * FR_LSTR;
        run_wfrag(wq   + (size_t)l*ID_*D_,    lw + OFF_WQ,            512, 512, 64, 0);
        run_wfrag(wk   + (size_t)l*ID_*D_,    lw + OFF_WQ + FR_QKV,   512, 512, 64, 0);
        run_wfrag(wv   + (size_t)l*ID_*D_,    lw + OFF_WQ + 2*FR_QKV, 512, 512, 64, 0);
        run_wfrag(wo   + (size_t)l*ID_*D_,    lw + OFF_WO, 512, 512, 64, 0);
        run_wfrag(pw1w + (size_t)l*2048*D_,   lw + OFF_P1, 2048, 512, 256, 1);
        run_wfrag(pw2w + (size_t)l*D_*INNER_, lw + OFF_P2, 512, 1024, 64, 0);
        run_wfrag(proj + (size_t)l*MM*DH_,    lw + OFF_PR, 266, 64, 48, 0);
    }
    biascat<<<(LNUM*512 + 255)/256, 256>>>(bq, bk, bv, qkvb);
    bias2<<<(LNUM*2048 + 255)/256, 256>>>(pw1b, pw1bi);

    cudaMemcpyAsync(xo, x, (size_t)ROWS * D_ * sizeof(float),
                    cudaMemcpyDeviceToDevice);

    const float dn    = (float)(1.0 / sqrt(sqrt(64.0)));
    const float ratio = (float)(1.0 / sqrt(266.0));

    for (int l = 0; l < LNUM; l++) {
        uint32_t* lw = wf + (size_t)l * FR_LSTR;

        ln_kernel<<<ROWS, 128>>>(xo, ln1g + (size_t)l*D_, ln1b + (size_t)l*D_, h);
        run_gemm_h(h, lw + OFF_WQ, qk, vh, qkvb + (size_t)l*1536, nullptr,
                   ROWS, 1536, D_, 3);
        proj_favor<<<(2*RH)/64, 256>>>(qk, lw + OFF_PR, fph, dn, ratio);
        {
            dim3 k1(8, NBH);
            ksum1<<<k1, 288>>>(kph, part);
            ksum2<<<NBH, 288>>>(part, ks);
            dim3 cg(NCHK, NBH);
            ctx_mma<<<cg, 256>>>(kph, vh, cpart);
            dim3 rg(5, NBH);
            reduceT<<<rg, 256>>>(cpart, ks, ctxT);
            dim3 ag(SEQ / 128, NBH);
            attn_mma<<<ag, 256>>>(qph, ctxT, att);
        }
        run_gemm_h(att, lw + OFF_WO, xo, nullptr, bo + (size_t)l*D_, xo,
                   ROWS, D_, ID_, 0);
        ln_kernel<<<ROWS, 128>>>(xo, ln2g + (size_t)l*D_, ln2b + (size_t)l*D_, h);
        run_gemm_h(h, lw + OFF_P1, nullptr, glu, pw1bi + (size_t)l*2048, nullptr,
                   ROWS, 2048, D_, 4);
        {
            dim3 dg(INNER_/DC_CH, SEQ/DC_TN, B_);
            dwconv2<<<dg, 256>>>(glu, dww + (size_t)l*INNER_*KW, dwb + (size_t)l*INNER_, dw);
        }
        run_gemm_h(dw, lw + OFF_P2, xo, nullptr, pw2b + (size_t)l*D_, xo,
                   ROWS, D_, INNER_, 0);
    }
}

// round 15
// speedup vs baseline: 1.1473x; 1.0172x over previous
#include <cuda_runtime.h>
#include <cuda_fp16.h>
#include <math.h>
#include <stdint.h>

// ---------------- problem constants ----------------
#define B_     4
#define SEQ    2048
#define D_     512
#define H_     8
#define DH_    64
#define ID_    512
#define MM     266
#define MMP    272
#define INNER_ 1024
#define KW     31
#define LNUM   6
#define ROWS   (B_*SEQ)
#define RH     (ROWS*H_)
#define NBH    (B_*H_)
#define NCHK   4

// ---------------- device scratch ----------------
__device__ __half g_h    [ROWS*D_];
__device__ float  g_qk   [2*(size_t)ROWS*ID_];
__device__ __half g_vh   [ROWS*ID_];
__device__ __half g_fph  [2*(size_t)RH*MMP];
__device__ float  g_ks   [NBH*MMP];
__device__ float  g_part [NBH*8*MMP];
__device__ float  g_cpart[(size_t)NBH*NCHK*MMP*DH_];
__device__ __half g_ctxT [(size_t)NBH*80*288];
__device__ __half g_att  [ROWS*ID_];
__device__ __half g_glu  [ROWS*INNER_];
__device__ __half g_dw   [ROWS*INNER_];
__device__ float  g_qkvbias[LNUM*1536];
__device__ float  g_pw1bi [LNUM*2048];

#define FR_QKV  (64*32*128)
#define FR_PW1  (256*32*128)
#define FR_PW2  (64*64*128)
#define FR_PROJ (48*4*128)
#define FR_LSTR (4*FR_QKV + FR_PW1 + FR_PW2 + FR_PROJ)
__device__ uint32_t g_wfrag[(size_t)LNUM * FR_LSTR];

// ---------------- helpers ----------------
__device__ __forceinline__ uint32_t pk2h(__half a, __half b) {
    __half2 t = __halves2half2(a, b);
    return *reinterpret_cast<uint32_t*>(&t);
}
__device__ __forceinline__ void splitf4h(float4 v, uint2& hi, uint2& lo) {
    __half h0 = __float2half_rn(v.x), h1 = __float2half_rn(v.y),
           h2 = __float2half_rn(v.z), h3 = __float2half_rn(v.w);
    hi.x = pk2h(h0, h1); hi.y = pk2h(h2, h3);
    lo.x = pk2h(__float2half_rn(v.x - __half2float(h0)),
                __float2half_rn(v.y - __half2float(h1)));
    lo.y = pk2h(__float2half_rn(v.z - __half2float(h2)),
                __float2half_rn(v.w - __half2float(h3)));
}
__device__ __forceinline__ void ldm4(uint32_t* r, uint32_t addr) {
    asm volatile("ldmatrix.sync.aligned.m8n8.x4.shared.b16 {%0,%1,%2,%3}, [%4];\n"
                 : "=r"(r[0]), "=r"(r[1]), "=r"(r[2]), "=r"(r[3]) : "r"(addr));
}
__device__ __forceinline__ void ldm4t(uint32_t* r, uint32_t addr) {
    asm volatile("ldmatrix.sync.aligned.m8n8.x4.trans.shared.b16 {%0,%1,%2,%3}, [%4];\n"
                 : "=r"(r[0]), "=r"(r[1]), "=r"(r[2]), "=r"(r[3]) : "r"(addr));
}
__device__ __forceinline__ void mma_f16(float* c, const uint32_t* a, const uint32_t* b) {
    asm volatile(
        "mma.sync.aligned.m16n8k16.row.col.f32.f16.f16.f32 "
        "{%0,%1,%2,%3}, {%4,%5,%6,%7}, {%8,%9}, {%0,%1,%2,%3};\n"
        : "+f"(c[0]), "+f"(c[1]), "+f"(c[2]), "+f"(c[3])
        : "r"(a[0]), "r"(a[1]), "r"(a[2]), "r"(a[3]), "r"(b[0]), "r"(b[1]));
}
__device__ __forceinline__ void cpa16(uint32_t dst, const void* src) {
    asm volatile("cp.async.cg.shared.global [%0], [%1], 16;\n"
                 :: "r"(dst), "l"(src) : "memory");
}

// ---------------- weight -> fragment converter (fp16 hi/lo) -----------------
__global__ void wfrag(const float* __restrict__ W, uint32_t* __restrict__ out,
                      int Ndim, int Kdim, int NT8, int pair)
{
    const int KT16 = Kdim >> 4;
    size_t idx = (size_t)blockIdx.x * 256 + threadIdx.x;
    size_t total = (size_t)NT8 * KT16 * 128;
    if (idx >= total) return;
    int r     = (int)(idx & 1);
    int l     = (int)((idx >> 1) & 31);
    int plane = (int)((idx >> 6) & 1);
    size_t ft = idx >> 7;
    int k16 = (int)(ft % KT16);
    int n8  = (int)(ft / KT16);
    int n = n8 * 8 + (l >> 2);
    int k = k16 * 16 + (l & 3) * 2 + r * 8;
    float v0 = 0.f, v1 = 0.f;
    if (n < Ndim) {
        int srcn = pair ? ((n & 1) ? 1024 + (n >> 1) : (n >> 1)) : n;
        float2 vv = *(const float2*)&W[(size_t)srcn * Kdim + k];
        v0 = vv.x; v1 = vv.y;
    }
    __half h0 = __float2half_rn(v0), h1 = __float2half_rn(v1);
    uint32_t val = (plane == 0)
        ? pk2h(h0, h1)
        : pk2h(__float2half_rn(v0 - __half2float(h0)),
               __float2half_rn(v1 - __half2float(h1)));
    out[idx] = val;
}

__global__ void biascat(const float* __restrict__ bq, const float* __restrict__ bk,
                        const float* __restrict__ bv, float* __restrict__ out)
{
    int i = blockIdx.x * 256 + threadIdx.x;
    if (i < LNUM * 512) {
        int l = i >> 9, c = i & 511;
        out[l*1536 + c]        = bq[i];
        out[l*1536 + 512 + c]  = bk[i];
        out[l*1536 + 1024 + c] = bv[i];
    }
}
__global__ void bias2(const float* __restrict__ pw1b, float* __restrict__ out)
{
    int i = blockIdx.x * 256 + threadIdx.x;
    if (i < LNUM * 2048) {
        int l = i >> 11, c = i & 2047;
        int src = (c & 1) ? 1024 + (c >> 1) : (c >> 1);
        out[l*2048 + c] = pw1b[(size_t)l*2048 + src];
    }
}

#define ASTR 40
#define A_STAGE (128*ASTR)               // halfs per A stage
#define B_STAGE (32*128)                 // uint32 per B stage (32 blocks x 128)
#define GH_SMEM (2*A_STAGE*2 + 2*B_STAGE*4)   // 20480 + 32768 = 53248 bytes

// ======================================================================
// gemm_h: A and B both staged via cp.async double buffer.
// modes: 0 C fp32 (+extra resid), 3 qkv split, 4 pair-gate
// ======================================================================
__global__ __launch_bounds__(256, 2)
void gemm_h(const __half* __restrict__ A, const uint32_t* __restrict__ Bf,
            float* __restrict__ C, __half* __restrict__ Ch,
            const float* __restrict__ bias, const float* __restrict__ extra,
            int Mdim, int Ndim, int Kdim, int mode)
{
    extern __shared__ __align__(16) char dynsm[];
    __half*   Asm = (__half*)dynsm;                       // [2][128][ASTR]
    uint32_t* Bsm = (uint32_t*)(dynsm + 2*A_STAGE*2);     // [2][32][128]

    const int tid  = threadIdx.x;
    const int lane = tid & 31;
    const int warp = tid >> 5;
    const int wm = (warp & 1) * 64;
    const int wn = (warp >> 1) * 32;
    const int bm = blockIdx.y * 128;
    const int bn = blockIdx.x * 128;
    const int KT16 = Kdim >> 4;
    const int n8c = bn >> 3;              // CTA n8 base

    float acc[4][4][4];
    #pragma unroll
    for (int i = 0; i < 4; i++)
        #pragma unroll
        for (int j = 0; j < 4; j++)
            #pragma unroll
            for (int t = 0; t < 4; t++) acc[i][j][t] = 0.f;

    const int a_m = lane & 15;
    const int a_k = (lane >> 4) << 3;
    const uint32_t sA = (uint32_t)__cvta_generic_to_shared(Asm);
    const uint32_t sB = (uint32_t)__cvta_generic_to_shared(Bsm);

    const int r0 = tid >> 2;
    const int c8 = (tid & 3) * 8;
    // B copy mapping: 1024 16B-chunks per stage, 4 per thread
    const int KT = Kdim >> 5;

    auto issue = [&](int kt, int st) {
        #pragma unroll
        for (int u = 0; u < 2; u++) {
            int row = r0 + u * 64;
            cpa16(sA + (uint32_t)st * (A_STAGE*2) + (uint32_t)(row * ASTR + c8) * 2,
                  &A[(size_t)(bm + row) * Kdim + kt*32 + c8]);
        }
        #pragma unroll
        for (int u = 0; u < 4; u++) {
            int ch = tid + u * 256;       // 0..1023
            int blk = ch >> 5;            // 0..31
            int off = (ch & 31) * 4;      // uint32 offset in block
            int n8i = blk >> 1;
            int ks  = blk & 1;
            cpa16(sB + (uint32_t)st * (B_STAGE*4) + (uint32_t)(blk * 128 + off) * 4,
                  Bf + ((size_t)(n8c + n8i) * KT16 + (kt*2 + ks)) * 128 + off);
        }
        asm volatile("cp.async.commit_group;\n" ::: "memory");
    };

    issue(0, 0);
    if (KT > 1) issue(1, 1);

    for (int kt = 0; kt < KT; kt++) {
        const int st = kt & 1;
        if (kt + 1 < KT) asm volatile("cp.async.wait_group 1;\n" ::: "memory");
        else             asm volatile("cp.async.wait_group 0;\n" ::: "memory");
        __syncthreads();

        const uint32_t* bst = Bsm + (size_t)st * B_STAGE;
        uint32_t bhf[2][4][2];
        #pragma unroll
        for (int ks = 0; ks < 2; ks++)
            #pragma unroll
            for (int nt = 0; nt < 4; nt++) {
                const uint32_t* p = bst + (((wn >> 3) + nt) * 2 + ks) * 128 + lane * 2;
                uint2 hv = *(const uint2*)p;
                bhf[ks][nt][0] = hv.x; bhf[ks][nt][1] = hv.y;
            }
        const uint32_t stBase = sA + (uint32_t)st * (A_STAGE*2);
        #pragma unroll
        for (int ks = 0; ks < 2; ks++) {
            #pragma unroll
            for (int mt = 0; mt < 4; mt++) {
                uint32_t ah[4];
                uint32_t addr = stBase + (uint32_t)(((wm + mt*16 + a_m) * ASTR) + ks*16 + a_k) * 2;
                ldm4(ah, addr);
                #pragma unroll
                for (int nt = 0; nt < 4; nt++)
                    mma_f16(acc[mt][nt], ah, bhf[ks][nt]);
            }
        }
        __syncthreads();
        if (kt + 2 < KT) issue(kt + 2, st);
    }

    const int gr = lane >> 2;
    const int gc = (lane & 3) * 2;
    #pragma unroll
    for (int mt = 0; mt < 4; mt++) {
        #pragma unroll
        for (int nt = 0; nt < 4; nt++) {
            const float* cp = acc[mt][nt];
            int row = bm + wm + mt*16 + gr;
            int col = bn + wn + nt*8 + gc;
            #pragma unroll
            for (int half = 0; half < 2; half++) {
                int rr = row + half*8;
                float v0 = cp[half*2 + 0];
                float v1 = cp[half*2 + 1];
                if (bias) { v0 += bias[col]; v1 += bias[col + 1]; }
                if (mode == 0) {
                    if (extra) {
                        v0 += extra[(size_t)rr * Ndim + col];
                        v1 += extra[(size_t)rr * Ndim + col + 1];
                    }
                    *(float2*)&C[(size_t)rr * Ndim + col] = make_float2(v0, v1);
                } else if (mode == 4) {
                    Ch[(size_t)rr * (Ndim >> 1) + (col >> 1)] =
                        __float2half(v0 / (1.f + expf(-v1)));
                } else { // mode 3
                    if (col < 1024) {
                        *(float2*)&C[(size_t)(col >> 9) * ((size_t)ROWS * ID_)
                                     + (size_t)rr * ID_ + (col & 511)] =
                            make_float2(v0, v1);
                    } else {
                        *(__half2*)&Ch[(size_t)rr * ID_ + (col & 511)] =
                            __floats2half2_rn(v0, v1);
                    }
                }
            }
        }
    }
}

// ======================================================================
// proj_favor: fused fph = favor( dn * qk @ proj^T ), 3-term split A.
// ======================================================================
#define PFP 72
__global__ __launch_bounds__(256, 2)
void proj_favor(const float* __restrict__ qk, const uint32_t* __restrict__ Bf,
                __half* __restrict__ fph, float dn, float ratio)
{
    __shared__ __align__(16) __half Ah[64][PFP];
    __shared__ __align__(16) __half Al[64][PFP];
    __shared__ float ds[64];
    __shared__ float hm[8][16];

    const int tid = threadIdx.x;
    const int lane = tid & 31;
    const int warp = tid >> 5;
    const int rg = warp >> 1;
    const int hn = warp & 1;
    const int wm = rg * 16;
    const size_t bm = (size_t)blockIdx.x * 64;
    const int isQ = (bm < (size_t)RH);

    #pragma unroll
    for (int u = 0; u < 4; u++) {
        int f = tid + u * 256;
        int row = f >> 4;
        int c4 = (f & 15) * 4;
        float4 v = *(const float4*)&qk[(bm + row) * DH_ + c4];
        uint2 hi, lo;
        splitf4h(v, hi, lo);
        *(uint2*)&Ah[row][c4] = hi;
        *(uint2*)&Al[row][c4] = lo;
    }
    __syncthreads();

    {
        int row = tid >> 2;
        int seg = (tid & 3) * 16;
        float s = 0.f;
        #pragma unroll
        for (int j = 0; j < 16; j++) {
            float q = __half2float(Ah[row][seg + j]) + __half2float(Al[row][seg + j]);
            s += q * q;
        }
        s += __shfl_xor_sync(0xffffffffu, s, 1);
        s += __shfl_xor_sync(0xffffffffu, s, 2);
        if ((tid & 3) == 0) ds[row] = s * 0.0625f;
    }

    float acc[17][4];
    #pragma unroll
    for (int nt = 0; nt < 17; nt++)
        #pragma unroll
        for (int j = 0; j < 4; j++) acc[nt][j] = 0.f;

    const uint32_t sH = (uint32_t)__cvta_generic_to_shared(&Ah[0][0]);
    const uint32_t sL = (uint32_t)__cvta_generic_to_shared(&Al[0][0]);
    const int a_m = lane & 15;
    const int a_k = (lane >> 4) << 3;
    const int n8base = hn * 17;

    #pragma unroll
    for (int k16 = 0; k16 < 4; k16++) {
        uint32_t ah[4], al[4];
        uint32_t off = (uint32_t)((wm + a_m) * PFP + k16*16 + a_k) * 2;
        ldm4(ah, sH + off);
        ldm4(al, sL + off);
        #pragma unroll
        for (int nt = 0; nt < 17; nt++) {
            const uint32_t* fb = Bf + ((size_t)(n8base + nt) * 4 + k16) * 128 + lane * 2;
            uint2 hv = *(const uint2*)fb;
            uint2 lv = *(const uint2*)(fb + 64);
            uint32_t bh[2] = {hv.x, hv.y};
            uint32_t bl[2] = {lv.x, lv.y};
            mma_f16(acc[nt], ah, bh);
            mma_f16(acc[nt], ah, bl);
            mma_f16(acc[nt], al, bh);
        }
    }

    const int gr = lane >> 2;
    const int gc = (lane & 3) * 2;
    const int cbase = hn * 136 + gc;

    if (isQ) {
        float mx0 = -1e30f, mx1 = -1e30f;
        #pragma unroll
        for (int nt = 0; nt < 17; nt++) {
            int c0 = cbase + nt*8;
            if (c0 < MM)     { mx0 = fmaxf(mx0, acc[nt][0]); mx1 = fmaxf(mx1, acc[nt][2]); }
            if (c0 + 1 < MM) { mx0 = fmaxf(mx0, acc[nt][1]); mx1 = fmaxf(mx1, acc[nt][3]); }
        }
        mx0 = fmaxf(mx0, __shfl_xor_sync(0xffffffffu, mx0, 1));
        mx0 = fmaxf(mx0, __shfl_xor_sync(0xffffffffu, mx0, 2));
        mx1 = fmaxf(mx1, __shfl_xor_sync(0xffffffffu, mx1, 1));
        mx1 = fmaxf(mx1, __shfl_xor_sync(0xffffffffu, mx1, 2));
        if ((lane & 3) == 0) { hm[warp][gr] = mx0; hm[warp][gr + 8] = mx1; }
    }
    __syncthreads();

    float fmx0 = 0.f, fmx1 = 0.f;
    if (isQ) {
        fmx0 = fmaxf(hm[warp][gr],     hm[warp ^ 1][gr])     * dn;
        fmx1 = fmaxf(hm[warp][gr + 8], hm[warp ^ 1][gr + 8]) * dn;
    }
    const float d0 = ds[wm + gr];
    const float d1 = ds[wm + gr + 8];
    __half* o0 = fph + (bm + wm + gr) * MMP;
    __half* o1 = o0 + (size_t)8 * MMP;

    #pragma unroll
    for (int nt = 0; nt < 17; nt++) {
        #pragma unroll
        for (int j = 0; j < 2; j++) {
            int col = cbase + nt*8 + j;
            float va = acc[nt][j]     * dn;
            float vb = acc[nt][2 + j] * dn;
            float ra, rb;
            if (col < MM) {
                if (isQ) {
                    ra = ratio * (expf(va - d0 - fmx0) + 1e-4f);
                    rb = ratio * (expf(vb - d1 - fmx1) + 1e-4f);
                } else {
                    ra = ratio * expf(va - d0 + 1e-4f);
                    rb = ratio * expf(vb - d1 + 1e-4f);
                }
            } else { ra = 0.f; rb = 0.f; }
            o0[col] = __float2half(ra);
            o1[col] = __float2half(rb);
        }
    }
}

// ======================================================================
// ctx_mma: kp^T @ v over 512-seq chunk (NCHK=4) -> fp32 partials
// ======================================================================
#define KPITCH 280
#define VPITCH 72
__global__ __launch_bounds__(256, 1)
void ctx_mma(const __half* __restrict__ kp, const __half* __restrict__ v,
             float* __restrict__ part)
{
    __shared__ __align__(16) __half Kp[32][KPITCH];
    __shared__ __align__(16) __half Vs[32][VPITCH];

    const int tid = threadIdx.x;
    const int lane = tid & 31;
    const int warp = tid >> 5;
    const int kc = blockIdx.x;
    const int bh = blockIdx.y;
    const int b = bh >> 3, h = bh & 7;

    const int nmt = (warp == 0) ? 3 : 2;
    int mts[3];
    mts[0] = 2*warp; mts[1] = 2*warp + 1; mts[2] = 16;

    float acc[3][8][4];
    #pragma unroll
    for (int t = 0; t < 3; t++)
        #pragma unroll
        for (int n = 0; n < 8; n++)
            #pragma unroll
            for (int j = 0; j < 4; j++) acc[t][n][j] = 0.f;

    const __half* kpb = kp + ((size_t)(b * SEQ) * H_ + h) * MMP;
    const __half* vb  = v  + ((size_t)(b * SEQ) * H_ + h) * DH_;

    const uint32_t sK = (uint32_t)__cvta_generic_to_shared(&Kp[0][0]);
    const uint32_t sV = (uint32_t)__cvta_generic_to_shared(&Vs[0][0]);
    const int r7 = lane & 7;
    const int NIT = SEQ / NCHK / 32;

    for (int it = 0; it < NIT; it++) {
        const int n0 = kc * (SEQ / NCHK) + it * 32;
        for (int f = tid; f < 32*34; f += 256) {
            int nn = f / 34, c8 = (f % 34) * 8;
            *(uint4*)&Kp[nn][c8] =
                *(const uint4*)&kpb[(size_t)(n0 + nn) * (H_*MMP) + c8];
        }
        {
            int nn = tid >> 3, c8 = (tid & 7) * 8;
            *(uint4*)&Vs[nn][c8] =
                *(const uint4*)&vb[(size_t)(n0 + nn) * (H_*DH_) + c8];
        }
        __syncthreads();

        #pragma unroll
        for (int ks = 0; ks < 2; ks++) {
            uint32_t bhf[8][2];
            #pragma unroll
            for (int g = 0; g < 4; g++) {
                int row = ks*16 + ((lane >> 3) & 1) * 8 + r7;
                int col = g*16 + (lane >> 4) * 8;
                uint32_t r[4];
                ldm4t(r, sV + (uint32_t)(row * VPITCH + col) * 2);
                bhf[2*g][0] = r[0]; bhf[2*g][1] = r[1];
                bhf[2*g+1][0] = r[2]; bhf[2*g+1][1] = r[3];
            }
            #pragma unroll
            for (int t = 0; t < 3; t++) {
                if (t < nmt) {
                    int m0 = mts[t] * 16;
                    int row = ks*16 + ((lane >> 4) & 1) * 8 + r7;
                    int col = m0 + ((lane >> 3) & 1) * 8;
                    uint32_t ah[4];
                    ldm4t(ah, sK + (uint32_t)(row * KPITCH + col) * 2);
                    #pragma unroll
                    for (int nt = 0; nt < 8; nt++)
                        mma_f16(acc[t][nt], ah, bhf[nt]);
                }
            }
        }
        __syncthreads();
    }

    const int gr = lane >> 2;
    const int gc = (lane & 3) * 2;
    float* pb = part + ((size_t)(bh * NCHK + kc)) * 272 * 64;
    #pragma unroll
    for (int t = 0; t < 3; t++) {
        if (t < nmt) {
            int m0 = mts[t] * 16;
            #pragma unroll
            for (int nt = 0; nt < 8; nt++) {
                int e = nt*8 + gc;
                pb[(size_t)(m0 + gr) * 64 + e]     = acc[t][nt][0];
                pb[(size_t)(m0 + gr) * 64 + e + 1] = acc[t][nt][1];
                pb[(size_t)(m0 + gr + 8) * 64 + e]     = acc[t][nt][2];
                pb[(size_t)(m0 + gr + 8) * 64 + e + 1] = acc[t][nt][3];
            }
        }
    }
}

// ---------------- reduceT ----------------
__global__ void reduceT(const float* __restrict__ part, const float* __restrict__ ks,
                        __half* __restrict__ ctxT)
{
    const int bh = blockIdx.y;
    const int m0 = blockIdx.x * 64;
    const int mw = (272 - m0 < 64) ? (272 - m0) : 64;
    __shared__ float sm[64][65];
    const int t = threadIdx.x;
    const int e  = t & 63;
    const int mr = t >> 6;
    for (int mm = mr; mm < mw; mm += 4) {
        float s = 0.f;
        #pragma unroll
        for (int kc = 0; kc < NCHK; kc++)
            s += part[(((size_t)(bh*NCHK + kc)) * 272 + m0 + mm) * 64 + e];
        sm[mm][e] = s;
    }
    __syncthreads();
    const int m  = t & 63;
    const int er = t >> 6;
    for (int ee = er; ee < 80; ee += 4) {
        if (m0 + m < 288) {
            float val = 0.f;
            if (m < mw) {
                if (ee < 64)       val = sm[m][ee];
                else if (ee == 64) val = ks[(size_t)bh * MMP + m0 + m];
            }
            ctxT[((size_t)bh * 80 + ee) * 288 + m0 + m] = __float2half(val);
        }
    }
}

// ======================================================================
// attn_mma
// ======================================================================
#define APITCH 24
__global__ __launch_bounds__(256, 2)
void attn_mma(const __half* __restrict__ qp, const __half* __restrict__ ctxT,
              __half* __restrict__ out)
{
    __shared__ __align__(16) __half As[128][APITCH];
    __shared__ __align__(16) __half Bs[80][APITCH];

    const int tid = threadIdx.x;
    const int lane = tid & 31;
    const int warp = tid >> 5;
    const int bm = blockIdx.x * 128;
    const int bh = blockIdx.y;
    const int b = bh >> 3, h = bh & 7;
    const int wm = warp * 16;

    const __half* qpb = qp + ((size_t)(b * SEQ) * H_ + h) * MMP;
    const __half* cb  = ctxT + (size_t)bh * 80 * 288;

    float acc[9][4];
    #pragma unroll
    for (int n = 0; n < 9; n++)
        #pragma unroll
        for (int j = 0; j < 4; j++) acc[n][j] = 0.f;

    const uint32_t sA = (uint32_t)__cvta_generic_to_shared(&As[0][0]);
    const uint32_t sB = (uint32_t)__cvta_generic_to_shared(&Bs[0][0]);
    const int a_m = lane & 15;
    const int a_k = (lane >> 4) << 3;
    const int b_n = (lane & 7) | ((lane & 16) >> 1);
    const int b_k = lane & 8;

    for (int k16 = 0; k16 < 17; k16++) {
        const int k0 = k16 * 16;
        {
            int row = tid >> 1, c8 = (tid & 1) * 8;
            *(uint4*)&As[row][c8] =
                *(const uint4*)&qpb[(size_t)(bm + row) * (H_*MMP) + k0 + c8];
        }
        if (tid < 160) {
            int row = tid >> 1, c8 = (tid & 1) * 8;
            *(uint4*)&Bs[row][c8] =
                *(const uint4*)&cb[(size_t)row * 288 + k0 + c8];
        }
        __syncthreads();

        uint32_t bhf[10][2];
        #pragma unroll
        for (int p = 0; p < 5; p++) {
            uint32_t r[4];
            ldm4(r, sB + (uint32_t)((p*16 + b_n) * APITCH + b_k) * 2);
            bhf[2*p][0] = r[0]; bhf[2*p][1] = r[1];
            bhf[2*p+1][0] = r[2]; bhf[2*p+1][1] = r[3];
        }
        {
            uint32_t ah[4];
            ldm4(ah, sA + (uint32_t)((wm + a_m) * APITCH + a_k) * 2);
            #pragma unroll
            for (int nt = 0; nt < 9; nt++)
                mma_f16(acc[nt], ah, bhf[nt]);
        }
        __syncthreads();
    }

    const int gr = lane >> 2;
    const int gc = (lane & 3) * 2;
    float d0 = __shfl_sync(0xffffffffu, acc[8][0], gr * 4);
    float d1 = __shfl_sync(0xffffffffu, acc[8][2], gr * 4);
    const float dinv0 = 1.f / (d0 + 1e-8f);
    const float dinv1 = 1.f / (d1 + 1e-8f);

    const size_t row0 = ((size_t)(b * SEQ + bm + wm + gr) * H_ + h) * DH_;
    const size_t row1 = row0 + (size_t)8 * H_ * DH_;
    #pragma unroll
    for (int nt = 0; nt < 8; nt++) {
        int e = nt*8 + gc;
        *(__half2*)&out[row0 + e] = __floats2half2_rn(acc[nt][0]*dinv0, acc[nt][1]*dinv0);
        *(__half2*)&out[row1 + e] = __floats2half2_rn(acc[nt][2]*dinv1, acc[nt][3]*dinv1);
    }
}

// ---------------- LayerNorm (fp16 out) -----------------
__global__ void ln_kernel(const float* __restrict__ x, const float* __restrict__ g,
                          const float* __restrict__ b, __half* __restrict__ out)
{
    const int r = blockIdx.x;
    const int t = threadIdx.x;
    const float4 v = ((const float4*)(x + (size_t)r * D_))[t];
    float s  = v.x + v.y + v.z + v.w;
    float ss = v.x*v.x + v.y*v.y + v.z*v.z + v.w*v.w;
    __shared__ float rs[128], rss[128];
    rs[t] = s; rss[t] = ss;
    __syncthreads();
    for (int o = 64; o > 0; o >>= 1) {
        if (t < o) { rs[t] += rs[t+o]; rss[t] += rss[t+o]; }
        __syncthreads();
    }
    const float mu   = rs[0] * (1.f / D_);
    const float var  = rss[0] * (1.f / D_) - mu * mu;
    const float rstd = rsqrtf(var + 1e-5f);
    const float4 gg = ((const float4*)g)[t];
    const float4 bb = ((const float4*)b)[t];
    __half2 p0 = __floats2half2_rn((v.x - mu) * rstd * gg.x + bb.x,
                                   (v.y - mu) * rstd * gg.y + bb.y);
    __half2 p1 = __floats2half2_rn((v.z - mu) * rstd * gg.z + bb.z,
                                   (v.w - mu) * rstd * gg.w + bb.w);
    uint2 st;
    st.x = *reinterpret_cast<uint32_t*>(&p0);
    st.y = *reinterpret_cast<uint32_t*>(&p1);
    *(uint2*)&out[(size_t)r * D_ + t * 4] = st;
}

// ---------------- ksum two-stage ---------------
__global__ void ksum1(const __half* __restrict__ kp, float* __restrict__ part)
{
    const int bh = blockIdx.y;
    const int chunk = blockIdx.x;
    const int m = threadIdx.x;
    if (m >= MMP) return;
    const int b = bh >> 3, h = bh & 7;
    const __half* base = kp + ((size_t)(b * SEQ + chunk * 256) * H_ + h) * MMP + m;
    const size_t stride = (size_t)H_ * MMP;
    float s0 = 0.f, s1 = 0.f, s2 = 0.f, s3 = 0.f;
    for (int n = 0; n < 256; n += 4) {
        s0 += __half2float(base[(n+0) * stride]);
        s1 += __half2float(base[(n+1) * stride]);
        s2 += __half2float(base[(n+2) * stride]);
        s3 += __half2float(base[(n+3) * stride]);
    }
    part[((size_t)bh * 8 + chunk) * MMP + m] = (s0 + s1) + (s2 + s3);
}
__global__ void ksum2(const float* __restrict__ part, float* __restrict__ ks)
{
    const int bh = blockIdx.x;
    const int m = threadIdx.x;
    if (m >= MMP) return;
    float s = 0.f;
    #pragma unroll
    for (int c = 0; c < 8; c++) s += part[((size_t)bh * 8 + c) * MMP + m];
    ks[(size_t)bh * MMP + m] = s;
}

// ---------------- depthwise conv + SiLU ---------------
#define DC_CH 128
#define DC_TN 32
__global__ __launch_bounds__(256)
void dwconv2(const __half* __restrict__ gin, const float* __restrict__ w,
             const float* __restrict__ bias, __half* __restrict__ out)
{
    __shared__ float sin_[DC_TN + 30][DC_CH];
    __shared__ float sw[DC_CH * KW];

    const int c0 = blockIdx.x * DC_CH;
    const int n0 = blockIdx.y * DC_TN;
    const int b  = blockIdx.z;
    const int t  = threadIdx.x;

    for (int i = t; i < DC_CH * KW; i += 256)
        sw[i] = w[(size_t)c0 * KW + i];
    #pragma unroll
    for (int u = 0; u < (DC_TN + 30) * DC_CH / 256; u++) {
        int f = t + u * 256;
        int rowi = f >> 7;
        int ch = f & 127;
        int n = n0 + rowi - 15;
        sin_[rowi][ch] = ((unsigned)n < SEQ)
            ? __half2float(gin[((size_t)(b * SEQ + n) << 10) + c0 + ch]) : 0.f;
    }
    __syncthreads();

    const int ch = t & 127;
    const int nl0 = (t >> 7) * 16;

    float wr[KW];
    #pragma unroll
    for (int k = 0; k < KW; k++) wr[k] = sw[ch * KW + k];
    const float bb = bias[c0 + ch];

    #pragma unroll
    for (int i = 0; i < 16; i++) {
        float acc = bb;
        #pragma unroll
        for (int k = 0; k < KW; k++)
            acc += sin_[nl0 + i + k][ch] * wr[k];
        float o = acc / (1.f + expf(-acc));
        out[((size_t)(b * SEQ + n0 + nl0 + i) << 10) + c0 + ch] = __float2half(o);
    }
}

// ---------------- host orchestration ----------------------------------------
static inline void run_gemm_h(const __half* A, const uint32_t* Bf, float* C,
                              __half* Ch, const float* bias, const float* extra,
                              int Mdim, int Ndim, int Kdim, int mode)
{
    dim3 grid(Ndim / 128, Mdim / 128);
    gemm_h<<<grid, 256, GH_SMEM>>>(A, Bf, C, Ch, bias, extra, Mdim, Ndim, Kdim, mode);
}
static inline void run_wfrag(const float* W, uint32_t* out, int Ndim, int Kdim,
                             int NT8, int pair)
{
    size_t total = (size_t)NT8 * (Kdim >> 4) * 128;
    wfrag<<<(unsigned)((total + 255) / 256), 256>>>(W, out, Ndim, Kdim, NT8, pair);
}

extern "C" void kernel_launch(void* const* d_in, const int* in_sizes, int n_in,
                              void* d_out, int out_size)
{
    const float* x    = (const float*)d_in[0];
    const float* ln1g = (const float*)d_in[1];
    const float* ln1b = (const float*)d_in[2];
    const float* wq   = (const float*)d_in[3];
    const float* bq   = (const float*)d_in[4];
    const float* wk   = (const float*)d_in[5];
    const float* bk   = (const float*)d_in[6];
    const float* wv   = (const float*)d_in[7];
    const float* bv   = (const float*)d_in[8];
    const float* wo   = (const float*)d_in[9];
    const float* bo   = (const float*)d_in[10];
    const float* proj = (const float*)d_in[11];
    const float* ln2g = (const float*)d_in[12];
    const float* ln2b = (const float*)d_in[13];
    const float* pw1w = (const float*)d_in[14];
    const float* pw1b = (const float*)d_in[15];
    const float* dww  = (const float*)d_in[16];
    const float* dwb  = (const float*)d_in[17];
    const float* pw2w = (const float*)d_in[18];
    const float* pw2b = (const float*)d_in[19];
    float* xo = (float*)d_out;

    cudaFuncSetAttribute(gemm_h, cudaFuncAttributeMaxDynamicSharedMemorySize, GH_SMEM);

    __half *h, *vh, *fph, *ctxT, *att, *glu, *dw;
    float *qk, *ks, *part, *cpart, *qkvb, *pw1bi;
    uint32_t* wf;
    cudaGetSymbolAddress((void**)&h,     g_h);
    cudaGetSymbolAddress((void**)&qk,    g_qk);
    cudaGetSymbolAddress((void**)&vh,    g_vh);
    cudaGetSymbolAddress((void**)&fph,   g_fph);
    cudaGetSymbolAddress((void**)&ks,    g_ks);
    cudaGetSymbolAddress((void**)&part,  g_part);
    cudaGetSymbolAddress((void**)&cpart, g_cpart);
    cudaGetSymbolAddress((void**)&ctxT,  g_ctxT);
    cudaGetSymbolAddress((void**)&att,   g_att);
    cudaGetSymbolAddress((void**)&glu,   g_glu);
    cudaGetSymbolAddress((void**)&dw,    g_dw);
    cudaGetSymbolAddress((void**)&qkvb,  g_qkvbias);
    cudaGetSymbolAddress((void**)&pw1bi, g_pw1bi);
    cudaGetSymbolAddress((void**)&wf,    g_wfrag);

    __half* qph = fph;
    __half* kph = fph + (size_t)RH * MMP;

    const size_t OFF_WQ = 0;
    const size_t OFF_WO = OFF_WQ + 3*FR_QKV;
    const size_t OFF_P1 = OFF_WO + FR_QKV;
    const size_t OFF_P2 = OFF_P1 + FR_PW1;
    const size_t OFF_PR = OFF_P2 + FR_PW2;

    for (int l = 0; l < LNUM; l++) {
        uint32_t* lw = wf + (size_t)l * FR_LSTR;
        run_wfrag(wq   + (size_t)l*ID_*D_,    lw + OFF_WQ,            512, 512, 64, 0);
        run_wfrag(wk   + (size_t)l*ID_*D_,    lw + OFF_WQ + FR_QKV,   512, 512, 64, 0);
        run_wfrag(wv   + (size_t)l*ID_*D_,    lw + OFF_WQ + 2*FR_QKV, 512, 512, 64, 0);
        run_wfrag(wo   + (size_t)l*ID_*D_,    lw + OFF_WO, 512, 512, 64, 0);
        run_wfrag(pw1w + (size_t)l*2048*D_,   lw + OFF_P1, 2048, 512, 256, 1);
        run_wfrag(pw2w + (size_t)l*D_*INNER_, lw + OFF_P2, 512, 1024, 64, 0);
        run_wfrag(proj + (size_t)l*MM*DH_,    lw + OFF_PR, 266, 64, 48, 0);
    }
    biascat<<<(LNUM*512 + 255)/256, 256>>>(bq, bk, bv, qkvb);
    bias2<<<(LNUM*2048 + 255)/256, 256>>>(pw1b, pw1bi);

    cudaMemcpyAsync(xo, x, (size_t)ROWS * D_ * sizeof(float),
                    cudaMemcpyDeviceToDevice);

    const float dn    = (float)(1.0 / sqrt(sqrt(64.0)));
    const float ratio = (float)(1.0 / sqrt(266.0));

    for (int l = 0; l < LNUM; l++) {
        uint32_t* lw = wf + (size_t)l * FR_LSTR;

        ln_kernel<<<ROWS, 128>>>(xo, ln1g + (size_t)l*D_, ln1b + (size_t)l*D_, h);
        run_gemm_h(h, lw + OFF_WQ, qk, vh, qkvb + (size_t)l*1536, nullptr,
                   ROWS, 1536, D_, 3);
        proj_favor<<<(2*RH)/64, 256>>>(qk, lw + OFF_PR, fph, dn, ratio);
        {
            dim3 k1(8, NBH);
            ksum1<<<k1, 288>>>(kph, part);
            ksum2<<<NBH, 288>>>(part, ks);
            dim3 cg(NCHK, NBH);
            ctx_mma<<<cg, 256>>>(kph, vh, cpart);
            dim3 rg(5, NBH);
            reduceT<<<rg, 256>>>(cpart, ks, ctxT);
            dim3 ag(SEQ / 128, NBH);
            attn_mma<<<ag, 256>>>(qph, ctxT, att);
        }
        run_gemm_h(att, lw + OFF_WO, xo, nullptr, bo + (size_t)l*D_, xo,
                   ROWS, D_, ID_, 0);
        ln_kernel<<<ROWS, 128>>>(xo, ln2g + (size_t)l*D_, ln2b + (size_t)l*D_, h);
        run_gemm_h(h, lw + OFF_P1, nullptr, glu, pw1bi + (size_t)l*2048, nullptr,
                   ROWS, 2048, D_, 4);
        {
            dim3 dg(INNER_/DC_CH, SEQ/DC_TN, B_);
            dwconv2<<<dg, 256>>>(glu, dww + (size_t)l*INNER_*KW, dwb + (size_t)l*INNER_, dw);
        }
        run_gemm_h(dw, lw + OFF_P2, xo, nullptr, pw2b + (size_t)l*D_, xo,
                   ROWS, D_, INNER_, 0);
    }
}

// round 16
// speedup vs baseline: 1.1698x; 1.0196x over previous
#include <cuda_runtime.h>
#include <cuda_fp16.h>
#include <math.h>
#include <stdint.h>

// ---------------- problem constants ----------------
#define B_     4
#define SEQ    2048
#define D_     512
#define H_     8
#define DH_    64
#define ID_    512
#define MM     266
#define MMP    272
#define INNER_ 1024
#define KW     31
#define LNUM   6
#define ROWS   (B_*SEQ)
#define RH     (ROWS*H_)
#define NBH    (B_*H_)
#define NCHK   4

// ---------------- device scratch ----------------
__device__ __half g_h    [ROWS*D_];
__device__ float  g_qk   [2*(size_t)ROWS*ID_];
__device__ __half g_vh   [ROWS*ID_];
__device__ __half g_fph  [2*(size_t)RH*MMP];
__device__ float  g_part [NBH*8*MMP];
__device__ float  g_cpart[(size_t)NBH*NCHK*MMP*DH_];
__device__ __half g_ctxT [(size_t)NBH*80*288];
__device__ __half g_att  [ROWS*ID_];
__device__ __half g_glu  [ROWS*INNER_];
__device__ __half g_dw   [ROWS*INNER_];
__device__ float  g_qkvbias[LNUM*1536];
__device__ float  g_pw1bi [LNUM*2048];

#define FR_QKV  (64*32*128)
#define FR_PW1  (256*32*128)
#define FR_PW2  (64*64*128)
#define FR_PROJ (48*4*128)
#define FR_LSTR (4*FR_QKV + FR_PW1 + FR_PW2 + FR_PROJ)
__device__ uint32_t g_wfrag[(size_t)LNUM * FR_LSTR];

// ---------------- helpers ----------------
__device__ __forceinline__ uint32_t pk2h(__half a, __half b) {
    __half2 t = __halves2half2(a, b);
    return *reinterpret_cast<uint32_t*>(&t);
}
__device__ __forceinline__ void splitf4h(float4 v, uint2& hi, uint2& lo) {
    __half h0 = __float2half_rn(v.x), h1 = __float2half_rn(v.y),
           h2 = __float2half_rn(v.z), h3 = __float2half_rn(v.w);
    hi.x = pk2h(h0, h1); hi.y = pk2h(h2, h3);
    lo.x = pk2h(__float2half_rn(v.x - __half2float(h0)),
                __float2half_rn(v.y - __half2float(h1)));
    lo.y = pk2h(__float2half_rn(v.z - __half2float(h2)),
                __float2half_rn(v.w - __half2float(h3)));
}
__device__ __forceinline__ void ldm4(uint32_t* r, uint32_t addr) {
    asm volatile("ldmatrix.sync.aligned.m8n8.x4.shared.b16 {%0,%1,%2,%3}, [%4];\n"
                 : "=r"(r[0]), "=r"(r[1]), "=r"(r[2]), "=r"(r[3]) : "r"(addr));
}
__device__ __forceinline__ void ldm4t(uint32_t* r, uint32_t addr) {
    asm volatile("ldmatrix.sync.aligned.m8n8.x4.trans.shared.b16 {%0,%1,%2,%3}, [%4];\n"
                 : "=r"(r[0]), "=r"(r[1]), "=r"(r[2]), "=r"(r[3]) : "r"(addr));
}
__device__ __forceinline__ void mma_f16(float* c, const uint32_t* a, const uint32_t* b) {
    asm volatile(
        "mma.sync.aligned.m16n8k16.row.col.f32.f16.f16.f32 "
        "{%0,%1,%2,%3}, {%4,%5,%6,%7}, {%8,%9}, {%0,%1,%2,%3};\n"
        : "+f"(c[0]), "+f"(c[1]), "+f"(c[2]), "+f"(c[3])
        : "r"(a[0]), "r"(a[1]), "r"(a[2]), "r"(a[3]), "r"(b[0]), "r"(b[1]));
}
__device__ __forceinline__ void cpa16(uint32_t dst, const void* src) {
    asm volatile("cp.async.cg.shared.global [%0], [%1], 16;\n"
                 :: "r"(dst), "l"(src) : "memory");
}

// ---------------- weight -> fragment converter (fp16 hi/lo) -----------------
__global__ void wfrag(const float* __restrict__ W, uint32_t* __restrict__ out,
                      int Ndim, int Kdim, int NT8, int pair)
{
    const int KT16 = Kdim >> 4;
    size_t idx = (size_t)blockIdx.x * 256 + threadIdx.x;
    size_t total = (size_t)NT8 * KT16 * 128;
    if (idx >= total) return;
    int r     = (int)(idx & 1);
    int l     = (int)((idx >> 1) & 31);
    int plane = (int)((idx >> 6) & 1);
    size_t ft = idx >> 7;
    int k16 = (int)(ft % KT16);
    int n8  = (int)(ft / KT16);
    int n = n8 * 8 + (l >> 2);
    int k = k16 * 16 + (l & 3) * 2 + r * 8;
    float v0 = 0.f, v1 = 0.f;
    if (n < Ndim) {
        int srcn = pair ? ((n & 1) ? 1024 + (n >> 1) : (n >> 1)) : n;
        float2 vv = *(const float2*)&W[(size_t)srcn * Kdim + k];
        v0 = vv.x; v1 = vv.y;
    }
    __half h0 = __float2half_rn(v0), h1 = __float2half_rn(v1);
    uint32_t val = (plane == 0)
        ? pk2h(h0, h1)
        : pk2h(__float2half_rn(v0 - __half2float(h0)),
               __float2half_rn(v1 - __half2float(h1)));
    out[idx] = val;
}

__global__ void biascat(const float* __restrict__ bq, const float* __restrict__ bk,
                        const float* __restrict__ bv, float* __restrict__ out)
{
    int i = blockIdx.x * 256 + threadIdx.x;
    if (i < LNUM * 512) {
        int l = i >> 9, c = i & 511;
        out[l*1536 + c]        = bq[i];
        out[l*1536 + 512 + c]  = bk[i];
        out[l*1536 + 1024 + c] = bv[i];
    }
}
__global__ void bias2(const float* __restrict__ pw1b, float* __restrict__ out)
{
    int i = blockIdx.x * 256 + threadIdx.x;
    if (i < LNUM * 2048) {
        int l = i >> 11, c = i & 2047;
        int src = (c & 1) ? 1024 + (c >> 1) : (c >> 1);
        out[l*2048 + c] = pw1b[(size_t)l*2048 + src];
    }
}

#define ASTR 40
#define A_STAGE (128*ASTR)
#define B_STAGE (32*128)
#define GH_SMEM (2*A_STAGE*2 + 2*B_STAGE*4)

// ======================================================================
// gemm_h: A and B both staged via cp.async double buffer.
// modes: 0 C fp32 (+extra resid), 3 qkv split, 4 pair-gate
// ======================================================================
__global__ __launch_bounds__(256, 2)
void gemm_h(const __half* __restrict__ A, const uint32_t* __restrict__ Bf,
            float* __restrict__ C, __half* __restrict__ Ch,
            const float* __restrict__ bias, const float* __restrict__ extra,
            int Mdim, int Ndim, int Kdim, int mode)
{
    extern __shared__ __align__(16) char dynsm[];
    __half*   Asm = (__half*)dynsm;
    uint32_t* Bsm = (uint32_t*)(dynsm + 2*A_STAGE*2);

    const int tid  = threadIdx.x;
    const int lane = tid & 31;
    const int warp = tid >> 5;
    const int wm = (warp & 1) * 64;
    const int wn = (warp >> 1) * 32;
    const int bm = blockIdx.y * 128;
    const int bn = blockIdx.x * 128;
    const int KT16 = Kdim >> 4;
    const int n8c = bn >> 3;

    float acc[4][4][4];
    #pragma unroll
    for (int i = 0; i < 4; i++)
        #pragma unroll
        for (int j = 0; j < 4; j++)
            #pragma unroll
            for (int t = 0; t < 4; t++) acc[i][j][t] = 0.f;

    const int a_m = lane & 15;
    const int a_k = (lane >> 4) << 3;
    const uint32_t sA = (uint32_t)__cvta_generic_to_shared(Asm);
    const uint32_t sB = (uint32_t)__cvta_generic_to_shared(Bsm);

    const int r0 = tid >> 2;
    const int c8 = (tid & 3) * 8;
    const int KT = Kdim >> 5;

    auto issue = [&](int kt, int st) {
        #pragma unroll
        for (int u = 0; u < 2; u++) {
            int row = r0 + u * 64;
            cpa16(sA + (uint32_t)st * (A_STAGE*2) + (uint32_t)(row * ASTR + c8) * 2,
                  &A[(size_t)(bm + row) * Kdim + kt*32 + c8]);
        }
        #pragma unroll
        for (int u = 0; u < 4; u++) {
            int ch = tid + u * 256;
            int blk = ch >> 5;
            int off = (ch & 31) * 4;
            int n8i = blk >> 1;
            int ks  = blk & 1;
            cpa16(sB + (uint32_t)st * (B_STAGE*4) + (uint32_t)(blk * 128 + off) * 4,
                  Bf + ((size_t)(n8c + n8i) * KT16 + (kt*2 + ks)) * 128 + off);
        }
        asm volatile("cp.async.commit_group;\n" ::: "memory");
    };

    issue(0, 0);
    if (KT > 1) issue(1, 1);

    for (int kt = 0; kt < KT; kt++) {
        const int st = kt & 1;
        if (kt + 1 < KT) asm volatile("cp.async.wait_group 1;\n" ::: "memory");
        else             asm volatile("cp.async.wait_group 0;\n" ::: "memory");
        __syncthreads();

        const uint32_t* bst = Bsm + (size_t)st * B_STAGE;
        uint32_t bhf[2][4][2];
        #pragma unroll
        for (int ks = 0; ks < 2; ks++)
            #pragma unroll
            for (int nt = 0; nt < 4; nt++) {
                const uint32_t* p = bst + (((wn >> 3) + nt) * 2 + ks) * 128 + lane * 2;
                uint2 hv = *(const uint2*)p;
                bhf[ks][nt][0] = hv.x; bhf[ks][nt][1] = hv.y;
            }
        const uint32_t stBase = sA + (uint32_t)st * (A_STAGE*2);
        #pragma unroll
        for (int ks = 0; ks < 2; ks++) {
            #pragma unroll
            for (int mt = 0; mt < 4; mt++) {
                uint32_t ah[4];
                uint32_t addr = stBase + (uint32_t)(((wm + mt*16 + a_m) * ASTR) + ks*16 + a_k) * 2;
                ldm4(ah, addr);
                #pragma unroll
                for (int nt = 0; nt < 4; nt++)
                    mma_f16(acc[mt][nt], ah, bhf[ks][nt]);
            }
        }
        __syncthreads();
        if (kt + 2 < KT) issue(kt + 2, st);
    }

    const int gr = lane >> 2;
    const int gc = (lane & 3) * 2;
    #pragma unroll
    for (int mt = 0; mt < 4; mt++) {
        #pragma unroll
        for (int nt = 0; nt < 4; nt++) {
            const float* cp = acc[mt][nt];
            int row = bm + wm + mt*16 + gr;
            int col = bn + wn + nt*8 + gc;
            #pragma unroll
            for (int half = 0; half < 2; half++) {
                int rr = row + half*8;
                float v0 = cp[half*2 + 0];
                float v1 = cp[half*2 + 1];
                if (bias) { v0 += bias[col]; v1 += bias[col + 1]; }
                if (mode == 0) {
                    if (extra) {
                        v0 += extra[(size_t)rr * Ndim + col];
                        v1 += extra[(size_t)rr * Ndim + col + 1];
                    }
                    *(float2*)&C[(size_t)rr * Ndim + col] = make_float2(v0, v1);
                } else if (mode == 4) {
                    Ch[(size_t)rr * (Ndim >> 1) + (col >> 1)] =
                        __float2half(v0 / (1.f + expf(-v1)));
                } else { // mode 3
                    if (col < 1024) {
                        *(float2*)&C[(size_t)(col >> 9) * ((size_t)ROWS * ID_)
                                     + (size_t)rr * ID_ + (col & 511)] =
                            make_float2(v0, v1);
                    } else {
                        *(__half2*)&Ch[(size_t)rr * ID_ + (col & 511)] =
                            __floats2half2_rn(v0, v1);
                    }
                }
            }
        }
    }
}

// ======================================================================
// proj_favor: fused fph = favor( dn * qk @ proj^T ), 3-term split A.
// ======================================================================
#define PFP 72
__global__ __launch_bounds__(256, 2)
void proj_favor(const float* __restrict__ qk, const uint32_t* __restrict__ Bf,
                __half* __restrict__ fph, float dn, float ratio)
{
    __shared__ __align__(16) __half Ah[64][PFP];
    __shared__ __align__(16) __half Al[64][PFP];
    __shared__ float ds[64];
    __shared__ float hm[8][16];

    const int tid = threadIdx.x;
    const int lane = tid & 31;
    const int warp = tid >> 5;
    const int rg = warp >> 1;
    const int hn = warp & 1;
    const int wm = rg * 16;
    const size_t bm = (size_t)blockIdx.x * 64;
    const int isQ = (bm < (size_t)RH);

    #pragma unroll
    for (int u = 0; u < 4; u++) {
        int f = tid + u * 256;
        int row = f >> 4;
        int c4 = (f & 15) * 4;
        float4 v = *(const float4*)&qk[(bm + row) * DH_ + c4];
        uint2 hi, lo;
        splitf4h(v, hi, lo);
        *(uint2*)&Ah[row][c4] = hi;
        *(uint2*)&Al[row][c4] = lo;
    }
    __syncthreads();

    {
        int row = tid >> 2;
        int seg = (tid & 3) * 16;
        float s = 0.f;
        #pragma unroll
        for (int j = 0; j < 16; j++) {
            float q = __half2float(Ah[row][seg + j]) + __half2float(Al[row][seg + j]);
            s += q * q;
        }
        s += __shfl_xor_sync(0xffffffffu, s, 1);
        s += __shfl_xor_sync(0xffffffffu, s, 2);
        if ((tid & 3) == 0) ds[row] = s * 0.0625f;
    }

    float acc[17][4];
    #pragma unroll
    for (int nt = 0; nt < 17; nt++)
        #pragma unroll
        for (int j = 0; j < 4; j++) acc[nt][j] = 0.f;

    const uint32_t sH = (uint32_t)__cvta_generic_to_shared(&Ah[0][0]);
    const uint32_t sL = (uint32_t)__cvta_generic_to_shared(&Al[0][0]);
    const int a_m = lane & 15;
    const int a_k = (lane >> 4) << 3;
    const int n8base = hn * 17;

    #pragma unroll
    for (int k16 = 0; k16 < 4; k16++) {
        uint32_t ah[4], al[4];
        uint32_t off = (uint32_t)((wm + a_m) * PFP + k16*16 + a_k) * 2;
        ldm4(ah, sH + off);
        ldm4(al, sL + off);
        #pragma unroll
        for (int nt = 0; nt < 17; nt++) {
            const uint32_t* fb = Bf + ((size_t)(n8base + nt) * 4 + k16) * 128 + lane * 2;
            uint2 hv = *(const uint2*)fb;
            uint2 lv = *(const uint2*)(fb + 64);
            uint32_t bh[2] = {hv.x, hv.y};
            uint32_t bl[2] = {lv.x, lv.y};
            mma_f16(acc[nt], ah, bh);
            mma_f16(acc[nt], ah, bl);
            mma_f16(acc[nt], al, bh);
        }
    }

    const int gr = lane >> 2;
    const int gc = (lane & 3) * 2;
    const int cbase = hn * 136 + gc;

    if (isQ) {
        float mx0 = -1e30f, mx1 = -1e30f;
        #pragma unroll
        for (int nt = 0; nt < 17; nt++) {
            int c0 = cbase + nt*8;
            if (c0 < MM)     { mx0 = fmaxf(mx0, acc[nt][0]); mx1 = fmaxf(mx1, acc[nt][2]); }
            if (c0 + 1 < MM) { mx0 = fmaxf(mx0, acc[nt][1]); mx1 = fmaxf(mx1, acc[nt][3]); }
        }
        mx0 = fmaxf(mx0, __shfl_xor_sync(0xffffffffu, mx0, 1));
        mx0 = fmaxf(mx0, __shfl_xor_sync(0xffffffffu, mx0, 2));
        mx1 = fmaxf(mx1, __shfl_xor_sync(0xffffffffu, mx1, 1));
        mx1 = fmaxf(mx1, __shfl_xor_sync(0xffffffffu, mx1, 2));
        if ((lane & 3) == 0) { hm[warp][gr] = mx0; hm[warp][gr + 8] = mx1; }
    }
    __syncthreads();

    float fmx0 = 0.f, fmx1 = 0.f;
    if (isQ) {
        fmx0 = fmaxf(hm[warp][gr],     hm[warp ^ 1][gr])     * dn;
        fmx1 = fmaxf(hm[warp][gr + 8], hm[warp ^ 1][gr + 8]) * dn;
    }
    const float d0 = ds[wm + gr];
    const float d1 = ds[wm + gr + 8];
    __half* o0 = fph + (bm + wm + gr) * MMP;
    __half* o1 = o0 + (size_t)8 * MMP;

    #pragma unroll
    for (int nt = 0; nt < 17; nt++) {
        #pragma unroll
        for (int j = 0; j < 2; j++) {
            int col = cbase + nt*8 + j;
            float va = acc[nt][j]     * dn;
            float vb = acc[nt][2 + j] * dn;
            float ra, rb;
            if (col < MM) {
                if (isQ) {
                    ra = ratio * (expf(va - d0 - fmx0) + 1e-4f);
                    rb = ratio * (expf(vb - d1 - fmx1) + 1e-4f);
                } else {
                    ra = ratio * expf(va - d0 + 1e-4f);
                    rb = ratio * expf(vb - d1 + 1e-4f);
                }
            } else { ra = 0.f; rb = 0.f; }
            o0[col] = __float2half(ra);
            o1[col] = __float2half(rb);
        }
    }
}

// ======================================================================
// ctx_mma: kp^T @ v over 512-seq chunk (NCHK=4) -> fp32 partials
// ======================================================================
#define KPITCH 280
#define VPITCH 72
__global__ __launch_bounds__(256, 1)
void ctx_mma(const __half* __restrict__ kp, const __half* __restrict__ v,
             float* __restrict__ part)
{
    __shared__ __align__(16) __half Kp[32][KPITCH];
    __shared__ __align__(16) __half Vs[32][VPITCH];

    const int tid = threadIdx.x;
    const int lane = tid & 31;
    const int warp = tid >> 5;
    const int kc = blockIdx.x;
    const int bh = blockIdx.y;
    const int b = bh >> 3, h = bh & 7;

    const int nmt = (warp == 0) ? 3 : 2;
    int mts[3];
    mts[0] = 2*warp; mts[1] = 2*warp + 1; mts[2] = 16;

    float acc[3][8][4];
    #pragma unroll
    for (int t = 0; t < 3; t++)
        #pragma unroll
        for (int n = 0; n < 8; n++)
            #pragma unroll
            for (int j = 0; j < 4; j++) acc[t][n][j] = 0.f;

    const __half* kpb = kp + ((size_t)(b * SEQ) * H_ + h) * MMP;
    const __half* vb  = v  + ((size_t)(b * SEQ) * H_ + h) * DH_;

    const uint32_t sK = (uint32_t)__cvta_generic_to_shared(&Kp[0][0]);
    const uint32_t sV = (uint32_t)__cvta_generic_to_shared(&Vs[0][0]);
    const int r7 = lane & 7;
    const int NIT = SEQ / NCHK / 32;

    for (int it = 0; it < NIT; it++) {
        const int n0 = kc * (SEQ / NCHK) + it * 32;
        for (int f = tid; f < 32*34; f += 256) {
            int nn = f / 34, c8 = (f % 34) * 8;
            *(uint4*)&Kp[nn][c8] =
                *(const uint4*)&kpb[(size_t)(n0 + nn) * (H_*MMP) + c8];
        }
        {
            int nn = tid >> 3, c8 = (tid & 7) * 8;
            *(uint4*)&Vs[nn][c8] =
                *(const uint4*)&vb[(size_t)(n0 + nn) * (H_*DH_) + c8];
        }
        __syncthreads();

        #pragma unroll
        for (int ks = 0; ks < 2; ks++) {
            uint32_t bhf[8][2];
            #pragma unroll
            for (int g = 0; g < 4; g++) {
                int row = ks*16 + ((lane >> 3) & 1) * 8 + r7;
                int col = g*16 + (lane >> 4) * 8;
                uint32_t r[4];
                ldm4t(r, sV + (uint32_t)(row * VPITCH + col) * 2);
                bhf[2*g][0] = r[0]; bhf[2*g][1] = r[1];
                bhf[2*g+1][0] = r[2]; bhf[2*g+1][1] = r[3];
            }
            #pragma unroll
            for (int t = 0; t < 3; t++) {
                if (t < nmt) {
                    int m0 = mts[t] * 16;
                    int row = ks*16 + ((lane >> 4) & 1) * 8 + r7;
                    int col = m0 + ((lane >> 3) & 1) * 8;
                    uint32_t ah[4];
                    ldm4t(ah, sK + (uint32_t)(row * KPITCH + col) * 2);
                    #pragma unroll
                    for (int nt = 0; nt < 8; nt++)
                        mma_f16(acc[t][nt], ah, bhf[nt]);
                }
            }
        }
        __syncthreads();
    }

    const int gr = lane >> 2;
    const int gc = (lane & 3) * 2;
    float* pb = part + ((size_t)(bh * NCHK + kc)) * 272 * 64;
    #pragma unroll
    for (int t = 0; t < 3; t++) {
        if (t < nmt) {
            int m0 = mts[t] * 16;
            #pragma unroll
            for (int nt = 0; nt < 8; nt++) {
                int e = nt*8 + gc;
                pb[(size_t)(m0 + gr) * 64 + e]     = acc[t][nt][0];
                pb[(size_t)(m0 + gr) * 64 + e + 1] = acc[t][nt][1];
                pb[(size_t)(m0 + gr + 8) * 64 + e]     = acc[t][nt][2];
                pb[(size_t)(m0 + gr + 8) * 64 + e + 1] = acc[t][nt][3];
            }
        }
    }
}

// ---------------- reduceT: sum ctx partials; ks row from ksum1 partials -----
__global__ void reduceT(const float* __restrict__ part, const float* __restrict__ kpart,
                        __half* __restrict__ ctxT)
{
    const int bh = blockIdx.y;
    const int m0 = blockIdx.x * 64;
    const int mw = (272 - m0 < 64) ? (272 - m0) : 64;
    __shared__ float sm[64][65];
    const int t = threadIdx.x;
    const int e  = t & 63;
    const int mr = t >> 6;
    for (int mm = mr; mm < mw; mm += 4) {
        float s = 0.f;
        #pragma unroll
        for (int kc = 0; kc < NCHK; kc++)
            s += part[(((size_t)(bh*NCHK + kc)) * 272 + m0 + mm) * 64 + e];
        sm[mm][e] = s;
    }
    __syncthreads();
    const int m  = t & 63;
    const int er = t >> 6;
    for (int ee = er; ee < 80; ee += 4) {
        if (m0 + m < 288) {
            float val = 0.f;
            if (m < mw) {
                if (ee < 64) {
                    val = sm[m][ee];
                } else if (ee == 64) {
                    #pragma unroll
                    for (int c = 0; c < 8; c++)
                        val += kpart[((size_t)bh * 8 + c) * MMP + m0 + m];
                }
            }
            ctxT[((size_t)bh * 80 + ee) * 288 + m0 + m] = __float2half(val);
        }
    }
}

// ======================================================================
// attn_mma
// ======================================================================
#define APITCH 24
__global__ __launch_bounds__(256, 2)
void attn_mma(const __half* __restrict__ qp, const __half* __restrict__ ctxT,
              __half* __restrict__ out)
{
    __shared__ __align__(16) __half As[128][APITCH];
    __shared__ __align__(16) __half Bs[80][APITCH];

    const int tid = threadIdx.x;
    const int lane = tid & 31;
    const int warp = tid >> 5;
    const int bm = blockIdx.x * 128;
    const int bh = blockIdx.y;
    const int b = bh >> 3, h = bh & 7;
    const int wm = warp * 16;

    const __half* qpb = qp + ((size_t)(b * SEQ) * H_ + h) * MMP;
    const __half* cb  = ctxT + (size_t)bh * 80 * 288;

    float acc[9][4];
    #pragma unroll
    for (int n = 0; n < 9; n++)
        #pragma unroll
        for (int j = 0; j < 4; j++) acc[n][j] = 0.f;

    const uint32_t sA = (uint32_t)__cvta_generic_to_shared(&As[0][0]);
    const uint32_t sB = (uint32_t)__cvta_generic_to_shared(&Bs[0][0]);
    const int a_m = lane & 15;
    const int a_k = (lane >> 4) << 3;
    const int b_n = (lane & 7) | ((lane & 16) >> 1);
    const int b_k = lane & 8;

    for (int k16 = 0; k16 < 17; k16++) {
        const int k0 = k16 * 16;
        {
            int row = tid >> 1, c8 = (tid & 1) * 8;
            *(uint4*)&As[row][c8] =
                *(const uint4*)&qpb[(size_t)(bm + row) * (H_*MMP) + k0 + c8];
        }
        if (tid < 160) {
            int row = tid >> 1, c8 = (tid & 1) * 8;
            *(uint4*)&Bs[row][c8] =
                *(const uint4*)&cb[(size_t)row * 288 + k0 + c8];
        }
        __syncthreads();

        uint32_t bhf[10][2];
        #pragma unroll
        for (int p = 0; p < 5; p++) {
            uint32_t r[4];
            ldm4(r, sB + (uint32_t)((p*16 + b_n) * APITCH + b_k) * 2);
            bhf[2*p][0] = r[0]; bhf[2*p][1] = r[1];
            bhf[2*p+1][0] = r[2]; bhf[2*p+1][1] = r[3];
        }
        {
            uint32_t ah[4];
            ldm4(ah, sA + (uint32_t)((wm + a_m) * APITCH + a_k) * 2);
            #pragma unroll
            for (int nt = 0; nt < 9; nt++)
                mma_f16(acc[nt], ah, bhf[nt]);
        }
        __syncthreads();
    }

    const int gr = lane >> 2;
    const int gc = (lane & 3) * 2;
    float d0 = __shfl_sync(0xffffffffu, acc[8][0], gr * 4);
    float d1 = __shfl_sync(0xffffffffu, acc[8][2], gr * 4);
    const float dinv0 = 1.f / (d0 + 1e-8f);
    const float dinv1 = 1.f / (d1 + 1e-8f);

    const size_t row0 = ((size_t)(b * SEQ + bm + wm + gr) * H_ + h) * DH_;
    const size_t row1 = row0 + (size_t)8 * H_ * DH_;
    #pragma unroll
    for (int nt = 0; nt < 8; nt++) {
        int e = nt*8 + gc;
        *(__half2*)&out[row0 + e] = __floats2half2_rn(acc[nt][0]*dinv0, acc[nt][1]*dinv0);
        *(__half2*)&out[row1 + e] = __floats2half2_rn(acc[nt][2]*dinv1, acc[nt][3]*dinv1);
    }
}

// ---------------- LayerNorm: warp per row, shuffle-only ---------------------
__global__ __launch_bounds__(256)
void ln_kernel(const float* __restrict__ x, const float* __restrict__ g,
               const float* __restrict__ b, __half* __restrict__ out)
{
    const int lane = threadIdx.x & 31;
    const int w    = threadIdx.x >> 5;
    const size_t r = (size_t)blockIdx.x * 8 + w;

    const float* xr = x + r * D_;
    float4 v[4];
    float s = 0.f, ss = 0.f;
    #pragma unroll
    for (int i = 0; i < 4; i++) {
        v[i] = ((const float4*)xr)[i * 32 + lane];
        s  += v[i].x + v[i].y + v[i].z + v[i].w;
        ss += v[i].x*v[i].x + v[i].y*v[i].y + v[i].z*v[i].z + v[i].w*v[i].w;
    }
    #pragma unroll
    for (int o = 16; o > 0; o >>= 1) {
        s  += __shfl_xor_sync(0xffffffffu, s,  o);
        ss += __shfl_xor_sync(0xffffffffu, ss, o);
    }
    const float mu   = s * (1.f / D_);
    const float var  = ss * (1.f / D_) - mu * mu;
    const float rstd = rsqrtf(var + 1e-5f);

    __half* orow = out + r * D_;
    #pragma unroll
    for (int i = 0; i < 4; i++) {
        const int c4 = i * 32 + lane;
        float4 gg = ((const float4*)g)[c4];
        float4 bb = ((const float4*)b)[c4];
        __half2 p0 = __floats2half2_rn((v[i].x - mu) * rstd * gg.x + bb.x,
                                       (v[i].y - mu) * rstd * gg.y + bb.y);
        __half2 p1 = __floats2half2_rn((v[i].z - mu) * rstd * gg.z + bb.z,
                                       (v[i].w - mu) * rstd * gg.w + bb.w);
        uint2 st;
        st.x = *reinterpret_cast<uint32_t*>(&p0);
        st.y = *reinterpret_cast<uint32_t*>(&p1);
        *(uint2*)&orow[c4 * 4] = st;
    }
}

// ---------------- ksum stage 1 (fp16 in) ---------------
__global__ void ksum1(const __half* __restrict__ kp, float* __restrict__ part)
{
    const int bh = blockIdx.y;
    const int chunk = blockIdx.x;
    const int m = threadIdx.x;
    if (m >= MMP) return;
    const int b = bh >> 3, h = bh & 7;
    const __half* base = kp + ((size_t)(b * SEQ + chunk * 256) * H_ + h) * MMP + m;
    const size_t stride = (size_t)H_ * MMP;
    float s0 = 0.f, s1 = 0.f, s2 = 0.f, s3 = 0.f;
    for (int n = 0; n < 256; n += 4) {
        s0 += __half2float(base[(n+0) * stride]);
        s1 += __half2float(base[(n+1) * stride]);
        s2 += __half2float(base[(n+2) * stride]);
        s3 += __half2float(base[(n+3) * stride]);
    }
    part[((size_t)bh * 8 + chunk) * MMP + m] = (s0 + s1) + (s2 + s3);
}

// ---------------- depthwise conv + SiLU ---------------
#define DC_CH 128
#define DC_TN 32
__global__ __launch_bounds__(256)
void dwconv2(const __half* __restrict__ gin, const float* __restrict__ w,
             const float* __restrict__ bias, __half* __restrict__ out)
{
    __shared__ float sin_[DC_TN + 30][DC_CH];
    __shared__ float sw[DC_CH * KW];

    const int c0 = blockIdx.x * DC_CH;
    const int n0 = blockIdx.y * DC_TN;
    const int b  = blockIdx.z;
    const int t  = threadIdx.x;

    for (int i = t; i < DC_CH * KW; i += 256)
        sw[i] = w[(size_t)c0 * KW + i];
    #pragma unroll
    for (int u = 0; u < (DC_TN + 30) * DC_CH / 256; u++) {
        int f = t + u * 256;
        int rowi = f >> 7;
        int ch = f & 127;
        int n = n0 + rowi - 15;
        sin_[rowi][ch] = ((unsigned)n < SEQ)
            ? __half2float(gin[((size_t)(b * SEQ + n) << 10) + c0 + ch]) : 0.f;
    }
    __syncthreads();

    const int ch = t & 127;
    const int nl0 = (t >> 7) * 16;

    float wr[KW];
    #pragma unroll
    for (int k = 0; k < KW; k++) wr[k] = sw[ch * KW + k];
    const float bb = bias[c0 + ch];

    #pragma unroll
    for (int i = 0; i < 16; i++) {
        float acc = bb;
        #pragma unroll
        for (int k = 0; k < KW; k++)
            acc += sin_[nl0 + i + k][ch] * wr[k];
        float o = acc / (1.f + expf(-acc));
        out[((size_t)(b * SEQ + n0 + nl0 + i) << 10) + c0 + ch] = __float2half(o);
    }
}

// ---------------- host orchestration ----------------------------------------
static inline void run_gemm_h(const __half* A, const uint32_t* Bf, float* C,
                              __half* Ch, const float* bias, const float* extra,
                              int Mdim, int Ndim, int Kdim, int mode)
{
    dim3 grid(Ndim / 128, Mdim / 128);
    gemm_h<<<grid, 256, GH_SMEM>>>(A, Bf, C, Ch, bias, extra, Mdim, Ndim, Kdim, mode);
}
static inline void run_wfrag(const float* W, uint32_t* out, int Ndim, int Kdim,
                             int NT8, int pair)
{
    size_t total = (size_t)NT8 * (Kdim >> 4) * 128;
    wfrag<<<(unsigned)((total + 255) / 256), 256>>>(W, out, Ndim, Kdim, NT8, pair);
}

extern "C" void kernel_launch(void* const* d_in, const int* in_sizes, int n_in,
                              void* d_out, int out_size)
{
    const float* x    = (const float*)d_in[0];
    const float* ln1g = (const float*)d_in[1];
    const float* ln1b = (const float*)d_in[2];
    const float* wq   = (const float*)d_in[3];
    const float* bq   = (const float*)d_in[4];
    const float* wk   = (const float*)d_in[5];
    const float* bk   = (const float*)d_in[6];
    const float* wv   = (const float*)d_in[7];
    const float* bv   = (const float*)d_in[8];
    const float* wo   = (const float*)d_in[9];
    const float* bo   = (const float*)d_in[10];
    const float* proj = (const float*)d_in[11];
    const float* ln2g = (const float*)d_in[12];
    const float* ln2b = (const float*)d_in[13];
    const float* pw1w = (const float*)d_in[14];
    const float* pw1b = (const float*)d_in[15];
    const float* dww  = (const float*)d_in[16];
    const float* dwb  = (const float*)d_in[17];
    const float* pw2w = (const float*)d_in[18];
    const float* pw2b = (const float*)d_in[19];
    float* xo = (float*)d_out;

    cudaFuncSetAttribute(gemm_h, cudaFuncAttributeMaxDynamicSharedMemorySize, GH_SMEM);

    __half *h, *vh, *fph, *ctxT, *att, *glu, *dw;
    float *qk, *part, *cpart, *qkvb, *pw1bi;
    uint32_t* wf;
    cudaGetSymbolAddress((void**)&h,     g_h);
    cudaGetSymbolAddress((void**)&qk,    g_qk);
    cudaGetSymbolAddress((void**)&vh,    g_vh);
    cudaGetSymbolAddress((void**)&fph,   g_fph);
    cudaGetSymbolAddress((void**)&part,  g_part);
    cudaGetSymbolAddress((void**)&cpart, g_cpart);
    cudaGetSymbolAddress((void**)&ctxT,  g_ctxT);
    cudaGetSymbolAddress((void**)&att,   g_att);
    cudaGetSymbolAddress((void**)&glu,   g_glu);
    cudaGetSymbolAddress((void**)&dw,    g_dw);
    cudaGetSymbolAddress((void**)&qkvb,  g_qkvbias);
    cudaGetSymbolAddress((void**)&pw1bi, g_pw1bi);
    cudaGetSymbolAddress((void**)&wf,    g_wfrag);

    __half* qph = fph;
    __half* kph = fph + (size_t)RH * MMP;

    const size_t OFF_WQ = 0;
    const size_t OFF_WO = OFF_WQ + 3*FR_QKV;
    const size_t OFF_P1 = OFF_WO + FR_QKV;
    const size_t OFF_P2 = OFF_P1 + FR_PW1;
    const size_t OFF_PR = OFF_P2 + FR_PW2;

    for (int l = 0; l < LNUM; l++) {
        uint32_t* lw = wf + (size_t)l * FR_LSTR;
        run_wfrag(wq   + (size_t)l*ID_*D_,    lw + OFF_WQ,            512, 512, 64, 0);
        run_wfrag(wk   + (size_t)l*ID_*D_,    lw + OFF_WQ + FR_QKV,   512, 512, 64, 0);
        run_wfrag(wv   + (size_t)l*ID_*D_,    lw + OFF_WQ + 2*FR_QKV, 512, 512, 64, 0);
        run_wfrag(wo   + (size_t)l*ID_*D_,    lw + OFF_WO, 512, 512, 64, 0);
        run_wfrag(pw1w + (size_t)l*2048*D_,   lw + OFF_P1, 2048, 512, 256, 1);
        run_wfrag(pw2w + (size_t)l*D_*INNER_, lw + OFF_P2, 512, 1024, 64, 0);
        run_wfrag(proj + (size_t)l*MM*DH_,    lw + OFF_PR, 266, 64, 48, 0);
    }
    biascat<<<(LNUM*512 + 255)/256, 256>>>(bq, bk, bv, qkvb);
    bias2<<<(LNUM*2048 + 255)/256, 256>>>(pw1b, pw1bi);

    cudaMemcpyAsync(xo, x, (size_t)ROWS * D_ * sizeof(float),
                    cudaMemcpyDeviceToDevice);

    const float dn    = (float)(1.0 / sqrt(sqrt(64.0)));
    const float ratio = (float)(1.0 / sqrt(266.0));

    for (int l = 0; l < LNUM; l++) {
        uint32_t* lw = wf + (size_t)l * FR_LSTR;

        ln_kernel<<<ROWS/8, 256>>>(xo, ln1g + (size_t)l*D_, ln1b + (size_t)l*D_, h);
        run_gemm_h(h, lw + OFF_WQ, qk, vh, qkvb + (size_t)l*1536, nullptr,
                   ROWS, 1536, D_, 3);
        proj_favor<<<(2*RH)/64, 256>>>(qk, lw + OFF_PR, fph, dn, ratio);
        {
            dim3 k1(8, NBH);
            ksum1<<<k1, 288>>>(kph, part);
            dim3 cg(NCHK, NBH);
            ctx_mma<<<cg, 256>>>(kph, vh, cpart);
            dim3 rg(5, NBH);
            reduceT<<<rg, 256>>>(cpart, part, ctxT);
            dim3 ag(SEQ / 128, NBH);
            attn_mma<<<ag, 256>>>(qph, ctxT, att);
        }
        run_gemm_h(att, lw + OFF_WO, xo, nullptr, bo + (size_t)l*D_, xo,
                   ROWS, D_, ID_, 0);
        ln_kernel<<<ROWS/8, 256>>>(xo, ln2g + (size_t)l*D_, ln2b + (size_t)l*D_, h);
        run_gemm_h(h, lw + OFF_P1, nullptr, glu, pw1bi + (size_t)l*2048, nullptr,
                   ROWS, 2048, D_, 4);
        {
            dim3 dg(INNER_/DC_CH, SEQ/DC_TN, B_);
            dwconv2<<<dg, 256>>>(glu, dww + (size_t)l*INNER_*KW, dwb + (size_t)l*INNER_, dw);
        }
        run_gemm_h(dw, lw + OFF_P2, xo, nullptr, pw2b + (size_t)l*D_, xo,
                   ROWS, D_, INNER_, 0);
    }
}

// round 17
// speedup vs baseline: 1.2135x; 1.0374x over previous
#include <cuda_runtime.h>
#include <cuda_fp16.h>
#include <math.h>
#include <stdint.h>

// ---------------- problem constants ----------------
#define B_     4
#define SEQ    2048
#define D_     512
#define H_     8
#define DH_    64
#define ID_    512
#define MM     266
#define MMP    272
#define INNER_ 1024
#define KW     31
#define LNUM   6
#define ROWS   (B_*SEQ)
#define RH     (ROWS*H_)
#define NBH    (B_*H_)
#define NCHK   4

// ---------------- device scratch ----------------
__device__ __half g_h    [ROWS*D_];
__device__ float  g_qk   [2*(size_t)ROWS*ID_];
__device__ __half g_vh   [ROWS*ID_];
__device__ __half g_fph  [2*(size_t)RH*MMP];
__device__ float  g_part [NBH*8*MMP];
__device__ float  g_cpart[(size_t)NBH*NCHK*MMP*DH_];
__device__ __half g_ctxT [(size_t)NBH*80*288];
__device__ __half g_att  [ROWS*ID_];
__device__ __half g_glu  [ROWS*INNER_];
__device__ __half g_dw   [ROWS*INNER_];
__device__ float  g_qkvbias[LNUM*1536];
__device__ float  g_pw1bi [LNUM*2048];

#define FR_QKV  (64*32*128)
#define FR_PW1  (256*32*128)
#define FR_PW2  (64*64*128)
#define FR_PROJ (48*4*128)
#define FR_LSTR (4*FR_QKV + FR_PW1 + FR_PW2 + FR_PROJ)
__device__ uint32_t g_wfrag[(size_t)LNUM * FR_LSTR];

// region boundaries within a layer's fragment block
#define ROFF_WO (3*FR_QKV)
#define ROFF_P1 (ROFF_WO + FR_QKV)
#define ROFF_P2 (ROFF_P1 + FR_PW1)
#define ROFF_PR (ROFF_P2 + FR_PW2)

// ---------------- helpers ----------------
__device__ __forceinline__ uint32_t pk2h(__half a, __half b) {
    __half2 t = __halves2half2(a, b);
    return *reinterpret_cast<uint32_t*>(&t);
}
__device__ __forceinline__ void splitf4h(float4 v, uint2& hi, uint2& lo) {
    __half h0 = __float2half_rn(v.x), h1 = __float2half_rn(v.y),
           h2 = __float2half_rn(v.z), h3 = __float2half_rn(v.w);
    hi.x = pk2h(h0, h1); hi.y = pk2h(h2, h3);
    lo.x = pk2h(__float2half_rn(v.x - __half2float(h0)),
                __float2half_rn(v.y - __half2float(h1)));
    lo.y = pk2h(__float2half_rn(v.z - __half2float(h2)),
                __float2half_rn(v.w - __half2float(h3)));
}
__device__ __forceinline__ void ldm4(uint32_t* r, uint32_t addr) {
    asm volatile("ldmatrix.sync.aligned.m8n8.x4.shared.b16 {%0,%1,%2,%3}, [%4];\n"
                 : "=r"(r[0]), "=r"(r[1]), "=r"(r[2]), "=r"(r[3]) : "r"(addr));
}
__device__ __forceinline__ void ldm4t(uint32_t* r, uint32_t addr) {
    asm volatile("ldmatrix.sync.aligned.m8n8.x4.trans.shared.b16 {%0,%1,%2,%3}, [%4];\n"
                 : "=r"(r[0]), "=r"(r[1]), "=r"(r[2]), "=r"(r[3]) : "r"(addr));
}
__device__ __forceinline__ void mma_f16(float* c, const uint32_t* a, const uint32_t* b) {
    asm volatile(
        "mma.sync.aligned.m16n8k16.row.col.f32.f16.f16.f32 "
        "{%0,%1,%2,%3}, {%4,%5,%6,%7}, {%8,%9}, {%0,%1,%2,%3};\n"
        : "+f"(c[0]), "+f"(c[1]), "+f"(c[2]), "+f"(c[3])
        : "r"(a[0]), "r"(a[1]), "r"(a[2]), "r"(a[3]), "r"(b[0]), "r"(b[1]));
}
__device__ __forceinline__ void cpa16(uint32_t dst, const void* src) {
    asm volatile("cp.async.cg.shared.global [%0], [%1], 16;\n"
                 :: "r"(dst), "l"(src) : "memory");
}

// ---------------- fused weight -> fragment converter (ALL weights) ----------
__device__ __forceinline__ uint32_t conv_frag(const float* __restrict__ W,
                                              int local, int Ndim, int Kdim, int pair)
{
    const int KT16 = Kdim >> 4;
    int r     = local & 1;
    int l     = (local >> 1) & 31;
    int plane = (local >> 6) & 1;
    int ft    = local >> 7;
    int k16 = ft % KT16;
    int n8  = ft / KT16;
    int n = n8 * 8 + (l >> 2);
    int k = k16 * 16 + (l & 3) * 2 + r * 8;
    float v0 = 0.f, v1 = 0.f;
    if (n < Ndim) {
        int srcn = pair ? ((n & 1) ? 1024 + (n >> 1) : (n >> 1)) : n;
        float2 vv = *(const float2*)&W[(size_t)srcn * Kdim + k];
        v0 = vv.x; v1 = vv.y;
    }
    __half h0 = __float2half_rn(v0), h1 = __float2half_rn(v1);
    return (plane == 0)
        ? pk2h(h0, h1)
        : pk2h(__float2half_rn(v0 - __half2float(h0)),
               __float2half_rn(v1 - __half2float(h1)));
}

__global__ __launch_bounds__(256)
void wfrag_all(const float* __restrict__ wq, const float* __restrict__ wk,
               const float* __restrict__ wv, const float* __restrict__ wo,
               const float* __restrict__ pw1w, const float* __restrict__ pw2w,
               const float* __restrict__ proj, uint32_t* __restrict__ out)
{
    const int off = blockIdx.x * 256 + threadIdx.x;   // 0..FR_LSTR-1
    const int l   = blockIdx.y;
    uint32_t val;
    if (off < ROFF_WO) {
        int widx  = off / FR_QKV;
        int local = off - widx * FR_QKV;
        const float* W = (widx == 0) ? wq : (widx == 1) ? wk : wv;
        val = conv_frag(W + (size_t)l * ID_ * D_, local, 512, 512, 0);
    } else if (off < ROFF_P1) {
        val = conv_frag(wo + (size_t)l * ID_ * D_, off - ROFF_WO, 512, 512, 0);
    } else if (off < ROFF_P2) {
        val = conv_frag(pw1w + (size_t)l * 2048 * D_, off - ROFF_P1, 2048, 512, 1);
    } else if (off < ROFF_PR) {
        val = conv_frag(pw2w + (size_t)l * D_ * INNER_, off - ROFF_P2, 512, 1024, 0);
    } else {
        val = conv_frag(proj + (size_t)l * MM * DH_, off - ROFF_PR, 266, 64, 0);
    }
    out[(size_t)l * FR_LSTR + off] = val;
}

__global__ void biascat(const float* __restrict__ bq, const float* __restrict__ bk,
                        const float* __restrict__ bv, float* __restrict__ out)
{
    int i = blockIdx.x * 256 + threadIdx.x;
    if (i < LNUM * 512) {
        int l = i >> 9, c = i & 511;
        out[l*1536 + c]        = bq[i];
        out[l*1536 + 512 + c]  = bk[i];
        out[l*1536 + 1024 + c] = bv[i];
    }
}
__global__ void bias2(const float* __restrict__ pw1b, float* __restrict__ out)
{
    int i = blockIdx.x * 256 + threadIdx.x;
    if (i < LNUM * 2048) {
        int l = i >> 11, c = i & 2047;
        int src = (c & 1) ? 1024 + (c >> 1) : (c >> 1);
        out[l*2048 + c] = pw1b[(size_t)l*2048 + src];
    }
}

#define ASTR 40
#define A_STAGE (128*ASTR)
#define B_STAGE (32*128)
#define GH_SMEM (2*A_STAGE*2 + 2*B_STAGE*4)

// ======================================================================
// gemm_h: A and B both staged via cp.async double buffer.
// modes: 0 C fp32 (+extra resid), 3 qkv split, 4 pair-gate
// ======================================================================
__global__ __launch_bounds__(256, 2)
void gemm_h(const __half* __restrict__ A, const uint32_t* __restrict__ Bf,
            float* __restrict__ C, __half* __restrict__ Ch,
            const float* __restrict__ bias, const float* __restrict__ extra,
            int Mdim, int Ndim, int Kdim, int mode)
{
    extern __shared__ __align__(16) char dynsm[];
    __half*   Asm = (__half*)dynsm;
    uint32_t* Bsm = (uint32_t*)(dynsm + 2*A_STAGE*2);

    const int tid  = threadIdx.x;
    const int lane = tid & 31;
    const int warp = tid >> 5;
    const int wm = (warp & 1) * 64;
    const int wn = (warp >> 1) * 32;
    const int bm = blockIdx.y * 128;
    const int bn = blockIdx.x * 128;
    const int KT16 = Kdim >> 4;
    const int n8c = bn >> 3;

    float acc[4][4][4];
    #pragma unroll
    for (int i = 0; i < 4; i++)
        #pragma unroll
        for (int j = 0; j < 4; j++)
            #pragma unroll
            for (int t = 0; t < 4; t++) acc[i][j][t] = 0.f;

    const int a_m = lane & 15;
    const int a_k = (lane >> 4) << 3;
    const uint32_t sA = (uint32_t)__cvta_generic_to_shared(Asm);
    const uint32_t sB = (uint32_t)__cvta_generic_to_shared(Bsm);

    const int r0 = tid >> 2;
    const int c8 = (tid & 3) * 8;
    const int KT = Kdim >> 5;

    auto issue = [&](int kt, int st) {
        #pragma unroll
        for (int u = 0; u < 2; u++) {
            int row = r0 + u * 64;
            cpa16(sA + (uint32_t)st * (A_STAGE*2) + (uint32_t)(row * ASTR + c8) * 2,
                  &A[(size_t)(bm + row) * Kdim + kt*32 + c8]);
        }
        #pragma unroll
        for (int u = 0; u < 4; u++) {
            int ch = tid + u * 256;
            int blk = ch >> 5;
            int off = (ch & 31) * 4;
            int n8i = blk >> 1;
            int ks  = blk & 1;
            cpa16(sB + (uint32_t)st * (B_STAGE*4) + (uint32_t)(blk * 128 + off) * 4,
                  Bf + ((size_t)(n8c + n8i) * KT16 + (kt*2 + ks)) * 128 + off);
        }
        asm volatile("cp.async.commit_group;\n" ::: "memory");
    };

    issue(0, 0);
    if (KT > 1) issue(1, 1);

    for (int kt = 0; kt < KT; kt++) {
        const int st = kt & 1;
        if (kt + 1 < KT) asm volatile("cp.async.wait_group 1;\n" ::: "memory");
        else             asm volatile("cp.async.wait_group 0;\n" ::: "memory");
        __syncthreads();

        const uint32_t* bst = Bsm + (size_t)st * B_STAGE;
        uint32_t bhf[2][4][2];
        #pragma unroll
        for (int ks = 0; ks < 2; ks++)
            #pragma unroll
            for (int nt = 0; nt < 4; nt++) {
                const uint32_t* p = bst + (((wn >> 3) + nt) * 2 + ks) * 128 + lane * 2;
                uint2 hv = *(const uint2*)p;
                bhf[ks][nt][0] = hv.x; bhf[ks][nt][1] = hv.y;
            }
        const uint32_t stBase = sA + (uint32_t)st * (A_STAGE*2);
        #pragma unroll
        for (int ks = 0; ks < 2; ks++) {
            #pragma unroll
            for (int mt = 0; mt < 4; mt++) {
                uint32_t ah[4];
                uint32_t addr = stBase + (uint32_t)(((wm + mt*16 + a_m) * ASTR) + ks*16 + a_k) * 2;
                ldm4(ah, addr);
                #pragma unroll
                for (int nt = 0; nt < 4; nt++)
                    mma_f16(acc[mt][nt], ah, bhf[ks][nt]);
            }
        }
        __syncthreads();
        if (kt + 2 < KT) issue(kt + 2, st);
    }

    const int gr = lane >> 2;
    const int gc = (lane & 3) * 2;
    #pragma unroll
    for (int mt = 0; mt < 4; mt++) {
        #pragma unroll
        for (int nt = 0; nt < 4; nt++) {
            const float* cp = acc[mt][nt];
            int row = bm + wm + mt*16 + gr;
            int col = bn + wn + nt*8 + gc;
            #pragma unroll
            for (int half = 0; half < 2; half++) {
                int rr = row + half*8;
                float v0 = cp[half*2 + 0];
                float v1 = cp[half*2 + 1];
                if (bias) { v0 += bias[col]; v1 += bias[col + 1]; }
                if (mode == 0) {
                    if (extra) {
                        v0 += extra[(size_t)rr * Ndim + col];
                        v1 += extra[(size_t)rr * Ndim + col + 1];
                    }
                    *(float2*)&C[(size_t)rr * Ndim + col] = make_float2(v0, v1);
                } else if (mode == 4) {
                    Ch[(size_t)rr * (Ndim >> 1) + (col >> 1)] =
                        __float2half(v0 / (1.f + expf(-v1)));
                } else { // mode 3
                    if (col < 1024) {
                        *(float2*)&C[(size_t)(col >> 9) * ((size_t)ROWS * ID_)
                                     + (size_t)rr * ID_ + (col & 511)] =
                            make_float2(v0, v1);
                    } else {
                        *(__half2*)&Ch[(size_t)rr * ID_ + (col & 511)] =
                            __floats2half2_rn(v0, v1);
                    }
                }
            }
        }
    }
}

// ======================================================================
// proj_favor: fused fph = favor( dn * qk @ proj^T ), 3-term split A.
// ======================================================================
#define PFP 72
__global__ __launch_bounds__(256, 2)
void proj_favor(const float* __restrict__ qk, const uint32_t* __restrict__ Bf,
                __half* __restrict__ fph, float dn, float ratio)
{
    __shared__ __align__(16) __half Ah[64][PFP];
    __shared__ __align__(16) __half Al[64][PFP];
    __shared__ float ds[64];
    __shared__ float hm[8][16];

    const int tid = threadIdx.x;
    const int lane = tid & 31;
    const int warp = tid >> 5;
    const int rg = warp >> 1;
    const int hn = warp & 1;
    const int wm = rg * 16;
    const size_t bm = (size_t)blockIdx.x * 64;
    const int isQ = (bm < (size_t)RH);

    #pragma unroll
    for (int u = 0; u < 4; u++) {
        int f = tid + u * 256;
        int row = f >> 4;
        int c4 = (f & 15) * 4;
        float4 v = *(const float4*)&qk[(bm + row) * DH_ + c4];
        uint2 hi, lo;
        splitf4h(v, hi, lo);
        *(uint2*)&Ah[row][c4] = hi;
        *(uint2*)&Al[row][c4] = lo;
    }
    __syncthreads();

    {
        int row = tid >> 2;
        int seg = (tid & 3) * 16;
        float s = 0.f;
        #pragma unroll
        for (int j = 0; j < 16; j++) {
            float q = __half2float(Ah[row][seg + j]) + __half2float(Al[row][seg + j]);
            s += q * q;
        }
        s += __shfl_xor_sync(0xffffffffu, s, 1);
        s += __shfl_xor_sync(0xffffffffu, s, 2);
        if ((tid & 3) == 0) ds[row] = s * 0.0625f;
    }

    float acc[17][4];
    #pragma unroll
    for (int nt = 0; nt < 17; nt++)
        #pragma unroll
        for (int j = 0; j < 4; j++) acc[nt][j] = 0.f;

    const uint32_t sH = (uint32_t)__cvta_generic_to_shared(&Ah[0][0]);
    const uint32_t sL = (uint32_t)__cvta_generic_to_shared(&Al[0][0]);
    const int a_m = lane & 15;
    const int a_k = (lane >> 4) << 3;
    const int n8base = hn * 17;

    #pragma unroll
    for (int k16 = 0; k16 < 4; k16++) {
        uint32_t ah[4], al[4];
        uint32_t off = (uint32_t)((wm + a_m) * PFP + k16*16 + a_k) * 2;
        ldm4(ah, sH + off);
        ldm4(al, sL + off);
        #pragma unroll
        for (int nt = 0; nt < 17; nt++) {
            const uint32_t* fb = Bf + ((size_t)(n8base + nt) * 4 + k16) * 128 + lane * 2;
            uint2 hv = *(const uint2*)fb;
            uint2 lv = *(const uint2*)(fb + 64);
            uint32_t bh[2] = {hv.x, hv.y};
            uint32_t bl[2] = {lv.x, lv.y};
            mma_f16(acc[nt], ah, bh);
            mma_f16(acc[nt], ah, bl);
            mma_f16(acc[nt], al, bh);
        }
    }

    const int gr = lane >> 2;
    const int gc = (lane & 3) * 2;
    const int cbase = hn * 136 + gc;

    if (isQ) {
        float mx0 = -1e30f, mx1 = -1e30f;
        #pragma unroll
        for (int nt = 0; nt < 17; nt++) {
            int c0 = cbase + nt*8;
            if (c0 < MM)     { mx0 = fmaxf(mx0, acc[nt][0]); mx1 = fmaxf(mx1, acc[nt][2]); }
            if (c0 + 1 < MM) { mx0 = fmaxf(mx0, acc[nt][1]); mx1 = fmaxf(mx1, acc[nt][3]); }
        }
        mx0 = fmaxf(mx0, __shfl_xor_sync(0xffffffffu, mx0, 1));
        mx0 = fmaxf(mx0, __shfl_xor_sync(0xffffffffu, mx0, 2));
        mx1 = fmaxf(mx1, __shfl_xor_sync(0xffffffffu, mx1, 1));
        mx1 = fmaxf(mx1, __shfl_xor_sync(0xffffffffu, mx1, 2));
        if ((lane & 3) == 0) { hm[warp][gr] = mx0; hm[warp][gr + 8] = mx1; }
    }
    __syncthreads();

    float fmx0 = 0.f, fmx1 = 0.f;
    if (isQ) {
        fmx0 = fmaxf(hm[warp][gr],     hm[warp ^ 1][gr])     * dn;
        fmx1 = fmaxf(hm[warp][gr + 8], hm[warp ^ 1][gr + 8]) * dn;
    }
    const float d0 = ds[wm + gr];
    const float d1 = ds[wm + gr + 8];
    __half* o0 = fph + (bm + wm + gr) * MMP;
    __half* o1 = o0 + (size_t)8 * MMP;

    #pragma unroll
    for (int nt = 0; nt < 17; nt++) {
        #pragma unroll
        for (int j = 0; j < 2; j++) {
            int col = cbase + nt*8 + j;
            float va = acc[nt][j]     * dn;
            float vb = acc[nt][2 + j] * dn;
            float ra, rb;
            if (col < MM) {
                if (isQ) {
                    ra = ratio * (expf(va - d0 - fmx0) + 1e-4f);
                    rb = ratio * (expf(vb - d1 - fmx1) + 1e-4f);
                } else {
                    ra = ratio * expf(va - d0 + 1e-4f);
                    rb = ratio * expf(vb - d1 + 1e-4f);
                }
            } else { ra = 0.f; rb = 0.f; }
            o0[col] = __float2half(ra);
            o1[col] = __float2half(rb);
        }
    }
}

// ======================================================================
// ctx_mma: kp^T @ v over 512-seq chunk (NCHK=4) -> fp32 partials
// ======================================================================
#define KPITCH 280
#define VPITCH 72
__global__ __launch_bounds__(256, 1)
void ctx_mma(const __half* __restrict__ kp, const __half* __restrict__ v,
             float* __restrict__ part)
{
    __shared__ __align__(16) __half Kp[32][KPITCH];
    __shared__ __align__(16) __half Vs[32][VPITCH];

    const int tid = threadIdx.x;
    const int lane = tid & 31;
    const int warp = tid >> 5;
    const int kc = blockIdx.x;
    const int bh = blockIdx.y;
    const int b = bh >> 3, h = bh & 7;

    const int nmt = (warp == 0) ? 3 : 2;
    int mts[3];
    mts[0] = 2*warp; mts[1] = 2*warp + 1; mts[2] = 16;

    float acc[3][8][4];
    #pragma unroll
    for (int t = 0; t < 3; t++)
        #pragma unroll
        for (int n = 0; n < 8; n++)
            #pragma unroll
            for (int j = 0; j < 4; j++) acc[t][n][j] = 0.f;

    const __half* kpb = kp + ((size_t)(b * SEQ) * H_ + h) * MMP;
    const __half* vb  = v  + ((size_t)(b * SEQ) * H_ + h) * DH_;

    const uint32_t sK = (uint32_t)__cvta_generic_to_shared(&Kp[0][0]);
    const uint32_t sV = (uint32_t)__cvta_generic_to_shared(&Vs[0][0]);
    const int r7 = lane & 7;
    const int NIT = SEQ / NCHK / 32;

    for (int it = 0; it < NIT; it++) {
        const int n0 = kc * (SEQ / NCHK) + it * 32;
        for (int f = tid; f < 32*34; f += 256) {
            int nn = f / 34, c8 = (f % 34) * 8;
            *(uint4*)&Kp[nn][c8] =
                *(const uint4*)&kpb[(size_t)(n0 + nn) * (H_*MMP) + c8];
        }
        {
            int nn = tid >> 3, c8 = (tid & 7) * 8;
            *(uint4*)&Vs[nn][c8] =
                *(const uint4*)&vb[(size_t)(n0 + nn) * (H_*DH_) + c8];
        }
        __syncthreads();

        #pragma unroll
        for (int ks = 0; ks < 2; ks++) {
            uint32_t bhf[8][2];
            #pragma unroll
            for (int g = 0; g < 4; g++) {
                int row = ks*16 + ((lane >> 3) & 1) * 8 + r7;
                int col = g*16 + (lane >> 4) * 8;
                uint32_t r[4];
                ldm4t(r, sV + (uint32_t)(row * VPITCH + col) * 2);
                bhf[2*g][0] = r[0]; bhf[2*g][1] = r[1];
                bhf[2*g+1][0] = r[2]; bhf[2*g+1][1] = r[3];
            }
            #pragma unroll
            for (int t = 0; t < 3; t++) {
                if (t < nmt) {
                    int m0 = mts[t] * 16;
                    int row = ks*16 + ((lane >> 4) & 1) * 8 + r7;
                    int col = m0 + ((lane >> 3) & 1) * 8;
                    uint32_t ah[4];
                    ldm4t(ah, sK + (uint32_t)(row * KPITCH + col) * 2);
                    #pragma unroll
                    for (int nt = 0; nt < 8; nt++)
                        mma_f16(acc[t][nt], ah, bhf[nt]);
                }
            }
        }
        __syncthreads();
    }

    const int gr = lane >> 2;
    const int gc = (lane & 3) * 2;
    float* pb = part + ((size_t)(bh * NCHK + kc)) * 272 * 64;
    #pragma unroll
    for (int t = 0; t < 3; t++) {
        if (t < nmt) {
            int m0 = mts[t] * 16;
            #pragma unroll
            for (int nt = 0; nt < 8; nt++) {
                int e = nt*8 + gc;
                pb[(size_t)(m0 + gr) * 64 + e]     = acc[t][nt][0];
                pb[(size_t)(m0 + gr) * 64 + e + 1] = acc[t][nt][1];
                pb[(size_t)(m0 + gr + 8) * 64 + e]     = acc[t][nt][2];
                pb[(size_t)(m0 + gr + 8) * 64 + e + 1] = acc[t][nt][3];
            }
        }
    }
}

// ---------------- reduceT: sum ctx partials; ks row from ksum1 partials -----
__global__ void reduceT(const float* __restrict__ part, const float* __restrict__ kpart,
                        __half* __restrict__ ctxT)
{
    const int bh = blockIdx.y;
    const int m0 = blockIdx.x * 64;
    const int mw = (272 - m0 < 64) ? (272 - m0) : 64;
    __shared__ float sm[64][65];
    const int t = threadIdx.x;
    const int e  = t & 63;
    const int mr = t >> 6;
    for (int mm = mr; mm < mw; mm += 4) {
        float s = 0.f;
        #pragma unroll
        for (int kc = 0; kc < NCHK; kc++)
            s += part[(((size_t)(bh*NCHK + kc)) * 272 + m0 + mm) * 64 + e];
        sm[mm][e] = s;
    }
    __syncthreads();
    const int m  = t & 63;
    const int er = t >> 6;
    for (int ee = er; ee < 80; ee += 4) {
        if (m0 + m < 288) {
            float val = 0.f;
            if (m < mw) {
                if (ee < 64) {
                    val = sm[m][ee];
                } else if (ee == 64) {
                    #pragma unroll
                    for (int c = 0; c < 8; c++)
                        val += kpart[((size_t)bh * 8 + c) * MMP + m0 + m];
                }
            }
            ctxT[((size_t)bh * 80 + ee) * 288 + m0 + m] = __float2half(val);
        }
    }
}

// ======================================================================
// attn_mma
// ======================================================================
#define APITCH 24
__global__ __launch_bounds__(256, 2)
void attn_mma(const __half* __restrict__ qp, const __half* __restrict__ ctxT,
              __half* __restrict__ out)
{
    __shared__ __align__(16) __half As[128][APITCH];
    __shared__ __align__(16) __half Bs[80][APITCH];

    const int tid = threadIdx.x;
    const int lane = tid & 31;
    const int warp = tid >> 5;
    const int bm = blockIdx.x * 128;
    const int bh = blockIdx.y;
    const int b = bh >> 3, h = bh & 7;
    const int wm = warp * 16;

    const __half* qpb = qp + ((size_t)(b * SEQ) * H_ + h) * MMP;
    const __half* cb  = ctxT + (size_t)bh * 80 * 288;

    float acc[9][4];
    #pragma unroll
    for (int n = 0; n < 9; n++)
        #pragma unroll
        for (int j = 0; j < 4; j++) acc[n][j] = 0.f;

    const uint32_t sA = (uint32_t)__cvta_generic_to_shared(&As[0][0]);
    const uint32_t sB = (uint32_t)__cvta_generic_to_shared(&Bs[0][0]);
    const int a_m = lane & 15;
    const int a_k = (lane >> 4) << 3;
    const int b_n = (lane & 7) | ((lane & 16) >> 1);
    const int b_k = lane & 8;

    for (int k16 = 0; k16 < 17; k16++) {
        const int k0 = k16 * 16;
        {
            int row = tid >> 1, c8 = (tid & 1) * 8;
            *(uint4*)&As[row][c8] =
                *(const uint4*)&qpb[(size_t)(bm + row) * (H_*MMP) + k0 + c8];
        }
        if (tid < 160) {
            int row = tid >> 1, c8 = (tid & 1) * 8;
            *(uint4*)&Bs[row][c8] =
                *(const uint4*)&cb[(size_t)row * 288 + k0 + c8];
        }
        __syncthreads();

        uint32_t bhf[10][2];
        #pragma unroll
        for (int p = 0; p < 5; p++) {
            uint32_t r[4];
            ldm4(r, sB + (uint32_t)((p*16 + b_n) * APITCH + b_k) * 2);
            bhf[2*p][0] = r[0]; bhf[2*p][1] = r[1];
            bhf[2*p+1][0] = r[2]; bhf[2*p+1][1] = r[3];
        }
        {
            uint32_t ah[4];
            ldm4(ah, sA + (uint32_t)((wm + a_m) * APITCH + a_k) * 2);
            #pragma unroll
            for (int nt = 0; nt < 9; nt++)
                mma_f16(acc[nt], ah, bhf[nt]);
        }
        __syncthreads();
    }

    const int gr = lane >> 2;
    const int gc = (lane & 3) * 2;
    float d0 = __shfl_sync(0xffffffffu, acc[8][0], gr * 4);
    float d1 = __shfl_sync(0xffffffffu, acc[8][2], gr * 4);
    const float dinv0 = 1.f / (d0 + 1e-8f);
    const float dinv1 = 1.f / (d1 + 1e-8f);

    const size_t row0 = ((size_t)(b * SEQ + bm + wm + gr) * H_ + h) * DH_;
    const size_t row1 = row0 + (size_t)8 * H_ * DH_;
    #pragma unroll
    for (int nt = 0; nt < 8; nt++) {
        int e = nt*8 + gc;
        *(__half2*)&out[row0 + e] = __floats2half2_rn(acc[nt][0]*dinv0, acc[nt][1]*dinv0);
        *(__half2*)&out[row1 + e] = __floats2half2_rn(acc[nt][2]*dinv1, acc[nt][3]*dinv1);
    }
}

// ---------------- LayerNorm: warp per row, shuffle-only ---------------------
__global__ __launch_bounds__(256)
void ln_kernel(const float* __restrict__ x, const float* __restrict__ g,
               const float* __restrict__ b, __half* __restrict__ out)
{
    const int lane = threadIdx.x & 31;
    const int w    = threadIdx.x >> 5;
    const size_t r = (size_t)blockIdx.x * 8 + w;

    const float* xr = x + r * D_;
    float4 v[4];
    float s = 0.f, ss = 0.f;
    #pragma unroll
    for (int i = 0; i < 4; i++) {
        v[i] = ((const float4*)xr)[i * 32 + lane];
        s  += v[i].x + v[i].y + v[i].z + v[i].w;
        ss += v[i].x*v[i].x + v[i].y*v[i].y + v[i].z*v[i].z + v[i].w*v[i].w;
    }
    #pragma unroll
    for (int o = 16; o > 0; o >>= 1) {
        s  += __shfl_xor_sync(0xffffffffu, s,  o);
        ss += __shfl_xor_sync(0xffffffffu, ss, o);
    }
    const float mu   = s * (1.f / D_);
    const float var  = ss * (1.f / D_) - mu * mu;
    const float rstd = rsqrtf(var + 1e-5f);

    __half* orow = out + r * D_;
    #pragma unroll
    for (int i = 0; i < 4; i++) {
        const int c4 = i * 32 + lane;
        float4 gg = ((const float4*)g)[c4];
        float4 bb = ((const float4*)b)[c4];
        __half2 p0 = __floats2half2_rn((v[i].x - mu) * rstd * gg.x + bb.x,
                                       (v[i].y - mu) * rstd * gg.y + bb.y);
        __half2 p1 = __floats2half2_rn((v[i].z - mu) * rstd * gg.z + bb.z,
                                       (v[i].w - mu) * rstd * gg.w + bb.w);
        uint2 st;
        st.x = *reinterpret_cast<uint32_t*>(&p0);
        st.y = *reinterpret_cast<uint32_t*>(&p1);
        *(uint2*)&orow[c4 * 4] = st;
    }
}

// ---------------- ksum stage 1 (fp16 in) ---------------
__global__ void ksum1(const __half* __restrict__ kp, float* __restrict__ part)
{
    const int bh = blockIdx.y;
    const int chunk = blockIdx.x;
    const int m = threadIdx.x;
    if (m >= MMP) return;
    const int b = bh >> 3, h = bh & 7;
    const __half* base = kp + ((size_t)(b * SEQ + chunk * 256) * H_ + h) * MMP + m;
    const size_t stride = (size_t)H_ * MMP;
    float s0 = 0.f, s1 = 0.f, s2 = 0.f, s3 = 0.f;
    for (int n = 0; n < 256; n += 4) {
        s0 += __half2float(base[(n+0) * stride]);
        s1 += __half2float(base[(n+1) * stride]);
        s2 += __half2float(base[(n+2) * stride]);
        s3 += __half2float(base[(n+3) * stride]);
    }
    part[((size_t)bh * 8 + chunk) * MMP + m] = (s0 + s1) + (s2 + s3);
}

// ---------------- depthwise conv + SiLU ---------------
#define DC_CH 128
#define DC_TN 32
__global__ __launch_bounds__(256)
void dwconv2(const __half* __restrict__ gin, const float* __restrict__ w,
             const float* __restrict__ bias, __half* __restrict__ out)
{
    __shared__ float sin_[DC_TN + 30][DC_CH];
    __shared__ float sw[DC_CH * KW];

    const int c0 = blockIdx.x * DC_CH;
    const int n0 = blockIdx.y * DC_TN;
    const int b  = blockIdx.z;
    const int t  = threadIdx.x;

    for (int i = t; i < DC_CH * KW; i += 256)
        sw[i] = w[(size_t)c0 * KW + i];
    #pragma unroll
    for (int u = 0; u < (DC_TN + 30) * DC_CH / 256; u++) {
        int f = t + u * 256;
        int rowi = f >> 7;
        int ch = f & 127;
        int n = n0 + rowi - 15;
        sin_[rowi][ch] = ((unsigned)n < SEQ)
            ? __half2float(gin[((size_t)(b * SEQ + n) << 10) + c0 + ch]) : 0.f;
    }
    __syncthreads();

    const int ch = t & 127;
    const int nl0 = (t >> 7) * 16;

    float wr[KW];
    #pragma unroll
    for (int k = 0; k < KW; k++) wr[k] = sw[ch * KW + k];
    const float bb = bias[c0 + ch];

    #pragma unroll
    for (int i = 0; i < 16; i++) {
        float acc = bb;
        #pragma unroll
        for (int k = 0; k < KW; k++)
            acc += sin_[nl0 + i + k][ch] * wr[k];
        float o = acc / (1.f + expf(-acc));
        out[((size_t)(b * SEQ + n0 + nl0 + i) << 10) + c0 + ch] = __float2half(o);
    }
}

// ---------------- host orchestration ----------------------------------------
static inline void run_gemm_h(const __half* A, const uint32_t* Bf, float* C,
                              __half* Ch, const float* bias, const float* extra,
                              int Mdim, int Ndim, int Kdim, int mode)
{
    dim3 grid(Ndim / 128, Mdim / 128);
    gemm_h<<<grid, 256, GH_SMEM>>>(A, Bf, C, Ch, bias, extra, Mdim, Ndim, Kdim, mode);
}

extern "C" void kernel_launch(void* const* d_in, const int* in_sizes, int n_in,
                              void* d_out, int out_size)
{
    const float* x    = (const float*)d_in[0];
    const float* ln1g = (const float*)d_in[1];
    const float* ln1b = (const float*)d_in[2];
    const float* wq   = (const float*)d_in[3];
    const float* bq   = (const float*)d_in[4];
    const float* wk   = (const float*)d_in[5];
    const float* bk   = (const float*)d_in[6];
    const float* wv   = (const float*)d_in[7];
    const float* bv   = (const float*)d_in[8];
    const float* wo   = (const float*)d_in[9];
    const float* bo   = (const float*)d_in[10];
    const float* proj = (const float*)d_in[11];
    const float* ln2g = (const float*)d_in[12];
    const float* ln2b = (const float*)d_in[13];
    const float* pw1w = (const float*)d_in[14];
    const float* pw1b = (const float*)d_in[15];
    const float* dww  = (const float*)d_in[16];
    const float* dwb  = (const float*)d_in[17];
    const float* pw2w = (const float*)d_in[18];
    const float* pw2b = (const float*)d_in[19];
    float* xo = (float*)d_out;

    cudaFuncSetAttribute(gemm_h, cudaFuncAttributeMaxDynamicSharedMemorySize, GH_SMEM);

    __half *h, *vh, *fph, *ctxT, *att, *glu, *dw;
    float *qk, *part, *cpart, *qkvb, *pw1bi;
    uint32_t* wf;
    cudaGetSymbolAddress((void**)&h,     g_h);
    cudaGetSymbolAddress((void**)&qk,    g_qk);
    cudaGetSymbolAddress((void**)&vh,    g_vh);
    cudaGetSymbolAddress((void**)&fph,   g_fph);
    cudaGetSymbolAddress((void**)&part,  g_part);
    cudaGetSymbolAddress((void**)&cpart, g_cpart);
    cudaGetSymbolAddress((void**)&ctxT,  g_ctxT);
    cudaGetSymbolAddress((void**)&att,   g_att);
    cudaGetSymbolAddress((void**)&glu,   g_glu);
    cudaGetSymbolAddress((void**)&dw,    g_dw);
    cudaGetSymbolAddress((void**)&qkvb,  g_qkvbias);
    cudaGetSymbolAddress((void**)&pw1bi, g_pw1bi);
    cudaGetSymbolAddress((void**)&wf,    g_wfrag);

    __half* qph = fph;
    __half* kph = fph + (size_t)RH * MMP;

    const size_t OFF_WQ = 0;
    const size_t OFF_WO = OFF_WQ + 3*FR_QKV;
    const size_t OFF_P1 = OFF_WO + FR_QKV;
    const size_t OFF_P2 = OFF_P1 + FR_PW1;
    const size_t OFF_PR = OFF_P2 + FR_PW2;

    // ---- one fused weight-prep launch ----
    {
        dim3 wg(FR_LSTR / 256, LNUM);
        wfrag_all<<<wg, 256>>>(wq, wk, wv, wo, pw1w, pw2w, proj, wf);
    }
    biascat<<<(LNUM*512 + 255)/256, 256>>>(bq, bk, bv, qkvb);
    bias2<<<(LNUM*2048 + 255)/256, 256>>>(pw1b, pw1bi);

    cudaMemcpyAsync(xo, x, (size_t)ROWS * D_ * sizeof(float),
                    cudaMemcpyDeviceToDevice);

    const float dn    = (float)(1.0 / sqrt(sqrt(64.0)));
    const float ratio = (float)(1.0 / sqrt(266.0));

    for (int l = 0; l < LNUM; l++) {
        uint32_t* lw = wf + (size_t)l * FR_LSTR;

        ln_kernel<<<ROWS/8, 256>>>(xo, ln1g + (size_t)l*D_, ln1b + (size_t)l*D_, h);
        run_gemm_h(h, lw + OFF_WQ, qk, vh, qkvb + (size_t)l*1536, nullptr,
                   ROWS, 1536, D_, 3);
        proj_favor<<<(2*RH)/64, 256>>>(qk, lw + OFF_PR, fph, dn, ratio);
        {
            dim3 k1(8, NBH);
            ksum1<<<k1, 288>>>(kph, part);
            dim3 cg(NCHK, NBH);
            ctx_mma<<<cg, 256>>>(kph, vh, cpart);
            dim3 rg(5, NBH);
            reduceT<<<rg, 256>>>(cpart, part, ctxT);
            dim3 ag(SEQ / 128, NBH);
            attn_mma<<<ag, 256>>>(qph, ctxT, att);
        }
        run_gemm_h(att, lw + OFF_WO, xo, nullptr, bo + (size_t)l*D_, xo,
                   ROWS, D_, ID_, 0);
        ln_kernel<<<ROWS/8, 256>>>(xo, ln2g + (size_t)l*D_, ln2b + (size_t)l*D_, h);
        run_gemm_h(h, lw + OFF_P1, nullptr, glu, pw1bi + (size_t)l*2048, nullptr,
                   ROWS, 2048, D_, 4);
        {
            dim3 dg(INNER_/DC_CH, SEQ/DC_TN, B_);
            dwconv2<<<dg, 256>>>(glu, dww + (size_t)l*INNER_*KW, dwb + (size_t)l*INNER_, dw);
        }
        run_gemm_h(dw, lw + OFF_P2, xo, nullptr, pw2b + (size_t)l*D_, xo,
                   ROWS, D_, INNER_, 0);
    }
}